// round 5
// baseline (speedup 1.0000x reference)
#include <cuda_runtime.h>
#include <cuda_bf16.h>

#define Bb 2
#define Cc 64
#define Hh 256
#define Ww 256
#define HW (Hh*Ww)
#define NUMS 63
#define LL (NUMS*NUMS)          // 3969
#define K2 64
#define EPSf 1e-5f
#define TBL_W (2*NUMS-1)        // 125

typedef unsigned long long ull;

__device__ __forceinline__ ull fma2(ull a, ull b, ull c){
    ull d; asm("fma.rn.f32x2 %0, %1, %2, %3;" : "=l"(d) : "l"(a), "l"(b), "l"(c)); return d;
}
__device__ __forceinline__ ull add2(ull a, ull b){
    ull d; asm("add.rn.f32x2 %0, %1, %2;" : "=l"(d) : "l"(a), "l"(b)); return d;
}
__device__ __forceinline__ ull dup2(float v){
    ull d; asm("mov.b64 %0, {%1, %1};" : "=l"(d) : "f"(v)); return d;
}
__device__ __forceinline__ float2 unpk(ull a){
    float2 r; asm("mov.b64 {%0, %1}, %2;" : "=f"(r.x), "=f"(r.y) : "l"(a)); return r;
}

// ---------------- device scratch ----------------
#define BCL (Bb*Cc*LL)
__device__ float2 g_mif [BCL];   // (fg mean, 1/fg var)  [b][c][l]
__device__ float2 g_mib [BCL];   // (bg mean, 1/bg var)  [b][c][l]
__device__ float  g_sbv [BCL];   // bg var               [b][l][c]
__device__ float  g_tokf[BCL];   // tok_f partial (c 0..31)   [b][l][c]
__device__ float  g_tokb[BCL];   // tok_b partial (c 0..31)   [b][l][c]
__device__ float  g_tokf2[BCL];  // tok_f partial (c 32..63)
__device__ float  g_tokb2[BCL];  // tok_b partial (c 32..63)
__device__ float  g_ns  [BCL];   // new_std              [b][c][l]

// ---------------- Kernel 1: per-patch statistics ----------------
__global__ __launch_bounds__(256)
void k_stats(const float* __restrict__ x, const float* __restrict__ mask)
{
    int bl = blockIdx.x;
    int b  = bl / LL;
    int l  = bl - b * LL;
    int lh = l / NUMS, lw = l - lh * NUMS;
    int r0 = lh * 4, c0 = lw * 4;

    __shared__ float sm_m[64];
    int t = threadIdx.x;
    if (t < 64) {
        int kh = t >> 3, kw = t & 7;
        sm_m[t] = mask[(size_t)b * HW + (r0 + kh) * Ww + c0 + kw];
    }
    __syncthreads();

    int c = t >> 2;
    int j = t & 3;

    const float* xp = x + (((size_t)b * Cc + c) * Hh + r0 + 2 * j) * Ww + c0;
    float s1 = 0.f, s2 = 0.f, sm1 = 0.f, sm2 = 0.f, msum = 0.f;
    #pragma unroll
    for (int rr = 0; rr < 2; rr++) {
        float4 a = *(const float4*)(xp + rr * Ww);
        float4 bq = *(const float4*)(xp + rr * Ww + 4);
        float vv[8] = {a.x,a.y,a.z,a.w,bq.x,bq.y,bq.z,bq.w};
        #pragma unroll
        for (int kk = 0; kk < 8; kk++) {
            float m = sm_m[(2 * j + rr) * 8 + kk];
            float v = vv[kk];
            s1 += v; s2 += v * v;
            sm1 += m * v; sm2 += m * v * v;
            msum += m;
        }
    }
    #pragma unroll
    for (int d = 1; d < 4; d <<= 1) {
        s1  += __shfl_xor_sync(0xffffffff, s1,  d);
        s2  += __shfl_xor_sync(0xffffffff, s2,  d);
        sm1 += __shfl_xor_sync(0xffffffff, sm1, d);
        sm2 += __shfl_xor_sync(0xffffffff, sm2, d);
        msum+= __shfl_xor_sync(0xffffffff, msum,d);
    }
    if (j == 0) {
        float numf = msum;
        float numb = 64.0f - msum;
        float mf = sm1 / (numf + EPSf);
        float vf = (sm2 - 2.f * mf * sm1 + mf * mf * numf) / (numf + EPSf);
        float sb1 = s1 - sm1, sb2 = s2 - sm2;
        float mb = sb1 / (numb + EPSf);
        float vb = (sb2 - 2.f * mb * sb1 + mb * mb * numb) / (numb + EPSf);
        size_t o = ((size_t)b * Cc + c) * LL + l;
        g_mif[o] = make_float2(mf, 1.0f / vf);
        g_mib[o] = make_float2(mb, 1.0f / vb);
        g_sbv[((size_t)b * LL + l) * Cc + c] = vb;
    }
}

// ---------------- Kernel 2: fused in_* build + token GEMM (f32x2, K-split) ----------------
// Tile 128L x 64D. Each block handles 32 channels (khalf). 64 phases of 32 k.
// grid (32, B, 4): z = type*2 + khalf. 256 threads.
// compute map: lgrp=t>>4 (8 L), dgrp=t&15 (4 D) -> 32 fp32 acc as 16 f32x2.
__global__ __launch_bounds__(256)
void k_gemm(const float* __restrict__ x, const float* __restrict__ mask,
            const float* __restrict__ w_fore, const float* __restrict__ w_back)
{
    int tile  = blockIdx.x;              // 0..31
    int b     = blockIdx.y;
    int type  = blockIdx.z >> 1;         // 0 = fore, 1 = back
    int khalf = blockIdx.z & 1;          // channel half
    const float*  w    = type ? w_back : w_fore;
    const float2* g_mi = type ? g_mib : g_mif;
    float* g_tk = type ? (khalf ? g_tokb2 : g_tokb)
                       : (khalf ? g_tokf2 : g_tokf);

    int l0 = tile * 128;
    int t  = threadIdx.x;

    __shared__ __align__(16) float ash [32][128];
    __shared__ __align__(16) float wsh2[32][136];   // W duplicated: [k][2d],[k][2d+1]

    // A-side thread mapping
    int la    = t & 127;
    int halfa = t >> 7;                  // stages rows halfa*2, halfa*2+1 of each 4-row phase
    int lgl   = l0 + la;
    bool lvalid = lgl < LL;
    int lg = lvalid ? lgl : (LL - 1);
    int lh = lg / NUMS, lw = lg - lh * NUMS;

    // mask bit words (word s covers patch rows 4s..4s+3), kept in registers
    unsigned int mb0 = 0, mb1 = 0;
    {
        const float* mp = mask + (size_t)b * HW + (lh * 4) * Ww + lw * 4;
        #pragma unroll
        for (int r = 0; r < 8; r++) {
            float4 a = *(const float4*)(mp + r * Ww);
            float4 bq = *(const float4*)(mp + r * Ww + 4);
            float mv[8] = {a.x,a.y,a.z,a.w,bq.x,bq.y,bq.z,bq.w};
            unsigned int bits = 0;
            #pragma unroll
            for (int kw = 0; kw < 8; kw++) {
                bool on = mv[kw] > 0.5f;
                if (type) on = !on;
                bits |= (on ? 1u : 0u) << (((r & 3) * 8) + kw);
            }
            if (r < 4) mb0 |= bits; else mb1 |= bits;
        }
    }

    // W-side mapping
    int wd = t & 63;          // output channel d
    int wi = t >> 6;          // k-subgroup 0..3 (8 k each)

    int lgrp = t >> 4, dgrp = t & 15;
    int c0 = khalf * 32;

    ull acc[4][4];
    #pragma unroll
    for (int i = 0; i < 4; i++)
        #pragma unroll
        for (int j2 = 0; j2 < 4; j2++) acc[i][j2] = 0ull;

    float4 xr0, xr1, xr2, xr3, wr0, wr1;
    float2 mi;

    auto LD = [&](int p) {
        int c = c0 + (p >> 1), sub = p & 1;
        const float* xp = x + (((size_t)b * Cc + c) * Hh + lh * 4 + sub * 4 + halfa * 2) * Ww + lw * 4;
        xr0 = *(const float4*)xp;
        xr1 = *(const float4*)(xp + 4);
        xr2 = *(const float4*)(xp + Ww);
        xr3 = *(const float4*)(xp + Ww + 4);
        mi  = g_mi[((size_t)b * Cc + c) * LL + lg];
        const float* wp = w + (size_t)wd * (Cc * K2) + c * K2 + sub * 32 + wi * 8;
        wr0 = *(const float4*)wp;
        wr1 = *(const float4*)(wp + 4);
    };
    LD(0);

    for (int p = 0; p < 64; p++) {
        __syncthreads();
        // ---- stage A ----
        {
            int sub = p & 1;
            unsigned int wsel = sub ? mb1 : mb0;
            float muv = lvalid ? mi.x : 0.f;
            float isv = lvalid ? mi.y : 0.f;
            float xv[16] = {xr0.x,xr0.y,xr0.z,xr0.w, xr1.x,xr1.y,xr1.z,xr1.w,
                            xr2.x,xr2.y,xr2.z,xr2.w, xr3.x,xr3.y,xr3.z,xr3.w};
            #pragma unroll
            for (int rr = 0; rr < 2; rr++) {
                int row = halfa * 2 + rr;
                #pragma unroll
                for (int kw = 0; kw < 8; kw++) {
                    bool on = (wsel >> (row * 8 + kw)) & 1u;
                    ash[row * 8 + kw][la] = on ? (xv[rr * 8 + kw] - muv) * isv : muv;
                }
            }
        }
        // ---- stage W (duplicated pairs for f32x2) ----
        {
            float wv[8] = {wr0.x,wr0.y,wr0.z,wr0.w, wr1.x,wr1.y,wr1.z,wr1.w};
            #pragma unroll
            for (int q = 0; q < 8; q++)
                *(float2*)&wsh2[wi * 8 + q][2 * wd] = make_float2(wv[q], wv[q]);
        }
        __syncthreads();
        if (p < 63) LD(p + 1);

        // ---- compute 32 k slices: 8L x 4D via f32x2 ----
        #pragma unroll 8
        for (int k = 0; k < 32; k++) {
            ulonglong2 A0 = *(const ulonglong2*)&ash[k][8 * lgrp];
            ulonglong2 A1 = *(const ulonglong2*)&ash[k][8 * lgrp + 4];
            ulonglong2 W0 = *(const ulonglong2*)&wsh2[k][8 * dgrp];
            ulonglong2 W1 = *(const ulonglong2*)&wsh2[k][8 * dgrp + 4];
            ull a2[4] = {A0.x, A0.y, A1.x, A1.y};
            ull wv[4] = {W0.x, W0.y, W1.x, W1.y};
            #pragma unroll
            for (int li = 0; li < 4; li++) {
                acc[li][0] = fma2(a2[li], wv[0], acc[li][0]);
                acc[li][1] = fma2(a2[li], wv[1], acc[li][1]);
                acc[li][2] = fma2(a2[li], wv[2], acc[li][2]);
                acc[li][3] = fma2(a2[li], wv[3], acc[li][3]);
            }
        }
    }

    // ---- write partial tok [b][l][d] ----
    #pragma unroll
    for (int li = 0; li < 4; li++) {
        float2 u0 = unpk(acc[li][0]);
        float2 u1 = unpk(acc[li][1]);
        float2 u2 = unpk(acc[li][2]);
        float2 u3 = unpk(acc[li][3]);
        int lbase = l0 + 8 * lgrp + 2 * li;
        if (lbase < LL) {
            float4 o = make_float4(u0.x, u1.x, u2.x, u3.x);
            *(float4*)(g_tk + ((size_t)b * LL + lbase) * Cc + 4 * dgrp) = o;
        }
        if (lbase + 1 < LL) {
            float4 o = make_float4(u0.y, u1.y, u2.y, u3.y);
            *(float4*)(g_tk + ((size_t)b * LL + lbase + 1) * Cc + 4 * dgrp) = o;
        }
    }
}

// ---------------- Kernel 3: attention (flash-style, octet butterfly, f32x2) ----------------
// 32 rows/block, 8 lanes/row (8 ch each). grid (125, B), 256 threads.
__global__ __launch_bounds__(256)
void k_attn(const float* __restrict__ rpb)
{
    int b  = blockIdx.y;
    int l0 = blockIdx.x * 32;
    int t  = threadIdx.x;
    int rloc = t >> 3;
    int og   = t & 7;
    int cbase = og * 8;

    int l = l0 + rloc;
    bool rvalid = (l < LL);
    int lr = rvalid ? l : (LL - 1);
    int lh = lr / NUMS, lw = lr - lh * NUMS;

    __shared__ __align__(16) float kb [64][64];
    __shared__ __align__(16) float vvs[64][64];
    __shared__ int mhs[64];
    __shared__ int mws[64];

    // q = tokf + tokf2 (8 channels), packed as 4 f32x2
    ull q2[4];
    {
        float2* qf = (float2*)q2;
        const float4* qa = (const float4*)(g_tokf  + ((size_t)b * LL + lr) * Cc + cbase);
        const float4* qb = (const float4*)(g_tokf2 + ((size_t)b * LL + lr) * Cc + cbase);
        float4 a0 = qa[0], a1 = qa[1];
        float4 b0 = qb[0], b1 = qb[1];
        qf[0] = make_float2(a0.x + b0.x, a0.y + b0.y);
        qf[1] = make_float2(a0.z + b0.z, a0.w + b0.w);
        qf[2] = make_float2(a1.x + b1.x, a1.y + b1.y);
        qf[3] = make_float2(a1.z + b1.z, a1.w + b1.w);
    }
    ull acc2[4] = {0ull, 0ull, 0ull, 0ull};
    float mrun = -1e30f, drun = 0.f;

    const int NT = (LL + 63) / 64;   // 63 tiles
    for (int ti = 0; ti < NT; ti++) {
        int m0 = ti * 64;
        int cnt = min(64, LL - m0);
        __syncthreads();
        for (int i = t; i < 1024; i += 256) {
            int row = i >> 4, col = i & 15;
            int m = m0 + row;
            if (m < LL) {
                float4 ka = ((const float4*)(g_tokb  + ((size_t)b*LL + m)*Cc))[col];
                float4 kc = ((const float4*)(g_tokb2 + ((size_t)b*LL + m)*Cc))[col];
                ((float4*)kb)[i]  = make_float4(ka.x+kc.x, ka.y+kc.y, ka.z+kc.z, ka.w+kc.w);
                ((float4*)vvs)[i] = ((const float4*)(g_sbv + ((size_t)b*LL + m)*Cc))[col];
            } else {
                float4 z = make_float4(0,0,0,0);
                ((float4*)kb)[i] = z;
                ((float4*)vvs)[i] = z;
            }
        }
        if (t < 64) {
            int m = min(m0 + t, LL - 1);
            int mh = m / NUMS;
            mhs[t] = mh; mws[t] = m - mh * NUMS;
        }
        __syncthreads();

        // ---- pass 1: logits, octet butterfly -> lane og owns j = jg*8+og ----
        float lreg[8];
        float tmax = -1e30f;
        #pragma unroll
        for (int jg = 0; jg < 8; jg++) {
            float p[8];
            #pragma unroll
            for (int jq = 0; jq < 8; jq++) {
                int jidx = jg * 8 + jq;
                const ulonglong2* kp = (const ulonglong2*)&kb[jidx][cbase];
                ulonglong2 K0 = kp[0], K1 = kp[1];
                ull pa = fma2(q2[0], K0.x, 0ull);
                ull pb = fma2(q2[1], K0.y, 0ull);
                pa = fma2(q2[2], K1.x, pa);
                pb = fma2(q2[3], K1.y, pb);
                float2 h = unpk(add2(pa, pb));
                p[jq] = h.x + h.y;
            }
            // butterfly level 1 (xor 1)
            float ve[4];
            #pragma unroll
            for (int k = 0; k < 4; k++) {
                float mine = (og & 1) ? p[2*k+1] : p[2*k];
                float oth  = (og & 1) ? p[2*k]   : p[2*k+1];
                ve[k] = mine + __shfl_xor_sync(0xffffffff, oth, 1);
            }
            // level 2 (xor 2)
            float we[2];
            #pragma unroll
            for (int k = 0; k < 2; k++) {
                float mine = (og & 2) ? ve[2*k+1] : ve[2*k];
                float oth  = (og & 2) ? ve[2*k]   : ve[2*k+1];
                we[k] = mine + __shfl_xor_sync(0xffffffff, oth, 2);
            }
            // level 3 (xor 4)
            float mine = (og & 4) ? we[1] : we[0];
            float oth  = (og & 4) ? we[0] : we[1];
            float tot = mine + __shfl_xor_sync(0xffffffff, oth, 4);

            int jown = jg * 8 + og;
            if (jown < cnt) {
                int bi = (lh - mhs[jown] + (NUMS-1)) * TBL_W + (lw - mws[jown] + (NUMS-1));
                tot += __ldg(rpb + bi);
            } else {
                tot = -1e30f;
            }
            lreg[jg] = tot;
            tmax = fmaxf(tmax, tot);
        }
        // octet-consistent tile max
        tmax = fmaxf(tmax, __shfl_xor_sync(0xffffffff, tmax, 1));
        tmax = fmaxf(tmax, __shfl_xor_sync(0xffffffff, tmax, 2));
        tmax = fmaxf(tmax, __shfl_xor_sync(0xffffffff, tmax, 4));

        // ---- pass 2: online softmax + PV ----
        float nm = fmaxf(mrun, tmax);
        float scale = __expf(mrun - nm);
        drun *= scale;
        ull sc2 = dup2(scale);
        #pragma unroll
        for (int i = 0; i < 4; i++) acc2[i] = fma2(acc2[i], sc2, 0ull);
        #pragma unroll
        for (int jg = 0; jg < 8; jg++) {
            float pj = __expf(lreg[jg] - nm);
            drun += pj;
            #pragma unroll
            for (int jq = 0; jq < 8; jq++) {
                float pbro = __shfl_sync(0xffffffff, pj, jq, 8);
                int jidx = jg * 8 + jq;
                ull pd = dup2(pbro);
                const ulonglong2* vp = (const ulonglong2*)&vvs[jidx][cbase];
                ulonglong2 V0 = vp[0], V1 = vp[1];
                acc2[0] = fma2(pd, V0.x, acc2[0]);
                acc2[1] = fma2(pd, V0.y, acc2[1]);
                acc2[2] = fma2(pd, V1.x, acc2[2]);
                acc2[3] = fma2(pd, V1.y, acc2[3]);
            }
        }
        mrun = nm;
    }
    drun += __shfl_xor_sync(0xffffffff, drun, 1);
    drun += __shfl_xor_sync(0xffffffff, drun, 2);
    drun += __shfl_xor_sync(0xffffffff, drun, 4);
    float inv = 1.0f / drun;
    if (rvalid) {
        #pragma unroll
        for (int i = 0; i < 4; i++) {
            float2 f = unpk(acc2[i]);
            g_ns[((size_t)b * Cc + cbase + 2*i    ) * LL + l] = f.x * inv;
            g_ns[((size_t)b * Cc + cbase + 2*i + 1) * LL + l] = f.y * inv;
        }
    }
}

// ---------------- Kernel 4: fold + epilogue ----------------
__global__ __launch_bounds__(256)
void k_epilogue(const float* __restrict__ x, const float* __restrict__ mask,
                const float* __restrict__ fg_g, const float* __restrict__ fg_b,
                const float* __restrict__ bg_g, const float* __restrict__ bg_b,
                float* __restrict__ out)
{
    int idx = blockIdx.x * 256 + threadIdx.x;
    int w = idx & 255;
    int h = (idx >> 8) & 255;
    int c = (idx >> 16) & 63;
    int b = idx >> 22;

    float m   = mask[(size_t)b * HW + h * Ww + w];
    float inm = 1.0f - m;
    float xv  = x[idx];
    float ubg = (xv * inm * (1.0f + bg_g[c]) + bg_b[c]) * inm;
    float xm  = xv * m;

    int ihs[2]; int nh = 0;
    int kh0 = h & 3;
    {
        int d = h - kh0;        { int ih = d >> 2; if (ih <= NUMS-1) ihs[nh++] = ih; }
        int d2 = h - (kh0 + 4); if (d2 >= 0) { int ih = d2 >> 2; if (ih <= NUMS-1) ihs[nh++] = ih; }
    }
    int iws[2]; int nw = 0;
    int kw0 = w & 3;
    {
        int d = w - kw0;        { int iw = d >> 2; if (iw <= NUMS-1) iws[nw++] = iw; }
        int d2 = w - (kw0 + 4); if (d2 >= 0) { int iw = d2 >> 2; if (iw <= NUMS-1) iws[nw++] = iw; }
    }

    float sum = 0.f;
    size_t base = ((size_t)b * Cc + c) * LL;
    for (int a = 0; a < nh; a++) {
        for (int e = 0; e < nw; e++) {
            int lp = ihs[a] * NUMS + iws[e];
            float2 mi = g_mif[base + lp];
            float ns  = g_ns [base + lp];
            float inf_ = (xm - mi.x) * mi.y * m + mi.x * inm;
            sum += inf_ * ns + ns;
        }
    }
    int count = nh * nw;                    // 1, 2 or 4
    float invc = (count == 4) ? 0.25f : ((count == 2) ? 0.5f : 1.0f);
    float val = (sum * invc) * (1.0f + fg_g[c]) + fg_b[c];
    val = val * m + ubg;
    out[idx] = val;
}

// ---------------- launch ----------------
extern "C" void kernel_launch(void* const* d_in, const int* in_sizes, int n_in,
                              void* d_out, int out_size)
{
    const float* x       = (const float*)d_in[0];
    const float* mask    = (const float*)d_in[1];
    const float* fg_g    = (const float*)d_in[2];
    const float* fg_b    = (const float*)d_in[3];
    const float* bg_g    = (const float*)d_in[4];
    const float* bg_b    = (const float*)d_in[5];
    const float* w_fore  = (const float*)d_in[6];
    const float* w_back  = (const float*)d_in[7];
    const float* rpb     = (const float*)d_in[8];
    float* out = (float*)d_out;

    k_stats<<<Bb * LL, 256>>>(x, mask);
    k_gemm<<<dim3(32, Bb, 4), 256>>>(x, mask, w_fore, w_back);
    k_attn<<<dim3((LL + 31) / 32, Bb), 256>>>(rpb);
    k_epilogue<<<(Bb * Cc * HW) / 256, 256>>>(x, mask, fg_g, fg_b, bg_g, bg_b, out);
}

// round 6
// speedup vs baseline: 1.0282x; 1.0282x over previous
#include <cuda_runtime.h>
#include <cuda_bf16.h>

#define Bb 2
#define Cc 64
#define Hh 256
#define Ww 256
#define HW (Hh*Ww)
#define NUMS 63
#define LL (NUMS*NUMS)          // 3969
#define K2 64
#define EPSf 1e-5f
#define TBL_W (2*NUMS-1)        // 125

typedef unsigned long long ull;

__device__ __forceinline__ ull fma2(ull a, ull b, ull c){
    ull d; asm("fma.rn.f32x2 %0, %1, %2, %3;" : "=l"(d) : "l"(a), "l"(b), "l"(c)); return d;
}
__device__ __forceinline__ ull add2(ull a, ull b){
    ull d; asm("add.rn.f32x2 %0, %1, %2;" : "=l"(d) : "l"(a), "l"(b)); return d;
}
__device__ __forceinline__ ull dup2(float v){
    ull d; asm("mov.b64 %0, {%1, %1};" : "=l"(d) : "f"(v)); return d;
}
__device__ __forceinline__ float2 unpk(ull a){
    float2 r; asm("mov.b64 {%0, %1}, %2;" : "=f"(r.x), "=f"(r.y) : "l"(a)); return r;
}

// ---------------- device scratch ----------------
#define BCL (Bb*Cc*LL)
__device__ float2 g_mif [BCL];   // (fg mean, 1/fg var)  [b][c][l]
__device__ float2 g_mib [BCL];   // (bg mean, 1/bg var)  [b][c][l]
__device__ float  g_sbv [BCL];   // bg var               [b][l][c]
__device__ float  g_tokf[BCL];   // tok_f partial (c 0..31)   [b][l][c]
__device__ float  g_tokb[BCL];   // tok_b partial (c 0..31)   [b][l][c]
__device__ float  g_tokf2[BCL];  // tok_f partial (c 32..63)
__device__ float  g_tokb2[BCL];  // tok_b partial (c 32..63)
__device__ float  g_ns  [BCL];   // new_std              [b][c][l]

// ---------------- Kernel 1: per-patch statistics (unchanged from R5) ----------------
__global__ __launch_bounds__(256)
void k_stats(const float* __restrict__ x, const float* __restrict__ mask)
{
    int bl = blockIdx.x;
    int b  = bl / LL;
    int l  = bl - b * LL;
    int lh = l / NUMS, lw = l - lh * NUMS;
    int r0 = lh * 4, c0 = lw * 4;

    __shared__ float sm_m[64];
    int t = threadIdx.x;
    if (t < 64) {
        int kh = t >> 3, kw = t & 7;
        sm_m[t] = mask[(size_t)b * HW + (r0 + kh) * Ww + c0 + kw];
    }
    __syncthreads();

    int c = t >> 2;
    int j = t & 3;

    const float* xp = x + (((size_t)b * Cc + c) * Hh + r0 + 2 * j) * Ww + c0;
    float s1 = 0.f, s2 = 0.f, sm1 = 0.f, sm2 = 0.f, msum = 0.f;
    #pragma unroll
    for (int rr = 0; rr < 2; rr++) {
        float4 a = *(const float4*)(xp + rr * Ww);
        float4 bq = *(const float4*)(xp + rr * Ww + 4);
        float vv[8] = {a.x,a.y,a.z,a.w,bq.x,bq.y,bq.z,bq.w};
        #pragma unroll
        for (int kk = 0; kk < 8; kk++) {
            float m = sm_m[(2 * j + rr) * 8 + kk];
            float v = vv[kk];
            s1 += v; s2 += v * v;
            sm1 += m * v; sm2 += m * v * v;
            msum += m;
        }
    }
    #pragma unroll
    for (int d = 1; d < 4; d <<= 1) {
        s1  += __shfl_xor_sync(0xffffffff, s1,  d);
        s2  += __shfl_xor_sync(0xffffffff, s2,  d);
        sm1 += __shfl_xor_sync(0xffffffff, sm1, d);
        sm2 += __shfl_xor_sync(0xffffffff, sm2, d);
        msum+= __shfl_xor_sync(0xffffffff, msum,d);
    }
    if (j == 0) {
        float numf = msum;
        float numb = 64.0f - msum;
        float mf = sm1 / (numf + EPSf);
        float vf = (sm2 - 2.f * mf * sm1 + mf * mf * numf) / (numf + EPSf);
        float sb1 = s1 - sm1, sb2 = s2 - sm2;
        float mb = sb1 / (numb + EPSf);
        float vb = (sb2 - 2.f * mb * sb1 + mb * mb * numb) / (numb + EPSf);
        size_t o = ((size_t)b * Cc + c) * LL + l;
        g_mif[o] = make_float2(mf, 1.0f / vf);
        g_mib[o] = make_float2(mb, 1.0f / vb);
        g_sbv[((size_t)b * LL + l) * Cc + c] = vb;
    }
}

// ---------------- Kernel 2: fused in_* build + token GEMM (unchanged from R5) ----------------
__global__ __launch_bounds__(256)
void k_gemm(const float* __restrict__ x, const float* __restrict__ mask,
            const float* __restrict__ w_fore, const float* __restrict__ w_back)
{
    int tile  = blockIdx.x;              // 0..31
    int b     = blockIdx.y;
    int type  = blockIdx.z >> 1;         // 0 = fore, 1 = back
    int khalf = blockIdx.z & 1;          // channel half
    const float*  w    = type ? w_back : w_fore;
    const float2* g_mi = type ? g_mib : g_mif;
    float* g_tk = type ? (khalf ? g_tokb2 : g_tokb)
                       : (khalf ? g_tokf2 : g_tokf);

    int l0 = tile * 128;
    int t  = threadIdx.x;

    __shared__ __align__(16) float ash [32][128];
    __shared__ __align__(16) float wsh2[32][136];   // W duplicated: [k][2d],[k][2d+1]

    int la    = t & 127;
    int halfa = t >> 7;
    int lgl   = l0 + la;
    bool lvalid = lgl < LL;
    int lg = lvalid ? lgl : (LL - 1);
    int lh = lg / NUMS, lw = lg - lh * NUMS;

    unsigned int mb0 = 0, mb1 = 0;
    {
        const float* mp = mask + (size_t)b * HW + (lh * 4) * Ww + lw * 4;
        #pragma unroll
        for (int r = 0; r < 8; r++) {
            float4 a = *(const float4*)(mp + r * Ww);
            float4 bq = *(const float4*)(mp + r * Ww + 4);
            float mv[8] = {a.x,a.y,a.z,a.w,bq.x,bq.y,bq.z,bq.w};
            unsigned int bits = 0;
            #pragma unroll
            for (int kw = 0; kw < 8; kw++) {
                bool on = mv[kw] > 0.5f;
                if (type) on = !on;
                bits |= (on ? 1u : 0u) << (((r & 3) * 8) + kw);
            }
            if (r < 4) mb0 |= bits; else mb1 |= bits;
        }
    }

    int wd = t & 63;
    int wi = t >> 6;

    int lgrp = t >> 4, dgrp = t & 15;
    int c0 = khalf * 32;

    ull acc[4][4];
    #pragma unroll
    for (int i = 0; i < 4; i++)
        #pragma unroll
        for (int j2 = 0; j2 < 4; j2++) acc[i][j2] = 0ull;

    float4 xr0, xr1, xr2, xr3, wr0, wr1;
    float2 mi;

    auto LD = [&](int p) {
        int c = c0 + (p >> 1), sub = p & 1;
        const float* xp = x + (((size_t)b * Cc + c) * Hh + lh * 4 + sub * 4 + halfa * 2) * Ww + lw * 4;
        xr0 = *(const float4*)xp;
        xr1 = *(const float4*)(xp + 4);
        xr2 = *(const float4*)(xp + Ww);
        xr3 = *(const float4*)(xp + Ww + 4);
        mi  = g_mi[((size_t)b * Cc + c) * LL + lg];
        const float* wp = w + (size_t)wd * (Cc * K2) + c * K2 + sub * 32 + wi * 8;
        wr0 = *(const float4*)wp;
        wr1 = *(const float4*)(wp + 4);
    };
    LD(0);

    for (int p = 0; p < 64; p++) {
        __syncthreads();
        {
            int sub = p & 1;
            unsigned int wsel = sub ? mb1 : mb0;
            float muv = lvalid ? mi.x : 0.f;
            float isv = lvalid ? mi.y : 0.f;
            float xv[16] = {xr0.x,xr0.y,xr0.z,xr0.w, xr1.x,xr1.y,xr1.z,xr1.w,
                            xr2.x,xr2.y,xr2.z,xr2.w, xr3.x,xr3.y,xr3.z,xr3.w};
            #pragma unroll
            for (int rr = 0; rr < 2; rr++) {
                int row = halfa * 2 + rr;
                #pragma unroll
                for (int kw = 0; kw < 8; kw++) {
                    bool on = (wsel >> (row * 8 + kw)) & 1u;
                    ash[row * 8 + kw][la] = on ? (xv[rr * 8 + kw] - muv) * isv : muv;
                }
            }
        }
        {
            float wv[8] = {wr0.x,wr0.y,wr0.z,wr0.w, wr1.x,wr1.y,wr1.z,wr1.w};
            #pragma unroll
            for (int q = 0; q < 8; q++)
                *(float2*)&wsh2[wi * 8 + q][2 * wd] = make_float2(wv[q], wv[q]);
        }
        __syncthreads();
        if (p < 63) LD(p + 1);

        #pragma unroll 8
        for (int k = 0; k < 32; k++) {
            ulonglong2 A0 = *(const ulonglong2*)&ash[k][8 * lgrp];
            ulonglong2 A1 = *(const ulonglong2*)&ash[k][8 * lgrp + 4];
            ulonglong2 W0 = *(const ulonglong2*)&wsh2[k][8 * dgrp];
            ulonglong2 W1 = *(const ulonglong2*)&wsh2[k][8 * dgrp + 4];
            ull a2[4] = {A0.x, A0.y, A1.x, A1.y};
            ull wv[4] = {W0.x, W0.y, W1.x, W1.y};
            #pragma unroll
            for (int li = 0; li < 4; li++) {
                acc[li][0] = fma2(a2[li], wv[0], acc[li][0]);
                acc[li][1] = fma2(a2[li], wv[1], acc[li][1]);
                acc[li][2] = fma2(a2[li], wv[2], acc[li][2]);
                acc[li][3] = fma2(a2[li], wv[3], acc[li][3]);
            }
        }
    }

    #pragma unroll
    for (int li = 0; li < 4; li++) {
        float2 u0 = unpk(acc[li][0]);
        float2 u1 = unpk(acc[li][1]);
        float2 u2 = unpk(acc[li][2]);
        float2 u3 = unpk(acc[li][3]);
        int lbase = l0 + 8 * lgrp + 2 * li;
        if (lbase < LL) {
            float4 o = make_float4(u0.x, u1.x, u2.x, u3.x);
            *(float4*)(g_tk + ((size_t)b * LL + lbase) * Cc + 4 * dgrp) = o;
        }
        if (lbase + 1 < LL) {
            float4 o = make_float4(u0.y, u1.y, u2.y, u3.y);
            *(float4*)(g_tk + ((size_t)b * LL + lbase + 1) * Cc + 4 * dgrp) = o;
        }
    }
}

// ---------------- Kernel 3: attention (full-tile specialized, f32x2) ----------------
// 32 rows/block, 8 lanes/row (8 ch each). 62 full tiles + scalar tail (m=3968).
__global__ __launch_bounds__(256)
void k_attn(const float* __restrict__ rpb)
{
    int b  = blockIdx.y;
    int l0 = blockIdx.x * 32;
    int t  = threadIdx.x;
    int rloc = t >> 3;
    int og   = t & 7;
    int cbase = og * 8;

    int l = l0 + rloc;
    bool rvalid = (l < LL);
    int lr = rvalid ? l : (LL - 1);
    int lh = lr / NUMS, lw = lr - lh * NUMS;
    int rowconst = (lh + 62) * TBL_W + (lw + 62);

    __shared__ __align__(16) float kb [64][64];
    __shared__ __align__(16) float vvs[64][64];
    __shared__ int rpish[64];

    // q = tokf + tokf2 (8 channels), packed as 4 f32x2
    ull q2[4];
    {
        float2* qf = (float2*)q2;
        const float4* qa = (const float4*)(g_tokf  + ((size_t)b * LL + lr) * Cc + cbase);
        const float4* qb = (const float4*)(g_tokf2 + ((size_t)b * LL + lr) * Cc + cbase);
        float4 a0 = qa[0], a1 = qa[1];
        float4 b0 = qb[0], b1 = qb[1];
        qf[0] = make_float2(a0.x + b0.x, a0.y + b0.y);
        qf[1] = make_float2(a0.z + b0.z, a0.w + b0.w);
        qf[2] = make_float2(a1.x + b1.x, a1.y + b1.y);
        qf[3] = make_float2(a1.z + b1.z, a1.w + b1.w);
    }
    ull acc2[4] = {0ull, 0ull, 0ull, 0ull};
    float mrun = -1e30f, drun = 0.f;

    // ---- 62 full tiles, no bounds checks ----
    for (int ti = 0; ti < 62; ti++) {
        int m0 = ti * 64;
        __syncthreads();
        #pragma unroll
        for (int it = 0; it < 4; it++) {
            int i = t + it * 256;
            int row = i >> 4, col = i & 15;
            int m = m0 + row;
            float4 ka = ((const float4*)(g_tokb  + ((size_t)b*LL + m)*Cc))[col];
            float4 kc = ((const float4*)(g_tokb2 + ((size_t)b*LL + m)*Cc))[col];
            ((float4*)kb)[i]  = make_float4(ka.x+kc.x, ka.y+kc.y, ka.z+kc.z, ka.w+kc.w);
            ((float4*)vvs)[i] = ((const float4*)(g_sbv + ((size_t)b*LL + m)*Cc))[col];
        }
        if (t < 64) {
            int m = m0 + t;
            int mh = m / NUMS;
            rpish[t] = mh * TBL_W + (m - mh * NUMS);
        }
        __syncthreads();

        // ---- pass 1: logits, octet butterfly -> lane og owns j = jg*8+og ----
        float lreg[8];
        float tmax = -1e30f;
        #pragma unroll
        for (int jg = 0; jg < 8; jg++) {
            float p[8];
            #pragma unroll
            for (int jq = 0; jq < 8; jq++) {
                int jidx = jg * 8 + jq;
                const ulonglong2* kp = (const ulonglong2*)&kb[jidx][cbase];
                ulonglong2 K0 = kp[0], K1 = kp[1];
                ull pa = fma2(q2[0], K0.x, 0ull);
                ull pb = fma2(q2[1], K0.y, 0ull);
                pa = fma2(q2[2], K1.x, pa);
                pb = fma2(q2[3], K1.y, pb);
                float2 h = unpk(add2(pa, pb));
                p[jq] = h.x + h.y;
            }
            float ve[4];
            #pragma unroll
            for (int k = 0; k < 4; k++) {
                float mine = (og & 1) ? p[2*k+1] : p[2*k];
                float oth  = (og & 1) ? p[2*k]   : p[2*k+1];
                ve[k] = mine + __shfl_xor_sync(0xffffffff, oth, 1);
            }
            float we[2];
            #pragma unroll
            for (int k = 0; k < 2; k++) {
                float mine = (og & 2) ? ve[2*k+1] : ve[2*k];
                float oth  = (og & 2) ? ve[2*k]   : ve[2*k+1];
                we[k] = mine + __shfl_xor_sync(0xffffffff, oth, 2);
            }
            float mine = (og & 4) ? we[1] : we[0];
            float oth  = (og & 4) ? we[0] : we[1];
            float tot = mine + __shfl_xor_sync(0xffffffff, oth, 4);

            tot += __ldg(rpb + rowconst - rpish[jg * 8 + og]);
            lreg[jg] = tot;
            tmax = fmaxf(tmax, tot);
        }
        tmax = fmaxf(tmax, __shfl_xor_sync(0xffffffff, tmax, 1));
        tmax = fmaxf(tmax, __shfl_xor_sync(0xffffffff, tmax, 2));
        tmax = fmaxf(tmax, __shfl_xor_sync(0xffffffff, tmax, 4));

        // ---- pass 2: online softmax + PV ----
        float nm = fmaxf(mrun, tmax);
        float scale = __expf(mrun - nm);
        drun *= scale;
        ull sc2 = dup2(scale);
        #pragma unroll
        for (int i = 0; i < 4; i++) acc2[i] = fma2(acc2[i], sc2, 0ull);
        #pragma unroll
        for (int jg = 0; jg < 8; jg++) {
            float pj = __expf(lreg[jg] - nm);
            drun += pj;
            #pragma unroll
            for (int jq = 0; jq < 8; jq++) {
                float pbro = __shfl_sync(0xffffffff, pj, jq, 8);
                int jidx = jg * 8 + jq;
                ull pd = dup2(pbro);
                const ulonglong2* vp = (const ulonglong2*)&vvs[jidx][cbase];
                ulonglong2 V0 = vp[0], V1 = vp[1];
                acc2[0] = fma2(pd, V0.x, acc2[0]);
                acc2[1] = fma2(pd, V0.y, acc2[1]);
                acc2[2] = fma2(pd, V1.x, acc2[2]);
                acc2[3] = fma2(pd, V1.y, acc2[3]);
            }
        }
        mrun = nm;
    }

    // ---- tail: single m = 3968 ----
    {
        const int mt = LL - 1;  // 3968
        float2 qf[4];
        #pragma unroll
        for (int i = 0; i < 4; i++) qf[i] = unpk(q2[i]);
        const float4* ka = (const float4*)(g_tokb  + ((size_t)b*LL + mt)*Cc + cbase);
        const float4* kc = (const float4*)(g_tokb2 + ((size_t)b*LL + mt)*Cc + cbase);
        float4 k0 = ka[0], k1 = ka[1];
        float4 c0 = kc[0], c1 = kc[1];
        float s = qf[0].x*(k0.x+c0.x) + qf[0].y*(k0.y+c0.y)
                + qf[1].x*(k0.z+c0.z) + qf[1].y*(k0.w+c0.w)
                + qf[2].x*(k1.x+c1.x) + qf[2].y*(k1.y+c1.y)
                + qf[3].x*(k1.z+c1.z) + qf[3].y*(k1.w+c1.w);
        s += __shfl_xor_sync(0xffffffff, s, 1);
        s += __shfl_xor_sync(0xffffffff, s, 2);
        s += __shfl_xor_sync(0xffffffff, s, 4);
        // rpi(3968) = 62*125 + 62 = 7812
        s += __ldg(rpb + rowconst - 7812);
        float nm = fmaxf(mrun, s);
        float scale = __expf(mrun - nm);
        float p = __expf(s - nm);
        drun *= scale;
        if (og == 0) drun += p;
        ull sc2 = dup2(scale);
        ull pd  = dup2(p);
        const ulonglong2* vp = (const ulonglong2*)(g_sbv + ((size_t)b*LL + mt)*Cc + cbase);
        ulonglong2 V0 = vp[0], V1 = vp[1];
        acc2[0] = fma2(acc2[0], sc2, 0ull); acc2[0] = fma2(pd, V0.x, acc2[0]);
        acc2[1] = fma2(acc2[1], sc2, 0ull); acc2[1] = fma2(pd, V0.y, acc2[1]);
        acc2[2] = fma2(acc2[2], sc2, 0ull); acc2[2] = fma2(pd, V1.x, acc2[2]);
        acc2[3] = fma2(acc2[3], sc2, 0ull); acc2[3] = fma2(pd, V1.y, acc2[3]);
    }

    drun += __shfl_xor_sync(0xffffffff, drun, 1);
    drun += __shfl_xor_sync(0xffffffff, drun, 2);
    drun += __shfl_xor_sync(0xffffffff, drun, 4);
    float inv = 1.0f / drun;
    if (rvalid) {
        #pragma unroll
        for (int i = 0; i < 4; i++) {
            float2 f = unpk(acc2[i]);
            g_ns[((size_t)b * Cc + cbase + 2*i    ) * LL + l] = f.x * inv;
            g_ns[((size_t)b * Cc + cbase + 2*i + 1) * LL + l] = f.y * inv;
        }
    }
}

// ---------------- Kernel 4: fold + epilogue (4 pixels / thread) ----------------
__global__ __launch_bounds__(256)
void k_epilogue(const float* __restrict__ x, const float* __restrict__ mask,
                const float* __restrict__ fg_g, const float* __restrict__ fg_b,
                const float* __restrict__ bg_g, const float* __restrict__ bg_b,
                float* __restrict__ out)
{
    int tid = blockIdx.x * 256 + threadIdx.x;
    int idx = tid * 4;
    int w0 = idx & 255;            // multiple of 4
    int h  = (idx >> 8) & 255;
    int c  = (idx >> 16) & 63;
    int b  = idx >> 22;
    int q  = w0 >> 2;

    float4 mv = *(const float4*)(mask + (size_t)b * HW + h * Ww + w0);
    float4 xv = *(const float4*)(x + idx);

    float bgG = 1.0f + bg_g[c], bgB = bg_b[c];
    float fgG = 1.0f + fg_g[c], fgB = fg_b[c];

    // shared window set for all 4 pixels
    int ih_hi = h >> 2;  int ih_lo = ih_hi - 1;
    bool vh_hi = (ih_hi <= NUMS - 1), vh_lo = (ih_lo >= 0);
    int iw_hi = q;       int iw_lo = q - 1;
    bool vw_hi = (iw_hi <= NUMS - 1), vw_lo = (iw_lo >= 0);

    float m[4]  = {mv.x, mv.y, mv.z, mv.w};
    float xs[4] = {xv.x, xv.y, xv.z, xv.w};
    float xm[4], inm[4];
    #pragma unroll
    for (int p = 0; p < 4; p++) { inm[p] = 1.0f - m[p]; xm[p] = xs[p] * m[p]; }

    float sum[4] = {0.f, 0.f, 0.f, 0.f};
    size_t base = ((size_t)b * Cc + c) * LL;

    int ihv[2] = {ih_lo, ih_hi};  bool vav[2] = {vh_lo, vh_hi};
    int iwv[2] = {iw_lo, iw_hi};  bool vev[2] = {vw_lo, vw_hi};
    #pragma unroll
    for (int a = 0; a < 2; a++) {
        #pragma unroll
        for (int e = 0; e < 2; e++) {
            if (vav[a] && vev[e]) {
                int lp = ihv[a] * NUMS + iwv[e];
                float2 mi = g_mif[base + lp];
                float ns  = g_ns [base + lp];
                #pragma unroll
                for (int p = 0; p < 4; p++) {
                    float inf_ = (xm[p] - mi.x) * mi.y * m[p] + mi.x * inm[p];
                    sum[p] += inf_ * ns + ns;
                }
            }
        }
    }
    int cnt = ((int)vh_hi + (int)vh_lo) * ((int)vw_hi + (int)vw_lo);
    float invc = (cnt == 4) ? 0.25f : ((cnt == 2) ? 0.5f : 1.0f);

    float4 o;
    float r[4];
    #pragma unroll
    for (int p = 0; p < 4; p++) {
        float ubg = (xs[p] * inm[p] * bgG + bgB) * inm[p];
        float val = (sum[p] * invc) * fgG + fgB;
        r[p] = val * m[p] + ubg;
    }
    o.x = r[0]; o.y = r[1]; o.z = r[2]; o.w = r[3];
    *(float4*)(out + idx) = o;
}

// ---------------- launch ----------------
extern "C" void kernel_launch(void* const* d_in, const int* in_sizes, int n_in,
                              void* d_out, int out_size)
{
    const float* x       = (const float*)d_in[0];
    const float* mask    = (const float*)d_in[1];
    const float* fg_g    = (const float*)d_in[2];
    const float* fg_b    = (const float*)d_in[3];
    const float* bg_g    = (const float*)d_in[4];
    const float* bg_b    = (const float*)d_in[5];
    const float* w_fore  = (const float*)d_in[6];
    const float* w_back  = (const float*)d_in[7];
    const float* rpb     = (const float*)d_in[8];
    float* out = (float*)d_out;

    k_stats<<<Bb * LL, 256>>>(x, mask);
    k_gemm<<<dim3(32, Bb, 4), 256>>>(x, mask, w_fore, w_back);
    k_attn<<<dim3((LL + 31) / 32, Bb), 256>>>(rpb);
    k_epilogue<<<(Bb * Cc * HW) / (256 * 4), 256>>>(x, mask, fg_g, fg_b, bg_g, bg_b, out);
}

// round 7
// speedup vs baseline: 1.2567x; 1.2222x over previous
#include <cuda_runtime.h>
#include <cuda_bf16.h>

#define Bb 2
#define Cc 64
#define Hh 256
#define Ww 256
#define HW (Hh*Ww)
#define NUMS 63
#define LL (NUMS*NUMS)          // 3969
#define K2 64
#define EPSf 1e-5f
#define TBL_W (2*NUMS-1)        // 125

typedef unsigned long long ull;

__device__ __forceinline__ ull fma2(ull a, ull b, ull c){
    ull d; asm("fma.rn.f32x2 %0, %1, %2, %3;" : "=l"(d) : "l"(a), "l"(b), "l"(c)); return d;
}
__device__ __forceinline__ ull add2(ull a, ull b){
    ull d; asm("add.rn.f32x2 %0, %1, %2;" : "=l"(d) : "l"(a), "l"(b)); return d;
}
__device__ __forceinline__ ull dup2(float v){
    ull d; asm("mov.b64 %0, {%1, %1};" : "=l"(d) : "f"(v)); return d;
}
__device__ __forceinline__ float2 unpk(ull a){
    float2 r; asm("mov.b64 {%0, %1}, %2;" : "=f"(r.x), "=f"(r.y) : "l"(a)); return r;
}

// ---------------- device scratch ----------------
#define BCL (Bb*Cc*LL)
__device__ float2 g_mif [BCL];   // (fg mean, 1/fg var)  [b][c][l]
__device__ float2 g_mib [BCL];   // (bg mean, 1/bg var)  [b][c][l]
__device__ float  g_sbv [BCL];   // bg var               [b][l][c]
__device__ float  g_tokf[BCL];   // tok_f partial (c 0..31)   [b][l][c]
__device__ float  g_tokb[BCL];   // tok_b partial (c 0..31)   [b][l][c]
__device__ float  g_tokf2[BCL];  // tok_f partial (c 32..63)
__device__ float  g_tokb2[BCL];  // tok_b partial (c 32..63)
__device__ float  g_ns  [BCL];   // new_std              [b][c][l]
// attention m-split partials
__device__ float2 g_md  [2*Bb*LL];      // (mrun, drun) per [s][b][l]
__device__ float  g_pacc[2*Bb*LL*Cc];   // acc per [s][b][l][c]

// ---------------- Kernel 1: per-patch statistics (unchanged) ----------------
__global__ __launch_bounds__(256)
void k_stats(const float* __restrict__ x, const float* __restrict__ mask)
{
    int bl = blockIdx.x;
    int b  = bl / LL;
    int l  = bl - b * LL;
    int lh = l / NUMS, lw = l - lh * NUMS;
    int r0 = lh * 4, c0 = lw * 4;

    __shared__ float sm_m[64];
    int t = threadIdx.x;
    if (t < 64) {
        int kh = t >> 3, kw = t & 7;
        sm_m[t] = mask[(size_t)b * HW + (r0 + kh) * Ww + c0 + kw];
    }
    __syncthreads();

    int c = t >> 2;
    int j = t & 3;

    const float* xp = x + (((size_t)b * Cc + c) * Hh + r0 + 2 * j) * Ww + c0;
    float s1 = 0.f, s2 = 0.f, sm1 = 0.f, sm2 = 0.f, msum = 0.f;
    #pragma unroll
    for (int rr = 0; rr < 2; rr++) {
        float4 a = *(const float4*)(xp + rr * Ww);
        float4 bq = *(const float4*)(xp + rr * Ww + 4);
        float vv[8] = {a.x,a.y,a.z,a.w,bq.x,bq.y,bq.z,bq.w};
        #pragma unroll
        for (int kk = 0; kk < 8; kk++) {
            float m = sm_m[(2 * j + rr) * 8 + kk];
            float v = vv[kk];
            s1 += v; s2 += v * v;
            sm1 += m * v; sm2 += m * v * v;
            msum += m;
        }
    }
    #pragma unroll
    for (int d = 1; d < 4; d <<= 1) {
        s1  += __shfl_xor_sync(0xffffffff, s1,  d);
        s2  += __shfl_xor_sync(0xffffffff, s2,  d);
        sm1 += __shfl_xor_sync(0xffffffff, sm1, d);
        sm2 += __shfl_xor_sync(0xffffffff, sm2, d);
        msum+= __shfl_xor_sync(0xffffffff, msum,d);
    }
    if (j == 0) {
        float numf = msum;
        float numb = 64.0f - msum;
        float mf = sm1 / (numf + EPSf);
        float vf = (sm2 - 2.f * mf * sm1 + mf * mf * numf) / (numf + EPSf);
        float sb1 = s1 - sm1, sb2 = s2 - sm2;
        float mb = sb1 / (numb + EPSf);
        float vb = (sb2 - 2.f * mb * sb1 + mb * mb * numb) / (numb + EPSf);
        size_t o = ((size_t)b * Cc + c) * LL + l;
        g_mif[o] = make_float2(mf, 1.0f / vf);
        g_mib[o] = make_float2(mb, 1.0f / vb);
        g_sbv[((size_t)b * LL + l) * Cc + c] = vb;
    }
}

// ---------------- Kernel 2: token GEMM, 8L x 8D register tile ----------------
// Tile 128L x 64D, K-split by channel half. 128 threads.
// lgrp=t>>3 (8 L), dgrp=t&7 (8 D) -> 64 fp32 acc as 32 f32x2.
__global__ __launch_bounds__(128)
void k_gemm(const float* __restrict__ x, const float* __restrict__ mask,
            const float* __restrict__ w_fore, const float* __restrict__ w_back)
{
    int tile  = blockIdx.x;              // 0..31
    int b     = blockIdx.y;
    int type  = blockIdx.z >> 1;
    int khalf = blockIdx.z & 1;
    const float*  w    = type ? w_back : w_fore;
    const float2* g_mi = type ? g_mib : g_mif;
    float* g_tk = type ? (khalf ? g_tokb2 : g_tokb)
                       : (khalf ? g_tokf2 : g_tokf);

    int l0 = tile * 128;
    int t  = threadIdx.x;

    __shared__ __align__(16) float ash [32][128];
    __shared__ __align__(16) float wsh2[32][136];  // dup pairs: [k][2d],[2d+1]

    // A-side: thread la stages one l fully (32 k per phase)
    int la  = t;
    int lgl = l0 + la;
    bool lvalid = lgl < LL;
    int lg = lvalid ? lgl : (LL - 1);
    int lh = lg / NUMS, lw = lg - lh * NUMS;

    unsigned int mb0 = 0, mb1 = 0;
    {
        const float* mp = mask + (size_t)b * HW + (lh * 4) * Ww + lw * 4;
        #pragma unroll
        for (int r = 0; r < 8; r++) {
            float4 a = *(const float4*)(mp + r * Ww);
            float4 bq = *(const float4*)(mp + r * Ww + 4);
            float mv[8] = {a.x,a.y,a.z,a.w,bq.x,bq.y,bq.z,bq.w};
            unsigned int bits = 0;
            #pragma unroll
            for (int kw = 0; kw < 8; kw++) {
                bool on = mv[kw] > 0.5f;
                if (type) on = !on;
                bits |= (on ? 1u : 0u) << (((r & 3) * 8) + kw);
            }
            if (r < 4) mb0 |= bits; else mb1 |= bits;
        }
    }

    // W-side: thread (wd = t&63, wi = t>>6) stages 16 k of channel c for d=wd
    int wd = t & 63;
    int wi = t >> 6;                     // 0/1

    int lgrp = t >> 3, dgrp = t & 7;
    int c0 = khalf * 32;

    ull acc[4][8];
    #pragma unroll
    for (int i = 0; i < 4; i++)
        #pragma unroll
        for (int j2 = 0; j2 < 8; j2++) acc[i][j2] = 0ull;

    float4 xa[4], xb[4], wr[4];
    float2 mi;

    auto LD = [&](int p) {
        int c = c0 + (p >> 1), sub = p & 1;
        const float* xp = x + (((size_t)b * Cc + c) * Hh + lh * 4 + sub * 4) * Ww + lw * 4;
        #pragma unroll
        for (int r = 0; r < 4; r++) {
            xa[r] = *(const float4*)(xp + r * Ww);
            xb[r] = *(const float4*)(xp + r * Ww + 4);
        }
        mi = g_mi[((size_t)b * Cc + c) * LL + lg];
        const float* wp = w + (size_t)wd * (Cc * K2) + c * K2 + sub * 32 + wi * 16;
        #pragma unroll
        for (int r = 0; r < 4; r++) wr[r] = *(const float4*)(wp + 4 * r);
    };
    LD(0);

    for (int p = 0; p < 64; p++) {
        __syncthreads();
        // ---- stage A (4 patch rows = 32 k) ----
        {
            int sub = p & 1;
            unsigned int wsel = sub ? mb1 : mb0;
            float muv = lvalid ? mi.x : 0.f;
            float isv = lvalid ? mi.y : 0.f;
            #pragma unroll
            for (int r = 0; r < 4; r++) {
                float xv[8] = {xa[r].x,xa[r].y,xa[r].z,xa[r].w,
                               xb[r].x,xb[r].y,xb[r].z,xb[r].w};
                #pragma unroll
                for (int kw = 0; kw < 8; kw++) {
                    bool on = (wsel >> (r * 8 + kw)) & 1u;
                    ash[r * 8 + kw][la] = on ? (xv[kw] - muv) * isv : muv;
                }
            }
        }
        // ---- stage W (duplicated pairs) ----
        {
            float wv[16] = {wr[0].x,wr[0].y,wr[0].z,wr[0].w,
                            wr[1].x,wr[1].y,wr[1].z,wr[1].w,
                            wr[2].x,wr[2].y,wr[2].z,wr[2].w,
                            wr[3].x,wr[3].y,wr[3].z,wr[3].w};
            #pragma unroll
            for (int q = 0; q < 16; q++)
                *(float2*)&wsh2[wi * 16 + q][2 * wd] = make_float2(wv[q], wv[q]);
        }
        __syncthreads();
        if (p < 63) LD(p + 1);

        // ---- compute: 32 k, 8L x 8D ----
        #pragma unroll 4
        for (int k = 0; k < 32; k++) {
            ulonglong2 A0 = *(const ulonglong2*)&ash[k][8 * lgrp];
            ulonglong2 A1 = *(const ulonglong2*)&ash[k][8 * lgrp + 4];
            ulonglong2 W0 = *(const ulonglong2*)&wsh2[k][16 * dgrp];
            ulonglong2 W1 = *(const ulonglong2*)&wsh2[k][16 * dgrp + 4];
            ulonglong2 W2 = *(const ulonglong2*)&wsh2[k][16 * dgrp + 8];
            ulonglong2 W3 = *(const ulonglong2*)&wsh2[k][16 * dgrp + 12];
            ull a2[4] = {A0.x, A0.y, A1.x, A1.y};
            ull wv[8] = {W0.x, W0.y, W1.x, W1.y, W2.x, W2.y, W3.x, W3.y};
            #pragma unroll
            for (int li = 0; li < 4; li++) {
                #pragma unroll
                for (int dj = 0; dj < 8; dj++)
                    acc[li][dj] = fma2(a2[li], wv[dj], acc[li][dj]);
            }
        }
    }

    // ---- write: acc[li][dj]: l = l0+8*lgrp+2*li (+1 in .y), d = 8*dgrp+dj ----
    #pragma unroll
    for (int li = 0; li < 4; li++) {
        float lo[8], hi[8];
        #pragma unroll
        for (int dj = 0; dj < 8; dj++) {
            float2 f = unpk(acc[li][dj]);
            lo[dj] = f.x; hi[dj] = f.y;
        }
        int le = l0 + 8 * lgrp + 2 * li;
        if (le < LL) {
            float* dst = g_tk + ((size_t)b * LL + le) * Cc + 8 * dgrp;
            *(float4*)dst       = make_float4(lo[0], lo[1], lo[2], lo[3]);
            *(float4*)(dst + 4) = make_float4(lo[4], lo[5], lo[6], lo[7]);
        }
        if (le + 1 < LL) {
            float* dst = g_tk + ((size_t)b * LL + le + 1) * Cc + 8 * dgrp;
            *(float4*)dst       = make_float4(hi[0], hi[1], hi[2], hi[3]);
            *(float4*)(dst + 4) = make_float4(hi[4], hi[5], hi[6], hi[7]);
        }
    }
}

// ---------------- Kernel 3: attention, 2 rows/thread, m-split 2 ----------------
// 64 rows/block, 8 lanes/row-pair. grid (63, B, 2 splits). 256 threads.
__global__ __launch_bounds__(256)
void k_attn(const float* __restrict__ rpb)
{
    int b  = blockIdx.y;
    int s  = blockIdx.z;                  // m-split
    int l0 = blockIdx.x * 64;
    int t  = threadIdx.x;
    int rloc = t >> 3;                    // 0..31
    int og   = t & 7;
    int cbase = og * 8;

    int lA = l0 + rloc, lB = l0 + rloc + 32;
    bool vA = lA < LL, vB = lB < LL;
    int lrA = vA ? lA : (LL - 1);
    int lrB = vB ? lB : (LL - 1);
    int lhA = lrA / NUMS, lwA = lrA - lhA * NUMS;
    int lhB = lrB / NUMS, lwB = lrB - lhB * NUMS;
    int rcA = (lhA + 62) * TBL_W + (lwA + 62);
    int rcB = (lhB + 62) * TBL_W + (lwB + 62);

    __shared__ __align__(16) float kb [64][64];
    __shared__ __align__(16) float vvs[64][64];
    __shared__ int rpish[64];

    ull q2[2][4];
    {
        #pragma unroll
        for (int rr = 0; rr < 2; rr++) {
            int lr = rr ? lrB : lrA;
            float2* qf = (float2*)q2[rr];
            const float4* qa = (const float4*)(g_tokf  + ((size_t)b * LL + lr) * Cc + cbase);
            const float4* qb = (const float4*)(g_tokf2 + ((size_t)b * LL + lr) * Cc + cbase);
            float4 a0 = qa[0], a1 = qa[1];
            float4 b0 = qb[0], b1 = qb[1];
            qf[0] = make_float2(a0.x + b0.x, a0.y + b0.y);
            qf[1] = make_float2(a0.z + b0.z, a0.w + b0.w);
            qf[2] = make_float2(a1.x + b1.x, a1.y + b1.y);
            qf[3] = make_float2(a1.z + b1.z, a1.w + b1.w);
        }
    }
    ull acc2[2][4] = {{0ull,0ull,0ull,0ull},{0ull,0ull,0ull,0ull}};
    float mrun[2] = {-1e30f, -1e30f};
    float drun[2] = {0.f, 0.f};

    // 31 full tiles for this split
    for (int tt = 0; tt < 31; tt++) {
        int m0 = (s * 31 + tt) * 64;
        __syncthreads();
        #pragma unroll
        for (int it = 0; it < 4; it++) {
            int i = t + it * 256;
            int row = i >> 4, col = i & 15;
            int m = m0 + row;
            float4 ka = ((const float4*)(g_tokb  + ((size_t)b*LL + m)*Cc))[col];
            float4 kc = ((const float4*)(g_tokb2 + ((size_t)b*LL + m)*Cc))[col];
            ((float4*)kb)[i]  = make_float4(ka.x+kc.x, ka.y+kc.y, ka.z+kc.z, ka.w+kc.w);
            ((float4*)vvs)[i] = ((const float4*)(g_sbv + ((size_t)b*LL + m)*Cc))[col];
        }
        if (t < 64) {
            int m = m0 + t;
            int mh = m / NUMS;
            rpish[t] = mh * TBL_W + (m - mh * NUMS);
        }
        __syncthreads();

        // ---- pass 1: logits for both rows; lane og owns j = jg*8+og ----
        float lreg[2][8];
        float tmax[2] = {-1e30f, -1e30f};
        #pragma unroll
        for (int jg = 0; jg < 8; jg++) {
            float p[2][8];
            #pragma unroll
            for (int jq = 0; jq < 8; jq++) {
                int jidx = jg * 8 + jq;
                const ulonglong2* kp = (const ulonglong2*)&kb[jidx][cbase];
                ulonglong2 K0 = kp[0], K1 = kp[1];
                #pragma unroll
                for (int rr = 0; rr < 2; rr++) {
                    ull pa = fma2(q2[rr][0], K0.x, 0ull);
                    ull pb = fma2(q2[rr][1], K0.y, 0ull);
                    pa = fma2(q2[rr][2], K1.x, pa);
                    pb = fma2(q2[rr][3], K1.y, pb);
                    float2 h = unpk(add2(pa, pb));
                    p[rr][jq] = h.x + h.y;
                }
            }
            #pragma unroll
            for (int rr = 0; rr < 2; rr++) {
                float ve[4];
                #pragma unroll
                for (int k = 0; k < 4; k++) {
                    float mine = (og & 1) ? p[rr][2*k+1] : p[rr][2*k];
                    float oth  = (og & 1) ? p[rr][2*k]   : p[rr][2*k+1];
                    ve[k] = mine + __shfl_xor_sync(0xffffffff, oth, 1);
                }
                float we[2];
                #pragma unroll
                for (int k = 0; k < 2; k++) {
                    float mine = (og & 2) ? ve[2*k+1] : ve[2*k];
                    float oth  = (og & 2) ? ve[2*k]   : ve[2*k+1];
                    we[k] = mine + __shfl_xor_sync(0xffffffff, oth, 2);
                }
                float mine = (og & 4) ? we[1] : we[0];
                float oth  = (og & 4) ? we[0] : we[1];
                float tot = mine + __shfl_xor_sync(0xffffffff, oth, 4);
                int rc = rr ? rcB : rcA;
                tot += __ldg(rpb + rc - rpish[jg * 8 + og]);
                lreg[rr][jg] = tot;
                tmax[rr] = fmaxf(tmax[rr], tot);
            }
        }
        #pragma unroll
        for (int rr = 0; rr < 2; rr++) {
            tmax[rr] = fmaxf(tmax[rr], __shfl_xor_sync(0xffffffff, tmax[rr], 1));
            tmax[rr] = fmaxf(tmax[rr], __shfl_xor_sync(0xffffffff, tmax[rr], 2));
            tmax[rr] = fmaxf(tmax[rr], __shfl_xor_sync(0xffffffff, tmax[rr], 4));
        }

        // ---- pass 2: online softmax + PV (V loads shared by both rows) ----
        float nm[2], pj[2];
        ull sc2;
        #pragma unroll
        for (int rr = 0; rr < 2; rr++) {
            nm[rr] = fmaxf(mrun[rr], tmax[rr]);
            float scale = __expf(mrun[rr] - nm[rr]);
            drun[rr] *= scale;
            sc2 = dup2(scale);
            #pragma unroll
            for (int i = 0; i < 4; i++) acc2[rr][i] = fma2(acc2[rr][i], sc2, 0ull);
            mrun[rr] = nm[rr];
        }
        #pragma unroll
        for (int jg = 0; jg < 8; jg++) {
            pj[0] = __expf(lreg[0][jg] - nm[0]);
            pj[1] = __expf(lreg[1][jg] - nm[1]);
            drun[0] += pj[0];
            drun[1] += pj[1];
            #pragma unroll
            for (int jq = 0; jq < 8; jq++) {
                float p0 = __shfl_sync(0xffffffff, pj[0], jq, 8);
                float p1 = __shfl_sync(0xffffffff, pj[1], jq, 8);
                int jidx = jg * 8 + jq;
                const ulonglong2* vp = (const ulonglong2*)&vvs[jidx][cbase];
                ulonglong2 V0 = vp[0], V1 = vp[1];
                ull pd0 = dup2(p0), pd1 = dup2(p1);
                acc2[0][0] = fma2(pd0, V0.x, acc2[0][0]);
                acc2[0][1] = fma2(pd0, V0.y, acc2[0][1]);
                acc2[0][2] = fma2(pd0, V1.x, acc2[0][2]);
                acc2[0][3] = fma2(pd0, V1.y, acc2[0][3]);
                acc2[1][0] = fma2(pd1, V0.x, acc2[1][0]);
                acc2[1][1] = fma2(pd1, V0.y, acc2[1][1]);
                acc2[1][2] = fma2(pd1, V1.x, acc2[1][2]);
                acc2[1][3] = fma2(pd1, V1.y, acc2[1][3]);
            }
        }
    }

    // ---- tail m = 3968, split 1 only ----
    if (s == 1) {
        const int mt = LL - 1;
        const float4* ka = (const float4*)(g_tokb  + ((size_t)b*LL + mt)*Cc + cbase);
        const float4* kc = (const float4*)(g_tokb2 + ((size_t)b*LL + mt)*Cc + cbase);
        float4 k0 = ka[0], k1 = ka[1];
        float4 c0 = kc[0], c1 = kc[1];
        const ulonglong2* vp = (const ulonglong2*)(g_sbv + ((size_t)b*LL + mt)*Cc + cbase);
        ulonglong2 V0 = vp[0], V1 = vp[1];
        #pragma unroll
        for (int rr = 0; rr < 2; rr++) {
            float2 qf[4];
            #pragma unroll
            for (int i = 0; i < 4; i++) qf[i] = unpk(q2[rr][i]);
            float sv = qf[0].x*(k0.x+c0.x) + qf[0].y*(k0.y+c0.y)
                     + qf[1].x*(k0.z+c0.z) + qf[1].y*(k0.w+c0.w)
                     + qf[2].x*(k1.x+c1.x) + qf[2].y*(k1.y+c1.y)
                     + qf[3].x*(k1.z+c1.z) + qf[3].y*(k1.w+c1.w);
            sv += __shfl_xor_sync(0xffffffff, sv, 1);
            sv += __shfl_xor_sync(0xffffffff, sv, 2);
            sv += __shfl_xor_sync(0xffffffff, sv, 4);
            int rc = rr ? rcB : rcA;
            sv += __ldg(rpb + rc - 7812);   // rpi(3968) = 62*125+62
            float nm = fmaxf(mrun[rr], sv);
            float scale = __expf(mrun[rr] - nm);
            float p = __expf(sv - nm);
            drun[rr] *= scale;
            if (og == 0) drun[rr] += p;
            ull sc2 = dup2(scale);
            ull pd  = dup2(p);
            #pragma unroll
            for (int i = 0; i < 4; i++) acc2[rr][i] = fma2(acc2[rr][i], sc2, 0ull);
            acc2[rr][0] = fma2(pd, V0.x, acc2[rr][0]);
            acc2[rr][1] = fma2(pd, V0.y, acc2[rr][1]);
            acc2[rr][2] = fma2(pd, V1.x, acc2[rr][2]);
            acc2[rr][3] = fma2(pd, V1.y, acc2[rr][3]);
            mrun[rr] = nm;
        }
    }

    // ---- store partials ----
    #pragma unroll
    for (int rr = 0; rr < 2; rr++) {
        float d = drun[rr];
        d += __shfl_xor_sync(0xffffffff, d, 1);
        d += __shfl_xor_sync(0xffffffff, d, 2);
        d += __shfl_xor_sync(0xffffffff, d, 4);
        bool v = rr ? vB : vA;
        int l = rr ? lB : lA;
        if (v) {
            float* dst = g_pacc + (((size_t)s * Bb + b) * LL + l) * Cc + cbase;
            #pragma unroll
            for (int i = 0; i < 4; i++) {
                float2 f = unpk(acc2[rr][i]);
                dst[2*i]   = f.x;
                dst[2*i+1] = f.y;
            }
            if (og == 0) g_md[((size_t)s * Bb + b) * LL + l] = make_float2(mrun[rr], d);
        }
    }
}

// ---------------- Kernel 3b: combine m-splits -> g_ns ----------------
__global__ __launch_bounds__(256)
void k_combine()
{
    int idx = blockIdx.x * 256 + threadIdx.x;
    if (idx >= Bb * LL * Cc) return;
    int c   = idx & 63;
    int row = idx >> 6;
    int l   = row % LL;
    int b   = row / LL;
    float2 md0 = g_md[(size_t)b * LL + l];
    float2 md1 = g_md[((size_t)Bb + b) * LL + l];
    float M  = fmaxf(md0.x, md1.x);
    float w0 = __expf(md0.x - M);
    float w1 = __expf(md1.x - M);
    float a0 = g_pacc[((size_t)b * LL + l) * Cc + c];
    float a1 = g_pacc[(((size_t)Bb + b) * LL + l) * Cc + c];
    g_ns[((size_t)b * Cc + c) * LL + l] =
        (w0 * a0 + w1 * a1) / (w0 * md0.y + w1 * md1.y);
}

// ---------------- Kernel 4: fold + epilogue (unchanged) ----------------
__global__ __launch_bounds__(256)
void k_epilogue(const float* __restrict__ x, const float* __restrict__ mask,
                const float* __restrict__ fg_g, const float* __restrict__ fg_b,
                const float* __restrict__ bg_g, const float* __restrict__ bg_b,
                float* __restrict__ out)
{
    int tid = blockIdx.x * 256 + threadIdx.x;
    int idx = tid * 4;
    int w0 = idx & 255;
    int h  = (idx >> 8) & 255;
    int c  = (idx >> 16) & 63;
    int b  = idx >> 22;
    int q  = w0 >> 2;

    float4 mv = *(const float4*)(mask + (size_t)b * HW + h * Ww + w0);
    float4 xv = *(const float4*)(x + idx);

    float bgG = 1.0f + bg_g[c], bgB = bg_b[c];
    float fgG = 1.0f + fg_g[c], fgB = fg_b[c];

    int ih_hi = h >> 2;  int ih_lo = ih_hi - 1;
    bool vh_hi = (ih_hi <= NUMS - 1), vh_lo = (ih_lo >= 0);
    int iw_hi = q;       int iw_lo = q - 1;
    bool vw_hi = (iw_hi <= NUMS - 1), vw_lo = (iw_lo >= 0);

    float m[4]  = {mv.x, mv.y, mv.z, mv.w};
    float xs[4] = {xv.x, xv.y, xv.z, xv.w};
    float xm[4], inm[4];
    #pragma unroll
    for (int p = 0; p < 4; p++) { inm[p] = 1.0f - m[p]; xm[p] = xs[p] * m[p]; }

    float sum[4] = {0.f, 0.f, 0.f, 0.f};
    size_t base = ((size_t)b * Cc + c) * LL;

    int ihv[2] = {ih_lo, ih_hi};  bool vav[2] = {vh_lo, vh_hi};
    int iwv[2] = {iw_lo, iw_hi};  bool vev[2] = {vw_lo, vw_hi};
    #pragma unroll
    for (int a = 0; a < 2; a++) {
        #pragma unroll
        for (int e = 0; e < 2; e++) {
            if (vav[a] && vev[e]) {
                int lp = ihv[a] * NUMS + iwv[e];
                float2 mi = g_mif[base + lp];
                float ns  = g_ns [base + lp];
                #pragma unroll
                for (int p = 0; p < 4; p++) {
                    float inf_ = (xm[p] - mi.x) * mi.y * m[p] + mi.x * inm[p];
                    sum[p] += inf_ * ns + ns;
                }
            }
        }
    }
    int cnt = ((int)vh_hi + (int)vh_lo) * ((int)vw_hi + (int)vw_lo);
    float invc = (cnt == 4) ? 0.25f : ((cnt == 2) ? 0.5f : 1.0f);

    float r[4];
    #pragma unroll
    for (int p = 0; p < 4; p++) {
        float ubg = (xs[p] * inm[p] * bgG + bgB) * inm[p];
        float val = (sum[p] * invc) * fgG + fgB;
        r[p] = val * m[p] + ubg;
    }
    *(float4*)(out + idx) = make_float4(r[0], r[1], r[2], r[3]);
}

// ---------------- launch ----------------
extern "C" void kernel_launch(void* const* d_in, const int* in_sizes, int n_in,
                              void* d_out, int out_size)
{
    const float* x       = (const float*)d_in[0];
    const float* mask    = (const float*)d_in[1];
    const float* fg_g    = (const float*)d_in[2];
    const float* fg_b    = (const float*)d_in[3];
    const float* bg_g    = (const float*)d_in[4];
    const float* bg_b    = (const float*)d_in[5];
    const float* w_fore  = (const float*)d_in[6];
    const float* w_back  = (const float*)d_in[7];
    const float* rpb     = (const float*)d_in[8];
    float* out = (float*)d_out;

    k_stats<<<Bb * LL, 256>>>(x, mask);
    k_gemm<<<dim3(32, Bb, 4), 128>>>(x, mask, w_fore, w_back);
    k_attn<<<dim3(63, Bb, 2), 256>>>(rpb);
    k_combine<<<(Bb * LL * Cc + 255) / 256, 256>>>();
    k_epilogue<<<(Bb * Cc * HW) / (256 * 4), 256>>>(x, mask, fg_g, fg_b, bg_g, bg_b, out);
}

// round 8
// speedup vs baseline: 2.3826x; 1.8960x over previous
#include <cuda_runtime.h>
#include <cuda_bf16.h>

#define Bb 2
#define Cc 64
#define Hh 256
#define Ww 256
#define HW (Hh*Ww)
#define NUMS 63
#define LL (NUMS*NUMS)          // 3969
#define K2 64
#define EPSf 1e-5f
#define TBL_W (2*NUMS-1)        // 125

typedef unsigned long long ull;

__device__ __forceinline__ ull fma2(ull a, ull b, ull c){
    ull d; asm("fma.rn.f32x2 %0, %1, %2, %3;" : "=l"(d) : "l"(a), "l"(b), "l"(c)); return d;
}
__device__ __forceinline__ ull add2(ull a, ull b){
    ull d; asm("add.rn.f32x2 %0, %1, %2;" : "=l"(d) : "l"(a), "l"(b)); return d;
}
__device__ __forceinline__ ull dup2(float v){
    ull d; asm("mov.b64 %0, {%1, %1};" : "=l"(d) : "f"(v)); return d;
}
__device__ __forceinline__ float2 unpk(ull a){
    float2 r; asm("mov.b64 {%0, %1}, %2;" : "=f"(r.x), "=f"(r.y) : "l"(a)); return r;
}

// ---------------- device scratch ----------------
#define BCL (Bb*Cc*LL)
__device__ float2 g_mif [BCL];
__device__ float2 g_mib [BCL];
__device__ float  g_sbv [BCL];
__device__ float  g_tokf[BCL];
__device__ float  g_tokb[BCL];
__device__ float  g_tokf2[BCL];
__device__ float  g_tokb2[BCL];
__device__ float  g_ns  [BCL];
__device__ float2 g_md  [2*Bb*LL];
__device__ float  g_pacc[2*Bb*LL*Cc];

// ---------------- Kernel 1: per-patch statistics (unchanged) ----------------
__global__ __launch_bounds__(256)
void k_stats(const float* __restrict__ x, const float* __restrict__ mask)
{
    int bl = blockIdx.x;
    int b  = bl / LL;
    int l  = bl - b * LL;
    int lh = l / NUMS, lw = l - lh * NUMS;
    int r0 = lh * 4, c0 = lw * 4;

    __shared__ float sm_m[64];
    int t = threadIdx.x;
    if (t < 64) {
        int kh = t >> 3, kw = t & 7;
        sm_m[t] = mask[(size_t)b * HW + (r0 + kh) * Ww + c0 + kw];
    }
    __syncthreads();

    int c = t >> 2;
    int j = t & 3;

    const float* xp = x + (((size_t)b * Cc + c) * Hh + r0 + 2 * j) * Ww + c0;
    float s1 = 0.f, s2 = 0.f, sm1 = 0.f, sm2 = 0.f, msum = 0.f;
    #pragma unroll
    for (int rr = 0; rr < 2; rr++) {
        float4 a = *(const float4*)(xp + rr * Ww);
        float4 bq = *(const float4*)(xp + rr * Ww + 4);
        float vv[8] = {a.x,a.y,a.z,a.w,bq.x,bq.y,bq.z,bq.w};
        #pragma unroll
        for (int kk = 0; kk < 8; kk++) {
            float m = sm_m[(2 * j + rr) * 8 + kk];
            float v = vv[kk];
            s1 += v; s2 += v * v;
            sm1 += m * v; sm2 += m * v * v;
            msum += m;
        }
    }
    #pragma unroll
    for (int d = 1; d < 4; d <<= 1) {
        s1  += __shfl_xor_sync(0xffffffff, s1,  d);
        s2  += __shfl_xor_sync(0xffffffff, s2,  d);
        sm1 += __shfl_xor_sync(0xffffffff, sm1, d);
        sm2 += __shfl_xor_sync(0xffffffff, sm2, d);
        msum+= __shfl_xor_sync(0xffffffff, msum,d);
    }
    if (j == 0) {
        float numf = msum;
        float numb = 64.0f - msum;
        float mf = sm1 / (numf + EPSf);
        float vf = (sm2 - 2.f * mf * sm1 + mf * mf * numf) / (numf + EPSf);
        float sb1 = s1 - sm1, sb2 = s2 - sm2;
        float mb = sb1 / (numb + EPSf);
        float vb = (sb2 - 2.f * mb * sb1 + mb * mb * numb) / (numb + EPSf);
        size_t o = ((size_t)b * Cc + c) * LL + l;
        g_mif[o] = make_float2(mf, 1.0f / vf);
        g_mib[o] = make_float2(mb, 1.0f / vb);
        g_sbv[((size_t)b * LL + l) * Cc + c] = vb;
    }
}

// ---------------- Kernel 2: token GEMM, 8L x 8D, non-dup W staging ----------------
__global__ __launch_bounds__(128)
void k_gemm(const float* __restrict__ x, const float* __restrict__ mask,
            const float* __restrict__ w_fore, const float* __restrict__ w_back)
{
    int tile  = blockIdx.x;
    int b     = blockIdx.y;
    int type  = blockIdx.z >> 1;
    int khalf = blockIdx.z & 1;
    const float*  w    = type ? w_back : w_fore;
    const float2* g_mi = type ? g_mib : g_mif;
    float* g_tk = type ? (khalf ? g_tokb2 : g_tokb)
                       : (khalf ? g_tokf2 : g_tokf);

    int l0 = tile * 128;
    int t  = threadIdx.x;

    __shared__ __align__(16) float ash[32][128];
    __shared__ __align__(16) float wsh[32][68];

    int la  = t;
    int lgl = l0 + la;
    bool lvalid = lgl < LL;
    int lg = lvalid ? lgl : (LL - 1);
    int lh = lg / NUMS, lw = lg - lh * NUMS;

    unsigned int mb0 = 0, mb1 = 0;
    {
        const float* mp = mask + (size_t)b * HW + (lh * 4) * Ww + lw * 4;
        #pragma unroll
        for (int r = 0; r < 8; r++) {
            float4 a = *(const float4*)(mp + r * Ww);
            float4 bq = *(const float4*)(mp + r * Ww + 4);
            float mv[8] = {a.x,a.y,a.z,a.w,bq.x,bq.y,bq.z,bq.w};
            unsigned int bits = 0;
            #pragma unroll
            for (int kw = 0; kw < 8; kw++) {
                bool on = mv[kw] > 0.5f;
                if (type) on = !on;
                bits |= (on ? 1u : 0u) << (((r & 3) * 8) + kw);
            }
            if (r < 4) mb0 |= bits; else mb1 |= bits;
        }
    }

    int wd = t & 63;
    int wi = t >> 6;

    int lgrp = t >> 3, dgrp = t & 7;
    int c0 = khalf * 32;

    ull acc[4][8];
    #pragma unroll
    for (int i = 0; i < 4; i++)
        #pragma unroll
        for (int j2 = 0; j2 < 8; j2++) acc[i][j2] = 0ull;

    float4 xa[4], xb[4], wr[4];
    float2 mi;

    auto LD = [&](int p) {
        int c = c0 + (p >> 1), sub = p & 1;
        const float* xp = x + (((size_t)b * Cc + c) * Hh + lh * 4 + sub * 4) * Ww + lw * 4;
        #pragma unroll
        for (int r = 0; r < 4; r++) {
            xa[r] = *(const float4*)(xp + r * Ww);
            xb[r] = *(const float4*)(xp + r * Ww + 4);
        }
        mi = g_mi[((size_t)b * Cc + c) * LL + lg];
        const float* wp = w + (size_t)wd * (Cc * K2) + c * K2 + sub * 32 + wi * 16;
        #pragma unroll
        for (int r = 0; r < 4; r++) wr[r] = *(const float4*)(wp + 4 * r);
    };
    LD(0);

    for (int p = 0; p < 64; p++) {
        __syncthreads();
        {
            int sub = p & 1;
            unsigned int wsel = sub ? mb1 : mb0;
            float muv = lvalid ? mi.x : 0.f;
            float isv = lvalid ? mi.y : 0.f;
            #pragma unroll
            for (int r = 0; r < 4; r++) {
                float xv[8] = {xa[r].x,xa[r].y,xa[r].z,xa[r].w,
                               xb[r].x,xb[r].y,xb[r].z,xb[r].w};
                #pragma unroll
                for (int kw = 0; kw < 8; kw++) {
                    bool on = (wsel >> (r * 8 + kw)) & 1u;
                    ash[r * 8 + kw][la] = on ? (xv[kw] - muv) * isv : muv;
                }
            }
        }
        {
            float wv[16] = {wr[0].x,wr[0].y,wr[0].z,wr[0].w,
                            wr[1].x,wr[1].y,wr[1].z,wr[1].w,
                            wr[2].x,wr[2].y,wr[2].z,wr[2].w,
                            wr[3].x,wr[3].y,wr[3].z,wr[3].w};
            #pragma unroll
            for (int q = 0; q < 16; q++)
                wsh[wi * 16 + q][wd] = wv[q];
        }
        __syncthreads();
        if (p < 63) LD(p + 1);

        #pragma unroll 4
        for (int k = 0; k < 32; k++) {
            ulonglong2 A0 = *(const ulonglong2*)&ash[k][8 * lgrp];
            ulonglong2 A1 = *(const ulonglong2*)&ash[k][8 * lgrp + 4];
            float4 w0 = *(const float4*)&wsh[k][8 * dgrp];
            float4 w1 = *(const float4*)&wsh[k][8 * dgrp + 4];
            ull a2[4] = {A0.x, A0.y, A1.x, A1.y};
            ull wv[8] = {dup2(w0.x), dup2(w0.y), dup2(w0.z), dup2(w0.w),
                         dup2(w1.x), dup2(w1.y), dup2(w1.z), dup2(w1.w)};
            #pragma unroll
            for (int li = 0; li < 4; li++) {
                #pragma unroll
                for (int dj = 0; dj < 8; dj++)
                    acc[li][dj] = fma2(a2[li], wv[dj], acc[li][dj]);
            }
        }
    }

    #pragma unroll
    for (int li = 0; li < 4; li++) {
        float lo[8], hi[8];
        #pragma unroll
        for (int dj = 0; dj < 8; dj++) {
            float2 f = unpk(acc[li][dj]);
            lo[dj] = f.x; hi[dj] = f.y;
        }
        int le = l0 + 8 * lgrp + 2 * li;
        if (le < LL) {
            float* dst = g_tk + ((size_t)b * LL + le) * Cc + 8 * dgrp;
            *(float4*)dst       = make_float4(lo[0], lo[1], lo[2], lo[3]);
            *(float4*)(dst + 4) = make_float4(lo[4], lo[5], lo[6], lo[7]);
        }
        if (le + 1 < LL) {
            float* dst = g_tk + ((size_t)b * LL + le + 1) * Cc + 8 * dgrp;
            *(float4*)dst       = make_float4(hi[0], hi[1], hi[2], hi[3]);
            *(float4*)(dst + 4) = make_float4(hi[4], hi[5], hi[6], hi[7]);
        }
    }
}

// ---------------- Kernel 3: attention, 4 rows/thread, m-split 2 ----------------
// 64 rows/block, 128 threads: rloc=t>>3 (16 groups), og=t&7, rows rloc+{0,16,32,48}.
__global__ __launch_bounds__(128)
void k_attn(const float* __restrict__ rpb)
{
    int b  = blockIdx.y;
    int s  = blockIdx.z;
    int l0 = blockIdx.x * 64;
    int t  = threadIdx.x;
    int rloc = t >> 3;
    int og   = t & 7;
    int cbase = og * 8;

    int lrow[4]; bool vrow[4]; int rc[4];
    #pragma unroll
    for (int rr = 0; rr < 4; rr++) {
        int l = l0 + rloc + rr * 16;
        vrow[rr] = (l < LL);
        int lr = vrow[rr] ? l : (LL - 1);
        lrow[rr] = lr;
        int lh = lr / NUMS, lw = lr - lh * NUMS;
        rc[rr] = (lh + 62) * TBL_W + (lw + 62);
    }

    __shared__ __align__(16) float kb [64][64];
    __shared__ __align__(16) float vvs[64][64];
    __shared__ int rpish[64];

    ull q2[4][4];
    #pragma unroll
    for (int rr = 0; rr < 4; rr++) {
        float2* qf = (float2*)q2[rr];
        const float4* qa = (const float4*)(g_tokf  + ((size_t)b * LL + lrow[rr]) * Cc + cbase);
        const float4* qb = (const float4*)(g_tokf2 + ((size_t)b * LL + lrow[rr]) * Cc + cbase);
        float4 a0 = qa[0], a1 = qa[1];
        float4 b0 = qb[0], b1 = qb[1];
        qf[0] = make_float2(a0.x + b0.x, a0.y + b0.y);
        qf[1] = make_float2(a0.z + b0.z, a0.w + b0.w);
        qf[2] = make_float2(a1.x + b1.x, a1.y + b1.y);
        qf[3] = make_float2(a1.z + b1.z, a1.w + b1.w);
    }
    ull acc2[4][4];
    #pragma unroll
    for (int rr = 0; rr < 4; rr++)
        #pragma unroll
        for (int i = 0; i < 4; i++) acc2[rr][i] = 0ull;
    float mrun[4] = {-1e30f,-1e30f,-1e30f,-1e30f};
    float drun[4] = {0.f,0.f,0.f,0.f};

    for (int tt = 0; tt < 31; tt++) {
        int m0 = (s * 31 + tt) * 64;
        __syncthreads();
        #pragma unroll
        for (int it = 0; it < 8; it++) {
            int i = t + it * 128;
            int row = i >> 4, col = i & 15;
            int m = m0 + row;
            float4 ka = ((const float4*)(g_tokb  + ((size_t)b*LL + m)*Cc))[col];
            float4 kc = ((const float4*)(g_tokb2 + ((size_t)b*LL + m)*Cc))[col];
            ((float4*)kb)[i]  = make_float4(ka.x+kc.x, ka.y+kc.y, ka.z+kc.z, ka.w+kc.w);
            ((float4*)vvs)[i] = ((const float4*)(g_sbv + ((size_t)b*LL + m)*Cc))[col];
        }
        if (t < 64) {
            int m = m0 + t;
            int mh = m / NUMS;
            rpish[t] = mh * TBL_W + (m - mh * NUMS);
        }
        __syncthreads();

        // ---- pass 1: logits for 4 rows; lane og owns j = jg*8+og ----
        float lreg[4][8];
        float tmax[4] = {-1e30f,-1e30f,-1e30f,-1e30f};
        #pragma unroll
        for (int jg = 0; jg < 8; jg++) {
            float p[4][8];
            #pragma unroll
            for (int jq = 0; jq < 8; jq++) {
                int jidx = jg * 8 + jq;
                const ulonglong2* kp = (const ulonglong2*)&kb[jidx][cbase];
                ulonglong2 K0 = kp[0], K1 = kp[1];
                #pragma unroll
                for (int rr = 0; rr < 4; rr++) {
                    ull pa = fma2(q2[rr][0], K0.x, 0ull);
                    ull pb = fma2(q2[rr][1], K0.y, 0ull);
                    pa = fma2(q2[rr][2], K1.x, pa);
                    pb = fma2(q2[rr][3], K1.y, pb);
                    float2 h = unpk(add2(pa, pb));
                    p[rr][jq] = h.x + h.y;
                }
            }
            int bofs = rpish[jg * 8 + og];
            #pragma unroll
            for (int rr = 0; rr < 4; rr++) {
                float ve[4];
                #pragma unroll
                for (int k = 0; k < 4; k++) {
                    float mine = (og & 1) ? p[rr][2*k+1] : p[rr][2*k];
                    float oth  = (og & 1) ? p[rr][2*k]   : p[rr][2*k+1];
                    ve[k] = mine + __shfl_xor_sync(0xffffffff, oth, 1);
                }
                float we[2];
                #pragma unroll
                for (int k = 0; k < 2; k++) {
                    float mine = (og & 2) ? ve[2*k+1] : ve[2*k];
                    float oth  = (og & 2) ? ve[2*k]   : ve[2*k+1];
                    we[k] = mine + __shfl_xor_sync(0xffffffff, oth, 2);
                }
                float mine = (og & 4) ? we[1] : we[0];
                float oth  = (og & 4) ? we[0] : we[1];
                float tot = mine + __shfl_xor_sync(0xffffffff, oth, 4);
                tot += __ldg(rpb + rc[rr] - bofs);
                lreg[rr][jg] = tot;
                tmax[rr] = fmaxf(tmax[rr], tot);
            }
        }
        #pragma unroll
        for (int rr = 0; rr < 4; rr++) {
            tmax[rr] = fmaxf(tmax[rr], __shfl_xor_sync(0xffffffff, tmax[rr], 1));
            tmax[rr] = fmaxf(tmax[rr], __shfl_xor_sync(0xffffffff, tmax[rr], 2));
            tmax[rr] = fmaxf(tmax[rr], __shfl_xor_sync(0xffffffff, tmax[rr], 4));
        }

        // ---- pass 2: online softmax + PV ----
        float nm[4];
        #pragma unroll
        for (int rr = 0; rr < 4; rr++) {
            nm[rr] = fmaxf(mrun[rr], tmax[rr]);
            float scale = __expf(mrun[rr] - nm[rr]);
            drun[rr] *= scale;
            ull sc2 = dup2(scale);
            #pragma unroll
            for (int i = 0; i < 4; i++) acc2[rr][i] = fma2(acc2[rr][i], sc2, 0ull);
            mrun[rr] = nm[rr];
        }
        #pragma unroll
        for (int jg = 0; jg < 8; jg++) {
            float pj[4];
            #pragma unroll
            for (int rr = 0; rr < 4; rr++) {
                pj[rr] = __expf(lreg[rr][jg] - nm[rr]);
                drun[rr] += pj[rr];
            }
            #pragma unroll
            for (int jq = 0; jq < 8; jq++) {
                int jidx = jg * 8 + jq;
                const ulonglong2* vp = (const ulonglong2*)&vvs[jidx][cbase];
                ulonglong2 V0 = vp[0], V1 = vp[1];
                #pragma unroll
                for (int rr = 0; rr < 4; rr++) {
                    float pb = __shfl_sync(0xffffffff, pj[rr], jq, 8);
                    ull pd = dup2(pb);
                    acc2[rr][0] = fma2(pd, V0.x, acc2[rr][0]);
                    acc2[rr][1] = fma2(pd, V0.y, acc2[rr][1]);
                    acc2[rr][2] = fma2(pd, V1.x, acc2[rr][2]);
                    acc2[rr][3] = fma2(pd, V1.y, acc2[rr][3]);
                }
            }
        }
    }

    // ---- tail m = 3968, split 1 only ----
    if (s == 1) {
        const int mt = LL - 1;
        const float4* ka = (const float4*)(g_tokb  + ((size_t)b*LL + mt)*Cc + cbase);
        const float4* kc = (const float4*)(g_tokb2 + ((size_t)b*LL + mt)*Cc + cbase);
        float4 k0 = ka[0], k1 = ka[1];
        float4 c0 = kc[0], c1 = kc[1];
        const ulonglong2* vp = (const ulonglong2*)(g_sbv + ((size_t)b*LL + mt)*Cc + cbase);
        ulonglong2 V0 = vp[0], V1 = vp[1];
        #pragma unroll
        for (int rr = 0; rr < 4; rr++) {
            float2 qf[4];
            #pragma unroll
            for (int i = 0; i < 4; i++) qf[i] = unpk(q2[rr][i]);
            float sv = qf[0].x*(k0.x+c0.x) + qf[0].y*(k0.y+c0.y)
                     + qf[1].x*(k0.z+c0.z) + qf[1].y*(k0.w+c0.w)
                     + qf[2].x*(k1.x+c1.x) + qf[2].y*(k1.y+c1.y)
                     + qf[3].x*(k1.z+c1.z) + qf[3].y*(k1.w+c1.w);
            sv += __shfl_xor_sync(0xffffffff, sv, 1);
            sv += __shfl_xor_sync(0xffffffff, sv, 2);
            sv += __shfl_xor_sync(0xffffffff, sv, 4);
            sv += __ldg(rpb + rc[rr] - 7812);
            float nm = fmaxf(mrun[rr], sv);
            float scale = __expf(mrun[rr] - nm);
            float p = __expf(sv - nm);
            drun[rr] *= scale;
            if (og == 0) drun[rr] += p;
            ull sc2 = dup2(scale);
            ull pd  = dup2(p);
            #pragma unroll
            for (int i = 0; i < 4; i++) acc2[rr][i] = fma2(acc2[rr][i], sc2, 0ull);
            acc2[rr][0] = fma2(pd, V0.x, acc2[rr][0]);
            acc2[rr][1] = fma2(pd, V0.y, acc2[rr][1]);
            acc2[rr][2] = fma2(pd, V1.x, acc2[rr][2]);
            acc2[rr][3] = fma2(pd, V1.y, acc2[rr][3]);
            mrun[rr] = nm;
        }
    }

    // ---- store partials ----
    #pragma unroll
    for (int rr = 0; rr < 4; rr++) {
        float d = drun[rr];
        d += __shfl_xor_sync(0xffffffff, d, 1);
        d += __shfl_xor_sync(0xffffffff, d, 2);
        d += __shfl_xor_sync(0xffffffff, d, 4);
        if (vrow[rr]) {
            int l = lrow[rr];
            float* dst = g_pacc + (((size_t)s * Bb + b) * LL + l) * Cc + cbase;
            #pragma unroll
            for (int i = 0; i < 4; i++) {
                float2 f = unpk(acc2[rr][i]);
                dst[2*i]   = f.x;
                dst[2*i+1] = f.y;
            }
            if (og == 0) g_md[((size_t)s * Bb + b) * LL + l] = make_float2(mrun[rr], d);
        }
    }
}

// ---------------- Kernel 3b: combine m-splits -> g_ns ----------------
__global__ __launch_bounds__(256)
void k_combine()
{
    int idx = blockIdx.x * 256 + threadIdx.x;
    if (idx >= Bb * LL * Cc) return;
    int c   = idx & 63;
    int row = idx >> 6;
    int l   = row % LL;
    int b   = row / LL;
    float2 md0 = g_md[(size_t)b * LL + l];
    float2 md1 = g_md[((size_t)Bb + b) * LL + l];
    float M  = fmaxf(md0.x, md1.x);
    float w0 = __expf(md0.x - M);
    float w1 = __expf(md1.x - M);
    float a0 = g_pacc[((size_t)b * LL + l) * Cc + c];
    float a1 = g_pacc[(((size_t)Bb + b) * LL + l) * Cc + c];
    g_ns[((size_t)b * Cc + c) * LL + l] =
        (w0 * a0 + w1 * a1) / (w0 * md0.y + w1 * md1.y);
}

// ---------------- Kernel 4: fold + epilogue (unchanged) ----------------
__global__ __launch_bounds__(256)
void k_epilogue(const float* __restrict__ x, const float* __restrict__ mask,
                const float* __restrict__ fg_g, const float* __restrict__ fg_b,
                const float* __restrict__ bg_g, const float* __restrict__ bg_b,
                float* __restrict__ out)
{
    int tid = blockIdx.x * 256 + threadIdx.x;
    int idx = tid * 4;
    int w0 = idx & 255;
    int h  = (idx >> 8) & 255;
    int c  = (idx >> 16) & 63;
    int b  = idx >> 22;
    int q  = w0 >> 2;

    float4 mv = *(const float4*)(mask + (size_t)b * HW + h * Ww + w0);
    float4 xv = *(const float4*)(x + idx);

    float bgG = 1.0f + bg_g[c], bgB = bg_b[c];
    float fgG = 1.0f + fg_g[c], fgB = fg_b[c];

    int ih_hi = h >> 2;  int ih_lo = ih_hi - 1;
    bool vh_hi = (ih_hi <= NUMS - 1), vh_lo = (ih_lo >= 0);
    int iw_hi = q;       int iw_lo = q - 1;
    bool vw_hi = (iw_hi <= NUMS - 1), vw_lo = (iw_lo >= 0);

    float m[4]  = {mv.x, mv.y, mv.z, mv.w};
    float xs[4] = {xv.x, xv.y, xv.z, xv.w};
    float xm[4], inm[4];
    #pragma unroll
    for (int p = 0; p < 4; p++) { inm[p] = 1.0f - m[p]; xm[p] = xs[p] * m[p]; }

    float sum[4] = {0.f, 0.f, 0.f, 0.f};
    size_t base = ((size_t)b * Cc + c) * LL;

    int ihv[2] = {ih_lo, ih_hi};  bool vav[2] = {vh_lo, vh_hi};
    int iwv[2] = {iw_lo, iw_hi};  bool vev[2] = {vw_lo, vw_hi};
    #pragma unroll
    for (int a = 0; a < 2; a++) {
        #pragma unroll
        for (int e = 0; e < 2; e++) {
            if (vav[a] && vev[e]) {
                int lp = ihv[a] * NUMS + iwv[e];
                float2 mi = g_mif[base + lp];
                float ns  = g_ns [base + lp];
                #pragma unroll
                for (int p = 0; p < 4; p++) {
                    float inf_ = (xm[p] - mi.x) * mi.y * m[p] + mi.x * inm[p];
                    sum[p] += inf_ * ns + ns;
                }
            }
        }
    }
    int cnt = ((int)vh_hi + (int)vh_lo) * ((int)vw_hi + (int)vw_lo);
    float invc = (cnt == 4) ? 0.25f : ((cnt == 2) ? 0.5f : 1.0f);

    float r[4];
    #pragma unroll
    for (int p = 0; p < 4; p++) {
        float ubg = (xs[p] * inm[p] * bgG + bgB) * inm[p];
        float val = (sum[p] * invc) * fgG + fgB;
        r[p] = val * m[p] + ubg;
    }
    *(float4*)(out + idx) = make_float4(r[0], r[1], r[2], r[3]);
}

// ---------------- launch ----------------
extern "C" void kernel_launch(void* const* d_in, const int* in_sizes, int n_in,
                              void* d_out, int out_size)
{
    const float* x       = (const float*)d_in[0];
    const float* mask    = (const float*)d_in[1];
    const float* fg_g    = (const float*)d_in[2];
    const float* fg_b    = (const float*)d_in[3];
    const float* bg_g    = (const float*)d_in[4];
    const float* bg_b    = (const float*)d_in[5];
    const float* w_fore  = (const float*)d_in[6];
    const float* w_back  = (const float*)d_in[7];
    const float* rpb     = (const float*)d_in[8];
    float* out = (float*)d_out;

    k_stats<<<Bb * LL, 256>>>(x, mask);
    k_gemm<<<dim3(32, Bb, 4), 128>>>(x, mask, w_fore, w_back);
    k_attn<<<dim3(63, Bb, 2), 128>>>(rpb);
    k_combine<<<(Bb * LL * Cc + 255) / 256, 256>>>();
    k_epilogue<<<(Bb * Cc * HW) / (256 * 4), 256>>>(x, mask, fg_g, fg_b, bg_g, bg_b, out);
}

// round 9
// speedup vs baseline: 2.5193x; 1.0574x over previous
#include <cuda_runtime.h>
#include <cuda_bf16.h>

#define Bb 2
#define Cc 64
#define Hh 256
#define Ww 256
#define HW (Hh*Ww)
#define NUMS 63
#define LL (NUMS*NUMS)          // 3969
#define K2 64
#define EPSf 1e-5f
#define TBL_W (2*NUMS-1)        // 125
#define NCELL 64                // 64x64 grid of 4x4 cells

typedef unsigned long long ull;

__device__ __forceinline__ ull fma2(ull a, ull b, ull c){
    ull d; asm("fma.rn.f32x2 %0, %1, %2, %3;" : "=l"(d) : "l"(a), "l"(b), "l"(c)); return d;
}
__device__ __forceinline__ ull add2(ull a, ull b){
    ull d; asm("add.rn.f32x2 %0, %1, %2;" : "=l"(d) : "l"(a), "l"(b)); return d;
}
__device__ __forceinline__ ull dup2(float v){
    ull d; asm("mov.b64 %0, {%1, %1};" : "=l"(d) : "f"(v)); return d;
}
__device__ __forceinline__ float2 unpk(ull a){
    float2 r; asm("mov.b64 {%0, %1}, %2;" : "=f"(r.x), "=f"(r.y) : "l"(a)); return r;
}

// ---------------- device scratch ----------------
#define BCL (Bb*Cc*LL)
__device__ float2 g_mif [BCL];
__device__ float2 g_mib [BCL];
__device__ float  g_sbv [BCL];
__device__ float  g_tokf[BCL];
__device__ float  g_tokb[BCL];
__device__ float  g_tokf2[BCL];
__device__ float  g_tokb2[BCL];
__device__ float  g_ns  [BCL];
__device__ float2 g_md  [2*Bb*LL];
__device__ float  g_pacc[2*Bb*LL*Cc];
// cell moments
__device__ float4 g_cellA[Bb*Cc*NCELL*NCELL];   // (s1, s2, sm1, sm2)
__device__ float  g_cellM[Bb*NCELL*NCELL];      // mask sum per cell

// ---------------- Kernel 1a: per-cell raw moments ----------------
__global__ __launch_bounds__(256)
void k_cells(const float* __restrict__ x, const float* __restrict__ mask)
{
    int idx = blockIdx.x * 256 + threadIdx.x;     // b*C*4096 + c*4096 + ci*64 + cj
    int cj = idx & 63;
    int ci = (idx >> 6) & 63;
    int c  = (idx >> 12) & 63;
    int b  = idx >> 18;

    const float* xp = x    + (((size_t)b * Cc + c) * Hh + ci * 4) * Ww + cj * 4;
    const float* mp = mask + ((size_t)b * HW + ci * 4 * Ww) + cj * 4;

    float s1 = 0.f, s2 = 0.f, sm1 = 0.f, sm2 = 0.f, ms = 0.f;
    #pragma unroll
    for (int r = 0; r < 4; r++) {
        float4 xv = *(const float4*)(xp + r * Ww);
        float4 mv = *(const float4*)(mp + r * Ww);
        float vv[4] = {xv.x, xv.y, xv.z, xv.w};
        float mm[4] = {mv.x, mv.y, mv.z, mv.w};
        #pragma unroll
        for (int k = 0; k < 4; k++) {
            float v = vv[k], m = mm[k];
            s1 += v; s2 += v * v;
            sm1 += m * v; sm2 += m * v * v;
            ms += m;
        }
    }
    g_cellA[idx] = make_float4(s1, s2, sm1, sm2);
    if (c == 0) g_cellM[b * (NCELL*NCELL) + ci * NCELL + cj] = ms;
}

// ---------------- Kernel 1b: patch stats from 4 cells ----------------
__global__ __launch_bounds__(256)
void k_pstats()
{
    int idx = blockIdx.x * 256 + threadIdx.x;
    if (idx >= Bb * Cc * LL) return;
    int l  = idx % LL;
    int bc = idx / LL;
    int lh = l / NUMS, lw = l - lh * NUMS;
    int b  = bc >> 6;

    const float4* ca = g_cellA + (size_t)bc * (NCELL*NCELL);
    const float*  cm = g_cellM + (size_t)b * (NCELL*NCELL);
    int c00 = lh * NCELL + lw;

    float4 a0 = ca[c00],         a1 = ca[c00 + 1];
    float4 a2 = ca[c00 + NCELL], a3 = ca[c00 + NCELL + 1];
    float msum = cm[c00] + cm[c00 + 1] + cm[c00 + NCELL] + cm[c00 + NCELL + 1];

    float s1  = a0.x + a1.x + a2.x + a3.x;
    float s2  = a0.y + a1.y + a2.y + a3.y;
    float sm1 = a0.z + a1.z + a2.z + a3.z;
    float sm2 = a0.w + a1.w + a2.w + a3.w;

    float numf = msum;
    float numb = 64.0f - msum;
    float mf = sm1 / (numf + EPSf);
    float vf = (sm2 - 2.f * mf * sm1 + mf * mf * numf) / (numf + EPSf);
    float sb1 = s1 - sm1, sb2 = s2 - sm2;
    float mb = sb1 / (numb + EPSf);
    float vb = (sb2 - 2.f * mb * sb1 + mb * mb * numb) / (numb + EPSf);

    g_mif[idx] = make_float2(mf, 1.0f / vf);
    g_mib[idx] = make_float2(mb, 1.0f / vb);
    int c = bc & 63;
    g_sbv[((size_t)b * LL + l) * Cc + c] = vb;
}

// ---------------- Kernel 2: token GEMM, 8L x 8D (unchanged from R8) ----------------
__global__ __launch_bounds__(128)
void k_gemm(const float* __restrict__ x, const float* __restrict__ mask,
            const float* __restrict__ w_fore, const float* __restrict__ w_back)
{
    int tile  = blockIdx.x;
    int b     = blockIdx.y;
    int type  = blockIdx.z >> 1;
    int khalf = blockIdx.z & 1;
    const float*  w    = type ? w_back : w_fore;
    const float2* g_mi = type ? g_mib : g_mif;
    float* g_tk = type ? (khalf ? g_tokb2 : g_tokb)
                       : (khalf ? g_tokf2 : g_tokf);

    int l0 = tile * 128;
    int t  = threadIdx.x;

    __shared__ __align__(16) float ash[32][128];
    __shared__ __align__(16) float wsh[32][68];

    int la  = t;
    int lgl = l0 + la;
    bool lvalid = lgl < LL;
    int lg = lvalid ? lgl : (LL - 1);
    int lh = lg / NUMS, lw = lg - lh * NUMS;

    unsigned int mb0 = 0, mb1 = 0;
    {
        const float* mp = mask + (size_t)b * HW + (lh * 4) * Ww + lw * 4;
        #pragma unroll
        for (int r = 0; r < 8; r++) {
            float4 a = *(const float4*)(mp + r * Ww);
            float4 bq = *(const float4*)(mp + r * Ww + 4);
            float mv[8] = {a.x,a.y,a.z,a.w,bq.x,bq.y,bq.z,bq.w};
            unsigned int bits = 0;
            #pragma unroll
            for (int kw = 0; kw < 8; kw++) {
                bool on = mv[kw] > 0.5f;
                if (type) on = !on;
                bits |= (on ? 1u : 0u) << (((r & 3) * 8) + kw);
            }
            if (r < 4) mb0 |= bits; else mb1 |= bits;
        }
    }

    int wd = t & 63;
    int wi = t >> 6;

    int lgrp = t >> 3, dgrp = t & 7;
    int c0 = khalf * 32;

    ull acc[4][8];
    #pragma unroll
    for (int i = 0; i < 4; i++)
        #pragma unroll
        for (int j2 = 0; j2 < 8; j2++) acc[i][j2] = 0ull;

    float4 xa[4], xb[4], wr[4];
    float2 mi;

    auto LD = [&](int p) {
        int c = c0 + (p >> 1), sub = p & 1;
        const float* xp = x + (((size_t)b * Cc + c) * Hh + lh * 4 + sub * 4) * Ww + lw * 4;
        #pragma unroll
        for (int r = 0; r < 4; r++) {
            xa[r] = *(const float4*)(xp + r * Ww);
            xb[r] = *(const float4*)(xp + r * Ww + 4);
        }
        mi = g_mi[((size_t)b * Cc + c) * LL + lg];
        const float* wp = w + (size_t)wd * (Cc * K2) + c * K2 + sub * 32 + wi * 16;
        #pragma unroll
        for (int r = 0; r < 4; r++) wr[r] = *(const float4*)(wp + 4 * r);
    };
    LD(0);

    for (int p = 0; p < 64; p++) {
        __syncthreads();
        {
            int sub = p & 1;
            unsigned int wsel = sub ? mb1 : mb0;
            float muv = lvalid ? mi.x : 0.f;
            float isv = lvalid ? mi.y : 0.f;
            #pragma unroll
            for (int r = 0; r < 4; r++) {
                float xv[8] = {xa[r].x,xa[r].y,xa[r].z,xa[r].w,
                               xb[r].x,xb[r].y,xb[r].z,xb[r].w};
                #pragma unroll
                for (int kw = 0; kw < 8; kw++) {
                    bool on = (wsel >> (r * 8 + kw)) & 1u;
                    ash[r * 8 + kw][la] = on ? (xv[kw] - muv) * isv : muv;
                }
            }
        }
        {
            float wv[16] = {wr[0].x,wr[0].y,wr[0].z,wr[0].w,
                            wr[1].x,wr[1].y,wr[1].z,wr[1].w,
                            wr[2].x,wr[2].y,wr[2].z,wr[2].w,
                            wr[3].x,wr[3].y,wr[3].z,wr[3].w};
            #pragma unroll
            for (int q = 0; q < 16; q++)
                wsh[wi * 16 + q][wd] = wv[q];
        }
        __syncthreads();
        if (p < 63) LD(p + 1);

        #pragma unroll 4
        for (int k = 0; k < 32; k++) {
            ulonglong2 A0 = *(const ulonglong2*)&ash[k][8 * lgrp];
            ulonglong2 A1 = *(const ulonglong2*)&ash[k][8 * lgrp + 4];
            float4 w0 = *(const float4*)&wsh[k][8 * dgrp];
            float4 w1 = *(const float4*)&wsh[k][8 * dgrp + 4];
            ull a2[4] = {A0.x, A0.y, A1.x, A1.y};
            ull wv[8] = {dup2(w0.x), dup2(w0.y), dup2(w0.z), dup2(w0.w),
                         dup2(w1.x), dup2(w1.y), dup2(w1.z), dup2(w1.w)};
            #pragma unroll
            for (int li = 0; li < 4; li++) {
                #pragma unroll
                for (int dj = 0; dj < 8; dj++)
                    acc[li][dj] = fma2(a2[li], wv[dj], acc[li][dj]);
            }
        }
    }

    #pragma unroll
    for (int li = 0; li < 4; li++) {
        float lo[8], hi[8];
        #pragma unroll
        for (int dj = 0; dj < 8; dj++) {
            float2 f = unpk(acc[li][dj]);
            lo[dj] = f.x; hi[dj] = f.y;
        }
        int le = l0 + 8 * lgrp + 2 * li;
        if (le < LL) {
            float* dst = g_tk + ((size_t)b * LL + le) * Cc + 8 * dgrp;
            *(float4*)dst       = make_float4(lo[0], lo[1], lo[2], lo[3]);
            *(float4*)(dst + 4) = make_float4(lo[4], lo[5], lo[6], lo[7]);
        }
        if (le + 1 < LL) {
            float* dst = g_tk + ((size_t)b * LL + le + 1) * Cc + 8 * dgrp;
            *(float4*)dst       = make_float4(hi[0], hi[1], hi[2], hi[3]);
            *(float4*)(dst + 4) = make_float4(hi[4], hi[5], hi[6], hi[7]);
        }
    }
}

// ---------------- Kernel 2b: merge K-split tok partials ----------------
__global__ __launch_bounds__(256)
void k_merge()
{
    int i = blockIdx.x * 256 + threadIdx.x;
    if (i >= BCL / 4) return;
    float4* f  = (float4*)g_tokf;
    float4* f2 = (float4*)g_tokf2;
    float4* bq = (float4*)g_tokb;
    float4* b2 = (float4*)g_tokb2;
    float4 a = f[i], c = f2[i];
    f[i] = make_float4(a.x + c.x, a.y + c.y, a.z + c.z, a.w + c.w);
    float4 d = bq[i], e = b2[i];
    bq[i] = make_float4(d.x + e.x, d.y + e.y, d.z + e.z, d.w + e.w);
}

// ---------------- Kernel 3: attention, 4 rows/thread, m-split 2 ----------------
__global__ __launch_bounds__(128)
void k_attn(const float* __restrict__ rpb)
{
    int b  = blockIdx.y;
    int s  = blockIdx.z;
    int l0 = blockIdx.x * 64;
    int t  = threadIdx.x;
    int rloc = t >> 3;
    int og   = t & 7;
    int cbase = og * 8;

    int lrow[4]; bool vrow[4]; int rc[4];
    #pragma unroll
    for (int rr = 0; rr < 4; rr++) {
        int l = l0 + rloc + rr * 16;
        vrow[rr] = (l < LL);
        int lr = vrow[rr] ? l : (LL - 1);
        lrow[rr] = lr;
        int lh = lr / NUMS, lw = lr - lh * NUMS;
        rc[rr] = (lh + 62) * TBL_W + (lw + 62);
    }

    __shared__ __align__(16) float kb [64][64];
    __shared__ __align__(16) float vvs[64][64];
    __shared__ int rpish[64];

    ull q2[4][4];
    #pragma unroll
    for (int rr = 0; rr < 4; rr++) {
        float2* qf = (float2*)q2[rr];
        const float4* qa = (const float4*)(g_tokf + ((size_t)b * LL + lrow[rr]) * Cc + cbase);
        float4 a0 = qa[0], a1 = qa[1];
        qf[0] = make_float2(a0.x, a0.y);
        qf[1] = make_float2(a0.z, a0.w);
        qf[2] = make_float2(a1.x, a1.y);
        qf[3] = make_float2(a1.z, a1.w);
    }
    ull acc2[4][4];
    #pragma unroll
    for (int rr = 0; rr < 4; rr++)
        #pragma unroll
        for (int i = 0; i < 4; i++) acc2[rr][i] = 0ull;
    float mrun[4] = {-1e30f,-1e30f,-1e30f,-1e30f};
    float drun[4] = {0.f,0.f,0.f,0.f};

    for (int tt = 0; tt < 31; tt++) {
        int m0 = (s * 31 + tt) * 64;
        __syncthreads();
        #pragma unroll
        for (int it = 0; it < 8; it++) {
            int i = t + it * 128;
            int row = i >> 4, col = i & 15;
            int m = m0 + row;
            ((float4*)kb)[i]  = ((const float4*)(g_tokb + ((size_t)b*LL + m)*Cc))[col];
            ((float4*)vvs)[i] = ((const float4*)(g_sbv  + ((size_t)b*LL + m)*Cc))[col];
        }
        if (t < 64) {
            int m = m0 + t;
            int mh = m / NUMS;
            rpish[t] = mh * TBL_W + (m - mh * NUMS);
        }
        __syncthreads();

        float lreg[4][8];
        float tmax[4] = {-1e30f,-1e30f,-1e30f,-1e30f};
        #pragma unroll
        for (int jg = 0; jg < 8; jg++) {
            float p[4][8];
            #pragma unroll
            for (int jq = 0; jq < 8; jq++) {
                int jidx = jg * 8 + jq;
                const ulonglong2* kp = (const ulonglong2*)&kb[jidx][cbase];
                ulonglong2 K0 = kp[0], K1 = kp[1];
                #pragma unroll
                for (int rr = 0; rr < 4; rr++) {
                    ull pa = fma2(q2[rr][0], K0.x, 0ull);
                    ull pb = fma2(q2[rr][1], K0.y, 0ull);
                    pa = fma2(q2[rr][2], K1.x, pa);
                    pb = fma2(q2[rr][3], K1.y, pb);
                    float2 h = unpk(add2(pa, pb));
                    p[rr][jq] = h.x + h.y;
                }
            }
            int bofs = rpish[jg * 8 + og];
            #pragma unroll
            for (int rr = 0; rr < 4; rr++) {
                float ve[4];
                #pragma unroll
                for (int k = 0; k < 4; k++) {
                    float mine = (og & 1) ? p[rr][2*k+1] : p[rr][2*k];
                    float oth  = (og & 1) ? p[rr][2*k]   : p[rr][2*k+1];
                    ve[k] = mine + __shfl_xor_sync(0xffffffff, oth, 1);
                }
                float we[2];
                #pragma unroll
                for (int k = 0; k < 2; k++) {
                    float mine = (og & 2) ? ve[2*k+1] : ve[2*k];
                    float oth  = (og & 2) ? ve[2*k]   : ve[2*k+1];
                    we[k] = mine + __shfl_xor_sync(0xffffffff, oth, 2);
                }
                float mine = (og & 4) ? we[1] : we[0];
                float oth  = (og & 4) ? we[0] : we[1];
                float tot = mine + __shfl_xor_sync(0xffffffff, oth, 4);
                tot += __ldg(rpb + rc[rr] - bofs);
                lreg[rr][jg] = tot;
                tmax[rr] = fmaxf(tmax[rr], tot);
            }
        }
        #pragma unroll
        for (int rr = 0; rr < 4; rr++) {
            tmax[rr] = fmaxf(tmax[rr], __shfl_xor_sync(0xffffffff, tmax[rr], 1));
            tmax[rr] = fmaxf(tmax[rr], __shfl_xor_sync(0xffffffff, tmax[rr], 2));
            tmax[rr] = fmaxf(tmax[rr], __shfl_xor_sync(0xffffffff, tmax[rr], 4));
        }

        float nm[4];
        #pragma unroll
        for (int rr = 0; rr < 4; rr++) {
            nm[rr] = fmaxf(mrun[rr], tmax[rr]);
            float scale = __expf(mrun[rr] - nm[rr]);
            drun[rr] *= scale;
            ull sc2 = dup2(scale);
            #pragma unroll
            for (int i = 0; i < 4; i++) acc2[rr][i] = fma2(acc2[rr][i], sc2, 0ull);
            mrun[rr] = nm[rr];
        }
        #pragma unroll
        for (int jg = 0; jg < 8; jg++) {
            float pj[4];
            #pragma unroll
            for (int rr = 0; rr < 4; rr++) {
                pj[rr] = __expf(lreg[rr][jg] - nm[rr]);
                drun[rr] += pj[rr];
            }
            #pragma unroll
            for (int jq = 0; jq < 8; jq++) {
                int jidx = jg * 8 + jq;
                const ulonglong2* vp = (const ulonglong2*)&vvs[jidx][cbase];
                ulonglong2 V0 = vp[0], V1 = vp[1];
                #pragma unroll
                for (int rr = 0; rr < 4; rr++) {
                    float pb = __shfl_sync(0xffffffff, pj[rr], jq, 8);
                    ull pd = dup2(pb);
                    acc2[rr][0] = fma2(pd, V0.x, acc2[rr][0]);
                    acc2[rr][1] = fma2(pd, V0.y, acc2[rr][1]);
                    acc2[rr][2] = fma2(pd, V1.x, acc2[rr][2]);
                    acc2[rr][3] = fma2(pd, V1.y, acc2[rr][3]);
                }
            }
        }
    }

    // ---- tail m = 3968, split 1 only ----
    if (s == 1) {
        const int mt = LL - 1;
        const float4* ka = (const float4*)(g_tokb + ((size_t)b*LL + mt)*Cc + cbase);
        float4 k0 = ka[0], k1 = ka[1];
        const ulonglong2* vp = (const ulonglong2*)(g_sbv + ((size_t)b*LL + mt)*Cc + cbase);
        ulonglong2 V0 = vp[0], V1 = vp[1];
        #pragma unroll
        for (int rr = 0; rr < 4; rr++) {
            float2 qf[4];
            #pragma unroll
            for (int i = 0; i < 4; i++) qf[i] = unpk(q2[rr][i]);
            float sv = qf[0].x*k0.x + qf[0].y*k0.y
                     + qf[1].x*k0.z + qf[1].y*k0.w
                     + qf[2].x*k1.x + qf[2].y*k1.y
                     + qf[3].x*k1.z + qf[3].y*k1.w;
            sv += __shfl_xor_sync(0xffffffff, sv, 1);
            sv += __shfl_xor_sync(0xffffffff, sv, 2);
            sv += __shfl_xor_sync(0xffffffff, sv, 4);
            sv += __ldg(rpb + rc[rr] - 7812);
            float nm = fmaxf(mrun[rr], sv);
            float scale = __expf(mrun[rr] - nm);
            float p = __expf(sv - nm);
            drun[rr] *= scale;
            if (og == 0) drun[rr] += p;
            ull sc2 = dup2(scale);
            ull pd  = dup2(p);
            #pragma unroll
            for (int i = 0; i < 4; i++) acc2[rr][i] = fma2(acc2[rr][i], sc2, 0ull);
            acc2[rr][0] = fma2(pd, V0.x, acc2[rr][0]);
            acc2[rr][1] = fma2(pd, V0.y, acc2[rr][1]);
            acc2[rr][2] = fma2(pd, V1.x, acc2[rr][2]);
            acc2[rr][3] = fma2(pd, V1.y, acc2[rr][3]);
            mrun[rr] = nm;
        }
    }

    #pragma unroll
    for (int rr = 0; rr < 4; rr++) {
        float d = drun[rr];
        d += __shfl_xor_sync(0xffffffff, d, 1);
        d += __shfl_xor_sync(0xffffffff, d, 2);
        d += __shfl_xor_sync(0xffffffff, d, 4);
        if (vrow[rr]) {
            int l = lrow[rr];
            float* dst = g_pacc + (((size_t)s * Bb + b) * LL + l) * Cc + cbase;
            #pragma unroll
            for (int i = 0; i < 4; i++) {
                float2 f = unpk(acc2[rr][i]);
                dst[2*i]   = f.x;
                dst[2*i+1] = f.y;
            }
            if (og == 0) g_md[((size_t)s * Bb + b) * LL + l] = make_float2(mrun[rr], d);
        }
    }
}

// ---------------- Kernel 3b: combine m-splits -> g_ns ----------------
__global__ __launch_bounds__(256)
void k_combine()
{
    int idx = blockIdx.x * 256 + threadIdx.x;
    if (idx >= Bb * LL * Cc) return;
    int c   = idx & 63;
    int row = idx >> 6;
    int l   = row % LL;
    int b   = row / LL;
    float2 md0 = g_md[(size_t)b * LL + l];
    float2 md1 = g_md[((size_t)Bb + b) * LL + l];
    float M  = fmaxf(md0.x, md1.x);
    float w0 = __expf(md0.x - M);
    float w1 = __expf(md1.x - M);
    float a0 = g_pacc[((size_t)b * LL + l) * Cc + c];
    float a1 = g_pacc[(((size_t)Bb + b) * LL + l) * Cc + c];
    g_ns[((size_t)b * Cc + c) * LL + l] =
        (w0 * a0 + w1 * a1) / (w0 * md0.y + w1 * md1.y);
}

// ---------------- Kernel 4: fold + epilogue (unchanged) ----------------
__global__ __launch_bounds__(256)
void k_epilogue(const float* __restrict__ x, const float* __restrict__ mask,
                const float* __restrict__ fg_g, const float* __restrict__ fg_b,
                const float* __restrict__ bg_g, const float* __restrict__ bg_b,
                float* __restrict__ out)
{
    int tid = blockIdx.x * 256 + threadIdx.x;
    int idx = tid * 4;
    int w0 = idx & 255;
    int h  = (idx >> 8) & 255;
    int c  = (idx >> 16) & 63;
    int b  = idx >> 22;
    int q  = w0 >> 2;

    float4 mv = *(const float4*)(mask + (size_t)b * HW + h * Ww + w0);
    float4 xv = *(const float4*)(x + idx);

    float bgG = 1.0f + bg_g[c], bgB = bg_b[c];
    float fgG = 1.0f + fg_g[c], fgB = fg_b[c];

    int ih_hi = h >> 2;  int ih_lo = ih_hi - 1;
    bool vh_hi = (ih_hi <= NUMS - 1), vh_lo = (ih_lo >= 0);
    int iw_hi = q;       int iw_lo = q - 1;
    bool vw_hi = (iw_hi <= NUMS - 1), vw_lo = (iw_lo >= 0);

    float m[4]  = {mv.x, mv.y, mv.z, mv.w};
    float xs[4] = {xv.x, xv.y, xv.z, xv.w};
    float xm[4], inm[4];
    #pragma unroll
    for (int p = 0; p < 4; p++) { inm[p] = 1.0f - m[p]; xm[p] = xs[p] * m[p]; }

    float sum[4] = {0.f, 0.f, 0.f, 0.f};
    size_t base = ((size_t)b * Cc + c) * LL;

    int ihv[2] = {ih_lo, ih_hi};  bool vav[2] = {vh_lo, vh_hi};
    int iwv[2] = {iw_lo, iw_hi};  bool vev[2] = {vw_lo, vw_hi};
    #pragma unroll
    for (int a = 0; a < 2; a++) {
        #pragma unroll
        for (int e = 0; e < 2; e++) {
            if (vav[a] && vev[e]) {
                int lp = ihv[a] * NUMS + iwv[e];
                float2 mi = g_mif[base + lp];
                float ns  = g_ns [base + lp];
                #pragma unroll
                for (int p = 0; p < 4; p++) {
                    float inf_ = (xm[p] - mi.x) * mi.y * m[p] + mi.x * inm[p];
                    sum[p] += inf_ * ns + ns;
                }
            }
        }
    }
    int cnt = ((int)vh_hi + (int)vh_lo) * ((int)vw_hi + (int)vw_lo);
    float invc = (cnt == 4) ? 0.25f : ((cnt == 2) ? 0.5f : 1.0f);

    float r[4];
    #pragma unroll
    for (int p = 0; p < 4; p++) {
        float ubg = (xs[p] * inm[p] * bgG + bgB) * inm[p];
        float val = (sum[p] * invc) * fgG + fgB;
        r[p] = val * m[p] + ubg;
    }
    *(float4*)(out + idx) = make_float4(r[0], r[1], r[2], r[3]);
}

// ---------------- launch ----------------
extern "C" void kernel_launch(void* const* d_in, const int* in_sizes, int n_in,
                              void* d_out, int out_size)
{
    const float* x       = (const float*)d_in[0];
    const float* mask    = (const float*)d_in[1];
    const float* fg_g    = (const float*)d_in[2];
    const float* fg_b    = (const float*)d_in[3];
    const float* bg_g    = (const float*)d_in[4];
    const float* bg_b    = (const float*)d_in[5];
    const float* w_fore  = (const float*)d_in[6];
    const float* w_back  = (const float*)d_in[7];
    const float* rpb     = (const float*)d_in[8];
    float* out = (float*)d_out;

    k_cells<<<(Bb * Cc * NCELL * NCELL) / 256, 256>>>(x, mask);
    k_pstats<<<(Bb * Cc * LL + 255) / 256, 256>>>();
    k_gemm<<<dim3(32, Bb, 4), 128>>>(x, mask, w_fore, w_back);
    k_merge<<<(BCL / 4 + 255) / 256, 256>>>();
    k_attn<<<dim3(63, Bb, 2), 128>>>(rpb);
    k_combine<<<(Bb * LL * Cc + 255) / 256, 256>>>();
    k_epilogue<<<(Bb * Cc * HW) / (256 * 4), 256>>>(x, mask, fg_g, fg_b, bg_g, bg_b, out);
}

// round 10
// speedup vs baseline: 2.5256x; 1.0025x over previous
#include <cuda_runtime.h>
#include <cuda_bf16.h>

#define Bb 2
#define Cc 64
#define Hh 256
#define Ww 256
#define HW (Hh*Ww)
#define NUMS 63
#define LL (NUMS*NUMS)          // 3969
#define K2 64
#define EPSf 1e-5f
#define TBL_W (2*NUMS-1)        // 125
#define NCELL 64

typedef unsigned long long ull;

__device__ __forceinline__ ull fma2(ull a, ull b, ull c){
    ull d; asm("fma.rn.f32x2 %0, %1, %2, %3;" : "=l"(d) : "l"(a), "l"(b), "l"(c)); return d;
}
__device__ __forceinline__ ull add2(ull a, ull b){
    ull d; asm("add.rn.f32x2 %0, %1, %2;" : "=l"(d) : "l"(a), "l"(b)); return d;
}
__device__ __forceinline__ ull dup2(float v){
    ull d; asm("mov.b64 %0, {%1, %1};" : "=l"(d) : "f"(v)); return d;
}
__device__ __forceinline__ float2 unpk(ull a){
    float2 r; asm("mov.b64 {%0, %1}, %2;" : "=f"(r.x), "=f"(r.y) : "l"(a)); return r;
}

// ---------------- device scratch ----------------
#define BCL (Bb*Cc*LL)
__device__ float2 g_mif [BCL];
__device__ float2 g_mib [BCL];
__device__ float  g_sbv [BCL];
__device__ float  g_tokf[BCL];
__device__ float  g_tokb[BCL];
__device__ float  g_tokf2[BCL];
__device__ float  g_tokb2[BCL];
__device__ float  g_ns  [BCL];
__device__ float2 g_md  [2*Bb*LL];
__device__ float  g_pacc[2*Bb*LL*Cc];
__device__ float4 g_cellA[Bb*Cc*NCELL*NCELL];
__device__ float  g_cellM[Bb*NCELL*NCELL];

// ---------------- Kernel 1a: per-cell raw moments ----------------
__global__ __launch_bounds__(256)
void k_cells(const float* __restrict__ x, const float* __restrict__ mask)
{
    int idx = blockIdx.x * 256 + threadIdx.x;
    int cj = idx & 63;
    int ci = (idx >> 6) & 63;
    int c  = (idx >> 12) & 63;
    int b  = idx >> 18;

    const float* xp = x    + (((size_t)b * Cc + c) * Hh + ci * 4) * Ww + cj * 4;
    const float* mp = mask + ((size_t)b * HW + ci * 4 * Ww) + cj * 4;

    float s1 = 0.f, s2 = 0.f, sm1 = 0.f, sm2 = 0.f, ms = 0.f;
    #pragma unroll
    for (int r = 0; r < 4; r++) {
        float4 xv = *(const float4*)(xp + r * Ww);
        float4 mv = *(const float4*)(mp + r * Ww);
        float vv[4] = {xv.x, xv.y, xv.z, xv.w};
        float mm[4] = {mv.x, mv.y, mv.z, mv.w};
        #pragma unroll
        for (int k = 0; k < 4; k++) {
            float v = vv[k], m = mm[k];
            s1 += v; s2 += v * v;
            sm1 += m * v; sm2 += m * v * v;
            ms += m;
        }
    }
    g_cellA[idx] = make_float4(s1, s2, sm1, sm2);
    if (c == 0) g_cellM[b * (NCELL*NCELL) + ci * NCELL + cj] = ms;
}

// ---------------- Kernel 1b: patch stats from 4 cells ----------------
__global__ __launch_bounds__(256)
void k_pstats()
{
    int idx = blockIdx.x * 256 + threadIdx.x;
    if (idx >= Bb * Cc * LL) return;
    int l  = idx % LL;
    int bc = idx / LL;
    int lh = l / NUMS, lw = l - lh * NUMS;
    int b  = bc >> 6;

    const float4* ca = g_cellA + (size_t)bc * (NCELL*NCELL);
    const float*  cm = g_cellM + (size_t)b * (NCELL*NCELL);
    int c00 = lh * NCELL + lw;

    float4 a0 = ca[c00],         a1 = ca[c00 + 1];
    float4 a2 = ca[c00 + NCELL], a3 = ca[c00 + NCELL + 1];
    float msum = cm[c00] + cm[c00 + 1] + cm[c00 + NCELL] + cm[c00 + NCELL + 1];

    float s1  = a0.x + a1.x + a2.x + a3.x;
    float s2  = a0.y + a1.y + a2.y + a3.y;
    float sm1 = a0.z + a1.z + a2.z + a3.z;
    float sm2 = a0.w + a1.w + a2.w + a3.w;

    float numf = msum;
    float numb = 64.0f - msum;
    float mf = sm1 / (numf + EPSf);
    float vf = (sm2 - 2.f * mf * sm1 + mf * mf * numf) / (numf + EPSf);
    float sb1 = s1 - sm1, sb2 = s2 - sm2;
    float mb = sb1 / (numb + EPSf);
    float vb = (sb2 - 2.f * mb * sb1 + mb * mb * numb) / (numb + EPSf);

    g_mif[idx] = make_float2(mf, 1.0f / vf);
    g_mib[idx] = make_float2(mb, 1.0f / vb);
    int c = bc & 63;
    g_sbv[((size_t)b * LL + l) * Cc + c] = vb;
}

// ---------------- Kernel 2: token GEMM, double-buffered, 1 sync/phase ----------------
__global__ __launch_bounds__(128)
void k_gemm(const float* __restrict__ x, const float* __restrict__ mask,
            const float* __restrict__ w_fore, const float* __restrict__ w_back)
{
    int tile  = blockIdx.x;
    int b     = blockIdx.y;
    int type  = blockIdx.z >> 1;
    int khalf = blockIdx.z & 1;
    const float*  w    = type ? w_back : w_fore;
    const float2* g_mi = type ? g_mib : g_mif;
    float* g_tk = type ? (khalf ? g_tokb2 : g_tokb)
                       : (khalf ? g_tokf2 : g_tokf);

    int l0 = tile * 128;
    int t  = threadIdx.x;

    __shared__ __align__(16) float ash[2][32][128];
    __shared__ __align__(16) float wsh[2][32][68];

    int la  = t;
    int lgl = l0 + la;
    bool lvalid = lgl < LL;
    int lg = lvalid ? lgl : (LL - 1);
    int lh = lg / NUMS, lw = lg - lh * NUMS;

    unsigned int mb0 = 0, mb1 = 0;
    {
        const float* mp = mask + (size_t)b * HW + (lh * 4) * Ww + lw * 4;
        #pragma unroll
        for (int r = 0; r < 8; r++) {
            float4 a = *(const float4*)(mp + r * Ww);
            float4 bq = *(const float4*)(mp + r * Ww + 4);
            float mv[8] = {a.x,a.y,a.z,a.w,bq.x,bq.y,bq.z,bq.w};
            unsigned int bits = 0;
            #pragma unroll
            for (int kw = 0; kw < 8; kw++) {
                bool on = mv[kw] > 0.5f;
                if (type) on = !on;
                bits |= (on ? 1u : 0u) << (((r & 3) * 8) + kw);
            }
            if (r < 4) mb0 |= bits; else mb1 |= bits;
        }
    }

    int wd = t & 63;
    int wi = t >> 6;

    int lgrp = t >> 3, dgrp = t & 7;
    int c0 = khalf * 32;

    ull acc[4][8];
    #pragma unroll
    for (int i = 0; i < 4; i++)
        #pragma unroll
        for (int j2 = 0; j2 < 8; j2++) acc[i][j2] = 0ull;

    float4 xa[4], xb[4], wr[4];
    float2 mi;

    auto LD = [&](int p) {
        int c = c0 + (p >> 1), sub = p & 1;
        const float* xp = x + (((size_t)b * Cc + c) * Hh + lh * 4 + sub * 4) * Ww + lw * 4;
        #pragma unroll
        for (int r = 0; r < 4; r++) {
            xa[r] = *(const float4*)(xp + r * Ww);
            xb[r] = *(const float4*)(xp + r * Ww + 4);
        }
        mi = g_mi[((size_t)b * Cc + c) * LL + lg];
        const float* wp = w + (size_t)wd * (Cc * K2) + c * K2 + sub * 32 + wi * 16;
        #pragma unroll
        for (int r = 0; r < 4; r++) wr[r] = *(const float4*)(wp + 4 * r);
    };

    auto STAGE = [&](int p, int buf) {
        int sub = p & 1;
        unsigned int wsel = sub ? mb1 : mb0;
        float muv = lvalid ? mi.x : 0.f;
        float isv = lvalid ? mi.y : 0.f;
        #pragma unroll
        for (int r = 0; r < 4; r++) {
            float xv[8] = {xa[r].x,xa[r].y,xa[r].z,xa[r].w,
                           xb[r].x,xb[r].y,xb[r].z,xb[r].w};
            #pragma unroll
            for (int kw = 0; kw < 8; kw++) {
                bool on = (wsel >> (r * 8 + kw)) & 1u;
                ash[buf][r * 8 + kw][la] = on ? (xv[kw] - muv) * isv : muv;
            }
        }
        float wv[16] = {wr[0].x,wr[0].y,wr[0].z,wr[0].w,
                        wr[1].x,wr[1].y,wr[1].z,wr[1].w,
                        wr[2].x,wr[2].y,wr[2].z,wr[2].w,
                        wr[3].x,wr[3].y,wr[3].z,wr[3].w};
        #pragma unroll
        for (int q = 0; q < 16; q++)
            wsh[buf][wi * 16 + q][wd] = wv[q];
    };

    LD(0);
    STAGE(0, 0);
    __syncthreads();

    for (int p = 0; p < 64; p++) {
        int cur = p & 1;
        if (p < 63) LD(p + 1);       // gmem prefetch; latency hidden by compute

        #pragma unroll 4
        for (int k = 0; k < 32; k++) {
            ulonglong2 A0 = *(const ulonglong2*)&ash[cur][k][8 * lgrp];
            ulonglong2 A1 = *(const ulonglong2*)&ash[cur][k][8 * lgrp + 4];
            float4 w0 = *(const float4*)&wsh[cur][k][8 * dgrp];
            float4 w1 = *(const float4*)&wsh[cur][k][8 * dgrp + 4];
            ull a2[4] = {A0.x, A0.y, A1.x, A1.y};
            ull wv[8] = {dup2(w0.x), dup2(w0.y), dup2(w0.z), dup2(w0.w),
                         dup2(w1.x), dup2(w1.y), dup2(w1.z), dup2(w1.w)};
            #pragma unroll
            for (int li = 0; li < 4; li++) {
                #pragma unroll
                for (int dj = 0; dj < 8; dj++)
                    acc[li][dj] = fma2(a2[li], wv[dj], acc[li][dj]);
            }
        }

        if (p < 63) {
            STAGE(p + 1, cur ^ 1);   // write the other buffer; no one reads it yet
            __syncthreads();         // single barrier per phase
        }
    }

    #pragma unroll
    for (int li = 0; li < 4; li++) {
        float lo[8], hi[8];
        #pragma unroll
        for (int dj = 0; dj < 8; dj++) {
            float2 f = unpk(acc[li][dj]);
            lo[dj] = f.x; hi[dj] = f.y;
        }
        int le = l0 + 8 * lgrp + 2 * li;
        if (le < LL) {
            float* dst = g_tk + ((size_t)b * LL + le) * Cc + 8 * dgrp;
            *(float4*)dst       = make_float4(lo[0], lo[1], lo[2], lo[3]);
            *(float4*)(dst + 4) = make_float4(lo[4], lo[5], lo[6], lo[7]);
        }
        if (le + 1 < LL) {
            float* dst = g_tk + ((size_t)b * LL + le + 1) * Cc + 8 * dgrp;
            *(float4*)dst       = make_float4(hi[0], hi[1], hi[2], hi[3]);
            *(float4*)(dst + 4) = make_float4(hi[4], hi[5], hi[6], hi[7]);
        }
    }
}

// ---------------- Kernel 2b: merge K-split tok partials ----------------
__global__ __launch_bounds__(256)
void k_merge()
{
    int i = blockIdx.x * 256 + threadIdx.x;
    if (i >= BCL / 4) return;
    float4* f  = (float4*)g_tokf;
    float4* f2 = (float4*)g_tokf2;
    float4* bq = (float4*)g_tokb;
    float4* b2 = (float4*)g_tokb2;
    float4 a = f[i], c = f2[i];
    f[i] = make_float4(a.x + c.x, a.y + c.y, a.z + c.z, a.w + c.w);
    float4 d = bq[i], e = b2[i];
    bq[i] = make_float4(d.x + e.x, d.y + e.y, d.z + e.z, d.w + e.w);
}

// ---------------- Kernel 3: attention, 4 rows/thread, K/V register prefetch ----------------
__global__ __launch_bounds__(128)
void k_attn(const float* __restrict__ rpb)
{
    int b  = blockIdx.y;
    int s  = blockIdx.z;
    int l0 = blockIdx.x * 64;
    int t  = threadIdx.x;
    int rloc = t >> 3;
    int og   = t & 7;
    int cbase = og * 8;

    int lrow[4]; bool vrow[4]; int rc[4];
    #pragma unroll
    for (int rr = 0; rr < 4; rr++) {
        int l = l0 + rloc + rr * 16;
        vrow[rr] = (l < LL);
        int lr = vrow[rr] ? l : (LL - 1);
        lrow[rr] = lr;
        int lh = lr / NUMS, lw = lr - lh * NUMS;
        rc[rr] = (lh + 62) * TBL_W + (lw + 62);
    }

    __shared__ __align__(16) float kb [64][64];
    __shared__ __align__(16) float vvs[64][64];
    __shared__ int rpish[64];

    ull q2[4][4];
    #pragma unroll
    for (int rr = 0; rr < 4; rr++) {
        float2* qf = (float2*)q2[rr];
        const float4* qa = (const float4*)(g_tokf + ((size_t)b * LL + lrow[rr]) * Cc + cbase);
        float4 a0 = qa[0], a1 = qa[1];
        qf[0] = make_float2(a0.x, a0.y);
        qf[1] = make_float2(a0.z, a0.w);
        qf[2] = make_float2(a1.x, a1.y);
        qf[3] = make_float2(a1.z, a1.w);
    }
    ull acc2[4][4];
    #pragma unroll
    for (int rr = 0; rr < 4; rr++)
        #pragma unroll
        for (int i = 0; i < 4; i++) acc2[rr][i] = 0ull;
    float mrun[4] = {-1e30f,-1e30f,-1e30f,-1e30f};
    float drun[4] = {0.f,0.f,0.f,0.f};

    // register prefetch buffers for K/V tiles
    float4 kr[8], vr[8];
    int prow = t >> 4, pcol = t & 15;   // row/col this thread stages (8 rows apart)

    auto FETCH = [&](int tt) {
        int m0 = (s * 31 + tt) * 64;
        #pragma unroll
        for (int it = 0; it < 8; it++) {
            int m = m0 + prow + it * 8;
            kr[it] = ((const float4*)(g_tokb + ((size_t)b*LL + m)*Cc))[pcol];
            vr[it] = ((const float4*)(g_sbv  + ((size_t)b*LL + m)*Cc))[pcol];
        }
    };

    FETCH(0);
    for (int tt = 0; tt < 31; tt++) {
        __syncthreads();   // previous tile's compute fully done
        #pragma unroll
        for (int it = 0; it < 8; it++) {
            int row = prow + it * 8;
            *(float4*)&kb [row][pcol * 4] = kr[it];
            *(float4*)&vvs[row][pcol * 4] = vr[it];
        }
        if (t < 64) {
            int m = (s * 31 + tt) * 64 + t;
            int mh = m / NUMS;
            rpish[t] = mh * TBL_W + (m - mh * NUMS);
        }
        __syncthreads();
        if (tt < 30) FETCH(tt + 1);   // LDG latency hidden under compute below

        float lreg[4][8];
        float tmax[4] = {-1e30f,-1e30f,-1e30f,-1e30f};
        #pragma unroll
        for (int jg = 0; jg < 8; jg++) {
            float p[4][8];
            #pragma unroll
            for (int jq = 0; jq < 8; jq++) {
                int jidx = jg * 8 + jq;
                const ulonglong2* kp = (const ulonglong2*)&kb[jidx][cbase];
                ulonglong2 K0 = kp[0], K1 = kp[1];
                #pragma unroll
                for (int rr = 0; rr < 4; rr++) {
                    ull pa = fma2(q2[rr][0], K0.x, 0ull);
                    ull pb = fma2(q2[rr][1], K0.y, 0ull);
                    pa = fma2(q2[rr][2], K1.x, pa);
                    pb = fma2(q2[rr][3], K1.y, pb);
                    float2 h = unpk(add2(pa, pb));
                    p[rr][jq] = h.x + h.y;
                }
            }
            int bofs = rpish[jg * 8 + og];
            #pragma unroll
            for (int rr = 0; rr < 4; rr++) {
                float ve[4];
                #pragma unroll
                for (int k = 0; k < 4; k++) {
                    float mine = (og & 1) ? p[rr][2*k+1] : p[rr][2*k];
                    float oth  = (og & 1) ? p[rr][2*k]   : p[rr][2*k+1];
                    ve[k] = mine + __shfl_xor_sync(0xffffffff, oth, 1);
                }
                float we[2];
                #pragma unroll
                for (int k = 0; k < 2; k++) {
                    float mine = (og & 2) ? ve[2*k+1] : ve[2*k];
                    float oth  = (og & 2) ? ve[2*k]   : ve[2*k+1];
                    we[k] = mine + __shfl_xor_sync(0xffffffff, oth, 2);
                }
                float mine = (og & 4) ? we[1] : we[0];
                float oth  = (og & 4) ? we[0] : we[1];
                float tot = mine + __shfl_xor_sync(0xffffffff, oth, 4);
                tot += __ldg(rpb + rc[rr] - bofs);
                lreg[rr][jg] = tot;
                tmax[rr] = fmaxf(tmax[rr], tot);
            }
        }
        #pragma unroll
        for (int rr = 0; rr < 4; rr++) {
            tmax[rr] = fmaxf(tmax[rr], __shfl_xor_sync(0xffffffff, tmax[rr], 1));
            tmax[rr] = fmaxf(tmax[rr], __shfl_xor_sync(0xffffffff, tmax[rr], 2));
            tmax[rr] = fmaxf(tmax[rr], __shfl_xor_sync(0xffffffff, tmax[rr], 4));
        }

        float nm[4];
        #pragma unroll
        for (int rr = 0; rr < 4; rr++) {
            nm[rr] = fmaxf(mrun[rr], tmax[rr]);
            float scale = __expf(mrun[rr] - nm[rr]);
            drun[rr] *= scale;
            ull sc2 = dup2(scale);
            #pragma unroll
            for (int i = 0; i < 4; i++) acc2[rr][i] = fma2(acc2[rr][i], sc2, 0ull);
            mrun[rr] = nm[rr];
        }
        #pragma unroll
        for (int jg = 0; jg < 8; jg++) {
            float pj[4];
            #pragma unroll
            for (int rr = 0; rr < 4; rr++) {
                pj[rr] = __expf(lreg[rr][jg] - nm[rr]);
                drun[rr] += pj[rr];
            }
            #pragma unroll
            for (int jq = 0; jq < 8; jq++) {
                int jidx = jg * 8 + jq;
                const ulonglong2* vp = (const ulonglong2*)&vvs[jidx][cbase];
                ulonglong2 V0 = vp[0], V1 = vp[1];
                #pragma unroll
                for (int rr = 0; rr < 4; rr++) {
                    float pb = __shfl_sync(0xffffffff, pj[rr], jq, 8);
                    ull pd = dup2(pb);
                    acc2[rr][0] = fma2(pd, V0.x, acc2[rr][0]);
                    acc2[rr][1] = fma2(pd, V0.y, acc2[rr][1]);
                    acc2[rr][2] = fma2(pd, V1.x, acc2[rr][2]);
                    acc2[rr][3] = fma2(pd, V1.y, acc2[rr][3]);
                }
            }
        }
    }

    // ---- tail m = 3968, split 1 only ----
    if (s == 1) {
        const int mt = LL - 1;
        const float4* ka = (const float4*)(g_tokb + ((size_t)b*LL + mt)*Cc + cbase);
        float4 k0 = ka[0], k1 = ka[1];
        const ulonglong2* vp = (const ulonglong2*)(g_sbv + ((size_t)b*LL + mt)*Cc + cbase);
        ulonglong2 V0 = vp[0], V1 = vp[1];
        #pragma unroll
        for (int rr = 0; rr < 4; rr++) {
            float2 qf[4];
            #pragma unroll
            for (int i = 0; i < 4; i++) qf[i] = unpk(q2[rr][i]);
            float sv = qf[0].x*k0.x + qf[0].y*k0.y
                     + qf[1].x*k0.z + qf[1].y*k0.w
                     + qf[2].x*k1.x + qf[2].y*k1.y
                     + qf[3].x*k1.z + qf[3].y*k1.w;
            sv += __shfl_xor_sync(0xffffffff, sv, 1);
            sv += __shfl_xor_sync(0xffffffff, sv, 2);
            sv += __shfl_xor_sync(0xffffffff, sv, 4);
            sv += __ldg(rpb + rc[rr] - 7812);
            float nm = fmaxf(mrun[rr], sv);
            float scale = __expf(mrun[rr] - nm);
            float p = __expf(sv - nm);
            drun[rr] *= scale;
            if (og == 0) drun[rr] += p;
            ull sc2 = dup2(scale);
            ull pd  = dup2(p);
            #pragma unroll
            for (int i = 0; i < 4; i++) acc2[rr][i] = fma2(acc2[rr][i], sc2, 0ull);
            acc2[rr][0] = fma2(pd, V0.x, acc2[rr][0]);
            acc2[rr][1] = fma2(pd, V0.y, acc2[rr][1]);
            acc2[rr][2] = fma2(pd, V1.x, acc2[rr][2]);
            acc2[rr][3] = fma2(pd, V1.y, acc2[rr][3]);
            mrun[rr] = nm;
        }
    }

    #pragma unroll
    for (int rr = 0; rr < 4; rr++) {
        float d = drun[rr];
        d += __shfl_xor_sync(0xffffffff, d, 1);
        d += __shfl_xor_sync(0xffffffff, d, 2);
        d += __shfl_xor_sync(0xffffffff, d, 4);
        if (vrow[rr]) {
            int l = lrow[rr];
            float* dst = g_pacc + (((size_t)s * Bb + b) * LL + l) * Cc + cbase;
            #pragma unroll
            for (int i = 0; i < 4; i++) {
                float2 f = unpk(acc2[rr][i]);
                dst[2*i]   = f.x;
                dst[2*i+1] = f.y;
            }
            if (og == 0) g_md[((size_t)s * Bb + b) * LL + l] = make_float2(mrun[rr], d);
        }
    }
}

// ---------------- Kernel 3b: combine m-splits -> g_ns ----------------
__global__ __launch_bounds__(256)
void k_combine()
{
    int idx = blockIdx.x * 256 + threadIdx.x;
    if (idx >= Bb * LL * Cc) return;
    int c   = idx & 63;
    int row = idx >> 6;
    int l   = row % LL;
    int b   = row / LL;
    float2 md0 = g_md[(size_t)b * LL + l];
    float2 md1 = g_md[((size_t)Bb + b) * LL + l];
    float M  = fmaxf(md0.x, md1.x);
    float w0 = __expf(md0.x - M);
    float w1 = __expf(md1.x - M);
    float a0 = g_pacc[((size_t)b * LL + l) * Cc + c];
    float a1 = g_pacc[(((size_t)Bb + b) * LL + l) * Cc + c];
    g_ns[((size_t)b * Cc + c) * LL + l] =
        (w0 * a0 + w1 * a1) / (w0 * md0.y + w1 * md1.y);
}

// ---------------- Kernel 4: fold + epilogue (unchanged) ----------------
__global__ __launch_bounds__(256)
void k_epilogue(const float* __restrict__ x, const float* __restrict__ mask,
                const float* __restrict__ fg_g, const float* __restrict__ fg_b,
                const float* __restrict__ bg_g, const float* __restrict__ bg_b,
                float* __restrict__ out)
{
    int tid = blockIdx.x * 256 + threadIdx.x;
    int idx = tid * 4;
    int w0 = idx & 255;
    int h  = (idx >> 8) & 255;
    int c  = (idx >> 16) & 63;
    int b  = idx >> 22;
    int q  = w0 >> 2;

    float4 mv = *(const float4*)(mask + (size_t)b * HW + h * Ww + w0);
    float4 xv = *(const float4*)(x + idx);

    float bgG = 1.0f + bg_g[c], bgB = bg_b[c];
    float fgG = 1.0f + fg_g[c], fgB = fg_b[c];

    int ih_hi = h >> 2;  int ih_lo = ih_hi - 1;
    bool vh_hi = (ih_hi <= NUMS - 1), vh_lo = (ih_lo >= 0);
    int iw_hi = q;       int iw_lo = q - 1;
    bool vw_hi = (iw_hi <= NUMS - 1), vw_lo = (iw_lo >= 0);

    float m[4]  = {mv.x, mv.y, mv.z, mv.w};
    float xs[4] = {xv.x, xv.y, xv.z, xv.w};
    float xm[4], inm[4];
    #pragma unroll
    for (int p = 0; p < 4; p++) { inm[p] = 1.0f - m[p]; xm[p] = xs[p] * m[p]; }

    float sum[4] = {0.f, 0.f, 0.f, 0.f};
    size_t base = ((size_t)b * Cc + c) * LL;

    int ihv[2] = {ih_lo, ih_hi};  bool vav[2] = {vh_lo, vh_hi};
    int iwv[2] = {iw_lo, iw_hi};  bool vev[2] = {vw_lo, vw_hi};
    #pragma unroll
    for (int a = 0; a < 2; a++) {
        #pragma unroll
        for (int e = 0; e < 2; e++) {
            if (vav[a] && vev[e]) {
                int lp = ihv[a] * NUMS + iwv[e];
                float2 mi = g_mif[base + lp];
                float ns  = g_ns [base + lp];
                #pragma unroll
                for (int p = 0; p < 4; p++) {
                    float inf_ = (xm[p] - mi.x) * mi.y * m[p] + mi.x * inm[p];
                    sum[p] += inf_ * ns + ns;
                }
            }
        }
    }
    int cnt = ((int)vh_hi + (int)vh_lo) * ((int)vw_hi + (int)vw_lo);
    float invc = (cnt == 4) ? 0.25f : ((cnt == 2) ? 0.5f : 1.0f);

    float r[4];
    #pragma unroll
    for (int p = 0; p < 4; p++) {
        float ubg = (xs[p] * inm[p] * bgG + bgB) * inm[p];
        float val = (sum[p] * invc) * fgG + fgB;
        r[p] = val * m[p] + ubg;
    }
    *(float4*)(out + idx) = make_float4(r[0], r[1], r[2], r[3]);
}

// ---------------- launch ----------------
extern "C" void kernel_launch(void* const* d_in, const int* in_sizes, int n_in,
                              void* d_out, int out_size)
{
    const float* x       = (const float*)d_in[0];
    const float* mask    = (const float*)d_in[1];
    const float* fg_g    = (const float*)d_in[2];
    const float* fg_b    = (const float*)d_in[3];
    const float* bg_g    = (const float*)d_in[4];
    const float* bg_b    = (const float*)d_in[5];
    const float* w_fore  = (const float*)d_in[6];
    const float* w_back  = (const float*)d_in[7];
    const float* rpb     = (const float*)d_in[8];
    float* out = (float*)d_out;

    k_cells<<<(Bb * Cc * NCELL * NCELL) / 256, 256>>>(x, mask);
    k_pstats<<<(Bb * Cc * LL + 255) / 256, 256>>>();
    k_gemm<<<dim3(32, Bb, 4), 128>>>(x, mask, w_fore, w_back);
    k_merge<<<(BCL / 4 + 255) / 256, 256>>>();
    k_attn<<<dim3(63, Bb, 2), 128>>>(rpb);
    k_combine<<<(Bb * LL * Cc + 255) / 256, 256>>>();
    k_epilogue<<<(Bb * Cc * HW) / (256 * 4), 256>>>(x, mask, fg_g, fg_b, bg_g, bg_b, out);
}

// round 11
// speedup vs baseline: 2.8079x; 1.1118x over previous
#include <cuda_runtime.h>
#include <cuda_bf16.h>

#define Bb 2
#define Cc 64
#define Hh 256
#define Ww 256
#define HW (Hh*Ww)
#define NUMS 63
#define LL (NUMS*NUMS)          // 3969
#define K2 64
#define EPSf 1e-5f
#define TBL_W (2*NUMS-1)        // 125
#define NCELL 64

typedef unsigned long long ull;

__device__ __forceinline__ ull fma2(ull a, ull b, ull c){
    ull d; asm("fma.rn.f32x2 %0, %1, %2, %3;" : "=l"(d) : "l"(a), "l"(b), "l"(c)); return d;
}
__device__ __forceinline__ ull add2(ull a, ull b){
    ull d; asm("add.rn.f32x2 %0, %1, %2;" : "=l"(d) : "l"(a), "l"(b)); return d;
}
__device__ __forceinline__ ull dup2(float v){
    ull d; asm("mov.b64 %0, {%1, %1};" : "=l"(d) : "f"(v)); return d;
}
__device__ __forceinline__ float2 unpk(ull a){
    float2 r; asm("mov.b64 {%0, %1}, %2;" : "=f"(r.x), "=f"(r.y) : "l"(a)); return r;
}

__device__ __forceinline__ unsigned int smaddr(const void* p){
    return (unsigned int)__cvta_generic_to_shared(p);
}
__device__ __forceinline__ void ldsm4(unsigned int* r, unsigned int addr){
    asm volatile("ldmatrix.sync.aligned.m8n8.x4.shared.b16 {%0,%1,%2,%3}, [%4];"
        : "=r"(r[0]), "=r"(r[1]), "=r"(r[2]), "=r"(r[3]) : "r"(addr));
}
__device__ __forceinline__ void ldsm4t(unsigned int* r, unsigned int addr){
    asm volatile("ldmatrix.sync.aligned.m8n8.x4.trans.shared.b16 {%0,%1,%2,%3}, [%4];"
        : "=r"(r[0]), "=r"(r[1]), "=r"(r[2]), "=r"(r[3]) : "r"(addr));
}
__device__ __forceinline__ void mma16816(float* d, const unsigned int* a,
                                         unsigned int b0, unsigned int b1){
    asm volatile("mma.sync.aligned.m16n8k16.row.col.f32.bf16.bf16.f32 "
        "{%0,%1,%2,%3}, {%4,%5,%6,%7}, {%8,%9}, {%0,%1,%2,%3};"
        : "+f"(d[0]), "+f"(d[1]), "+f"(d[2]), "+f"(d[3])
        : "r"(a[0]), "r"(a[1]), "r"(a[2]), "r"(a[3]), "r"(b0), "r"(b1));
}

// ---------------- device scratch ----------------
#define BCL (Bb*Cc*LL)
__device__ float2 g_mif [BCL];
__device__ float2 g_mib [BCL];
__device__ float  g_sbv [BCL];
__device__ float  g_tokf[BCL];
__device__ float  g_tokb[BCL];
__device__ float  g_tokf2[BCL];
__device__ float  g_tokb2[BCL];
__device__ float  g_ns  [BCL];
__device__ float2 g_md  [2*Bb*LL];
__device__ float  g_pacc[2*Bb*LL*Cc];
__device__ float4 g_cellA[Bb*Cc*NCELL*NCELL];
__device__ float  g_cellM[Bb*NCELL*NCELL];

// ---------------- Kernel 1a: per-cell raw moments ----------------
__global__ __launch_bounds__(256)
void k_cells(const float* __restrict__ x, const float* __restrict__ mask)
{
    int idx = blockIdx.x * 256 + threadIdx.x;
    int cj = idx & 63;
    int ci = (idx >> 6) & 63;
    int c  = (idx >> 12) & 63;
    int b  = idx >> 18;

    const float* xp = x    + (((size_t)b * Cc + c) * Hh + ci * 4) * Ww + cj * 4;
    const float* mp = mask + ((size_t)b * HW + ci * 4 * Ww) + cj * 4;

    float s1 = 0.f, s2 = 0.f, sm1 = 0.f, sm2 = 0.f, ms = 0.f;
    #pragma unroll
    for (int r = 0; r < 4; r++) {
        float4 xv = *(const float4*)(xp + r * Ww);
        float4 mv = *(const float4*)(mp + r * Ww);
        float vv[4] = {xv.x, xv.y, xv.z, xv.w};
        float mm[4] = {mv.x, mv.y, mv.z, mv.w};
        #pragma unroll
        for (int k = 0; k < 4; k++) {
            float v = vv[k], m = mm[k];
            s1 += v; s2 += v * v;
            sm1 += m * v; sm2 += m * v * v;
            ms += m;
        }
    }
    g_cellA[idx] = make_float4(s1, s2, sm1, sm2);
    if (c == 0) g_cellM[b * (NCELL*NCELL) + ci * NCELL + cj] = ms;
}

// ---------------- Kernel 1b: patch stats from 4 cells ----------------
__global__ __launch_bounds__(256)
void k_pstats()
{
    int idx = blockIdx.x * 256 + threadIdx.x;
    if (idx >= Bb * Cc * LL) return;
    int l  = idx % LL;
    int bc = idx / LL;
    int lh = l / NUMS, lw = l - lh * NUMS;
    int b  = bc >> 6;

    const float4* ca = g_cellA + (size_t)bc * (NCELL*NCELL);
    const float*  cm = g_cellM + (size_t)b * (NCELL*NCELL);
    int c00 = lh * NCELL + lw;

    float4 a0 = ca[c00],         a1 = ca[c00 + 1];
    float4 a2 = ca[c00 + NCELL], a3 = ca[c00 + NCELL + 1];
    float msum = cm[c00] + cm[c00 + 1] + cm[c00 + NCELL] + cm[c00 + NCELL + 1];

    float s1  = a0.x + a1.x + a2.x + a3.x;
    float s2  = a0.y + a1.y + a2.y + a3.y;
    float sm1 = a0.z + a1.z + a2.z + a3.z;
    float sm2 = a0.w + a1.w + a2.w + a3.w;

    float numf = msum;
    float numb = 64.0f - msum;
    float mf = sm1 / (numf + EPSf);
    float vf = (sm2 - 2.f * mf * sm1 + mf * mf * numf) / (numf + EPSf);
    float sb1 = s1 - sm1, sb2 = s2 - sm2;
    float mb = sb1 / (numb + EPSf);
    float vb = (sb2 - 2.f * mb * sb1 + mb * mb * numb) / (numb + EPSf);

    g_mif[idx] = make_float2(mf, 1.0f / vf);
    g_mib[idx] = make_float2(mb, 1.0f / vb);
    int c = bc & 63;
    g_sbv[((size_t)b * LL + l) * Cc + c] = vb;
}

// ---------------- Kernel 2: token GEMM via mma.sync bf16 (split precision) ----------------
// Tile: 64 L x 64 D x 2048 K (one khalf). grid (63, B, 4): z = type*2 + khalf.
// 128 threads = 4 warps, warp w owns M-rows [w*16, w*16+16).
// D = Ah*Wh + Ah*Wl + Al*Wh in f32 accumulators (3-product bf16 split, ~1e-5 rel).
__global__ __launch_bounds__(128)
void k_gemm(const float* __restrict__ x, const float* __restrict__ mask,
            const float* __restrict__ w_fore, const float* __restrict__ w_back)
{
    int tile  = blockIdx.x;              // 0..62 (l-tiles of 64)
    int b     = blockIdx.y;
    int type  = blockIdx.z >> 1;
    int khalf = blockIdx.z & 1;
    const float*  w    = type ? w_back : w_fore;
    const float2* g_mi = type ? g_mib : g_mif;
    float* g_tk = type ? (khalf ? g_tokb2 : g_tokb)
                       : (khalf ? g_tokf2 : g_tokf);

    int l0 = tile * 64;
    int t  = threadIdx.x;
    int lane = t & 31, warp = t >> 5;

    // A: [l row 0..63][k col 0..31], row stride 40 bf16 = 80 B (16B multiple)
    __shared__ __align__(16) __nv_bfloat16 Ah[64][40];
    __shared__ __align__(16) __nv_bfloat16 Al[64][40];
    // W: [k row 0..31][d col 0..63], row stride 72 bf16 = 144 B (16B multiple)
    __shared__ __align__(16) __nv_bfloat16 Wh[32][72];
    __shared__ __align__(16) __nv_bfloat16 Wl[32][72];

    // ---- A-build mapping: thread covers l = t>>1, k-local half = (t&1)*16 ----
    int al_  = t >> 1;
    int ksel = t & 1;
    int lgl = l0 + al_;
    int lg  = (lgl < LL) ? lgl : (LL - 1);
    int lh = lg / NUMS, lw = lg - lh * NUMS;

    // mask bits: msk[sub], bit i ~ pixel(row = sub*4 + ksel*2 + (i>>3), col = i&7)
    unsigned int msk[2];
    {
        const float* mp = mask + (size_t)b * HW + (lh * 4) * Ww + lw * 4;
        #pragma unroll
        for (int sub = 0; sub < 2; sub++) {
            unsigned int bits = 0;
            #pragma unroll
            for (int rr = 0; rr < 2; rr++) {
                int prow = sub * 4 + ksel * 2 + rr;
                float4 a = *(const float4*)(mp + prow * Ww);
                float4 bq = *(const float4*)(mp + prow * Ww + 4);
                float mv[8] = {a.x,a.y,a.z,a.w,bq.x,bq.y,bq.z,bq.w};
                #pragma unroll
                for (int kc = 0; kc < 8; kc++) {
                    bool on = mv[kc] > 0.5f;
                    if (type) on = !on;
                    bits |= (on ? 1u : 0u) << (rr * 8 + kc);
                }
            }
            msk[sub] = bits;
        }
    }

    // ---- W-build mapping: thread covers d = t&63, k-local half = (t>>6)*16 ----
    int wd = t & 63;
    int wk = (t >> 6) * 16;

    int c0 = khalf * 32;

    float acc[8][4];
    #pragma unroll
    for (int i = 0; i < 8; i++)
        #pragma unroll
        for (int j = 0; j < 4; j++) acc[i][j] = 0.f;

    // precomputed ldmatrix addresses (constant across phases)
    unsigned int aaddr_h[2], aaddr_l[2];     // per kstep
    unsigned int baddr_h[2][4], baddr_l[2][4];  // per kstep, per n-pair
    {
        int arow = warp * 16 + (lane & 15);
        int acol = (lane >> 4) << 3;
        int brow = lane & 15;
        int bcol = (lane >> 4) << 3;
        #pragma unroll
        for (int ks = 0; ks < 2; ks++) {
            aaddr_h[ks] = smaddr(&Ah[arow][ks * 16 + acol]);
            aaddr_l[ks] = smaddr(&Al[arow][ks * 16 + acol]);
            #pragma unroll
            for (int nb2 = 0; nb2 < 4; nb2++) {
                baddr_h[ks][nb2] = smaddr(&Wh[ks * 16 + brow][nb2 * 16 + bcol]);
                baddr_l[ks][nb2] = smaddr(&Wl[ks * 16 + brow][nb2 * 16 + bcol]);
            }
        }
    }

    for (int p = 0; p < 64; p++) {
        int c = c0 + (p >> 1), sub = p & 1;
        // ---- stage A (16 values: this thread's l row, k half) ----
        {
            const float* xp = x + (((size_t)b * Cc + c) * Hh + lh * 4 + sub * 4 + ksel * 2) * Ww + lw * 4;
            float4 r0a = *(const float4*)xp;
            float4 r0b = *(const float4*)(xp + 4);
            float4 r1a = *(const float4*)(xp + Ww);
            float4 r1b = *(const float4*)(xp + Ww + 4);
            float2 mi = g_mi[((size_t)b * Cc + c) * LL + lg];
            unsigned int bits = msk[sub];
            float xv[16] = {r0a.x,r0a.y,r0a.z,r0a.w, r0b.x,r0b.y,r0b.z,r0b.w,
                            r1a.x,r1a.y,r1a.z,r1a.w, r1b.x,r1b.y,r1b.z,r1b.w};
            int kb = ksel * 16;
            #pragma unroll
            for (int i = 0; i < 16; i++) {
                bool on = (bits >> i) & 1u;
                float v = on ? (xv[i] - mi.x) * mi.y : mi.x;
                __nv_bfloat16 h = __float2bfloat16(v);
                float hv = __bfloat162float(h);
                __nv_bfloat16 lo = __float2bfloat16(v - hv);
                Ah[al_][kb + i] = h;
                Al[al_][kb + i] = lo;
            }
        }
        // ---- stage W (16 values: this thread's d col, k half) ----
        {
            const float* wp = w + (size_t)wd * (Cc * K2) + c * K2 + sub * 32 + wk;
            float4 q0 = *(const float4*)wp;
            float4 q1 = *(const float4*)(wp + 4);
            float4 q2 = *(const float4*)(wp + 8);
            float4 q3 = *(const float4*)(wp + 12);
            float wv[16] = {q0.x,q0.y,q0.z,q0.w, q1.x,q1.y,q1.z,q1.w,
                            q2.x,q2.y,q2.z,q2.w, q3.x,q3.y,q3.z,q3.w};
            #pragma unroll
            for (int i = 0; i < 16; i++) {
                float v = wv[i];
                __nv_bfloat16 h = __float2bfloat16(v);
                float hv = __bfloat162float(h);
                __nv_bfloat16 lo = __float2bfloat16(v - hv);
                Wh[wk + i][wd] = h;
                Wl[wk + i][wd] = lo;
            }
        }
        __syncthreads();

        // ---- mma: 2 ksteps x 8 n-blocks x 3 products ----
        #pragma unroll
        for (int ks = 0; ks < 2; ks++) {
            unsigned int ah[4], alr[4];
            ldsm4(ah,  aaddr_h[ks]);
            ldsm4(alr, aaddr_l[ks]);
            #pragma unroll
            for (int nb2 = 0; nb2 < 4; nb2++) {
                unsigned int bh[4], blr[4];
                ldsm4t(bh,  baddr_h[ks][nb2]);
                ldsm4t(blr, baddr_l[ks][nb2]);
                mma16816(acc[nb2*2],     ah,  bh[0],  bh[1]);
                mma16816(acc[nb2*2 + 1], ah,  bh[2],  bh[3]);
                mma16816(acc[nb2*2],     ah,  blr[0], blr[1]);
                mma16816(acc[nb2*2 + 1], ah,  blr[2], blr[3]);
                mma16816(acc[nb2*2],     alr, bh[0],  bh[1]);
                mma16816(acc[nb2*2 + 1], alr, bh[2],  bh[3]);
            }
        }
        __syncthreads();   // before next phase restages smem
    }

    // ---- epilogue: fragment -> g_tk[b][l][d] ----
    int grp = lane >> 2, tig = lane & 3;
    #pragma unroll
    for (int nb = 0; nb < 8; nb++) {
        int d = nb * 8 + tig * 2;
        int lr0 = l0 + warp * 16 + grp;
        if (lr0 < LL)
            *(float2*)(g_tk + ((size_t)b * LL + lr0) * Cc + d) = make_float2(acc[nb][0], acc[nb][1]);
        int lr1 = lr0 + 8;
        if (lr1 < LL)
            *(float2*)(g_tk + ((size_t)b * LL + lr1) * Cc + d) = make_float2(acc[nb][2], acc[nb][3]);
    }
}

// ---------------- Kernel 2b: merge K-split tok partials ----------------
__global__ __launch_bounds__(256)
void k_merge()
{
    int i = blockIdx.x * 256 + threadIdx.x;
    if (i >= BCL / 4) return;
    float4* f  = (float4*)g_tokf;
    float4* f2 = (float4*)g_tokf2;
    float4* bq = (float4*)g_tokb;
    float4* b2 = (float4*)g_tokb2;
    float4 a = f[i], c = f2[i];
    f[i] = make_float4(a.x + c.x, a.y + c.y, a.z + c.z, a.w + c.w);
    float4 d = bq[i], e = b2[i];
    bq[i] = make_float4(d.x + e.x, d.y + e.y, d.z + e.z, d.w + e.w);
}

// ---------------- Kernel 3: attention, 4 rows/thread, K/V register prefetch ----------------
__global__ __launch_bounds__(128)
void k_attn(const float* __restrict__ rpb)
{
    int b  = blockIdx.y;
    int s  = blockIdx.z;
    int l0 = blockIdx.x * 64;
    int t  = threadIdx.x;
    int rloc = t >> 3;
    int og   = t & 7;
    int cbase = og * 8;

    int lrow[4]; bool vrow[4]; int rc[4];
    #pragma unroll
    for (int rr = 0; rr < 4; rr++) {
        int l = l0 + rloc + rr * 16;
        vrow[rr] = (l < LL);
        int lr = vrow[rr] ? l : (LL - 1);
        lrow[rr] = lr;
        int lh = lr / NUMS, lw = lr - lh * NUMS;
        rc[rr] = (lh + 62) * TBL_W + (lw + 62);
    }

    __shared__ __align__(16) float kb [64][64];
    __shared__ __align__(16) float vvs[64][64];
    __shared__ int rpish[64];

    ull q2[4][4];
    #pragma unroll
    for (int rr = 0; rr < 4; rr++) {
        float2* qf = (float2*)q2[rr];
        const float4* qa = (const float4*)(g_tokf + ((size_t)b * LL + lrow[rr]) * Cc + cbase);
        float4 a0 = qa[0], a1 = qa[1];
        qf[0] = make_float2(a0.x, a0.y);
        qf[1] = make_float2(a0.z, a0.w);
        qf[2] = make_float2(a1.x, a1.y);
        qf[3] = make_float2(a1.z, a1.w);
    }
    ull acc2[4][4];
    #pragma unroll
    for (int rr = 0; rr < 4; rr++)
        #pragma unroll
        for (int i = 0; i < 4; i++) acc2[rr][i] = 0ull;
    float mrun[4] = {-1e30f,-1e30f,-1e30f,-1e30f};
    float drun[4] = {0.f,0.f,0.f,0.f};

    float4 kr[8], vr[8];
    int prow = t >> 4, pcol = t & 15;

    auto FETCH = [&](int tt) {
        int m0 = (s * 31 + tt) * 64;
        #pragma unroll
        for (int it = 0; it < 8; it++) {
            int m = m0 + prow + it * 8;
            kr[it] = ((const float4*)(g_tokb + ((size_t)b*LL + m)*Cc))[pcol];
            vr[it] = ((const float4*)(g_sbv  + ((size_t)b*LL + m)*Cc))[pcol];
        }
    };

    FETCH(0);
    for (int tt = 0; tt < 31; tt++) {
        __syncthreads();
        #pragma unroll
        for (int it = 0; it < 8; it++) {
            int row = prow + it * 8;
            *(float4*)&kb [row][pcol * 4] = kr[it];
            *(float4*)&vvs[row][pcol * 4] = vr[it];
        }
        if (t < 64) {
            int m = (s * 31 + tt) * 64 + t;
            int mh = m / NUMS;
            rpish[t] = mh * TBL_W + (m - mh * NUMS);
        }
        __syncthreads();
        if (tt < 30) FETCH(tt + 1);

        float lreg[4][8];
        float tmax[4] = {-1e30f,-1e30f,-1e30f,-1e30f};
        #pragma unroll
        for (int jg = 0; jg < 8; jg++) {
            float p[4][8];
            #pragma unroll
            for (int jq = 0; jq < 8; jq++) {
                int jidx = jg * 8 + jq;
                const ulonglong2* kp = (const ulonglong2*)&kb[jidx][cbase];
                ulonglong2 K0 = kp[0], K1 = kp[1];
                #pragma unroll
                for (int rr = 0; rr < 4; rr++) {
                    ull pa = fma2(q2[rr][0], K0.x, 0ull);
                    ull pb = fma2(q2[rr][1], K0.y, 0ull);
                    pa = fma2(q2[rr][2], K1.x, pa);
                    pb = fma2(q2[rr][3], K1.y, pb);
                    float2 h = unpk(add2(pa, pb));
                    p[rr][jq] = h.x + h.y;
                }
            }
            int bofs = rpish[jg * 8 + og];
            #pragma unroll
            for (int rr = 0; rr < 4; rr++) {
                float ve[4];
                #pragma unroll
                for (int k = 0; k < 4; k++) {
                    float mine = (og & 1) ? p[rr][2*k+1] : p[rr][2*k];
                    float oth  = (og & 1) ? p[rr][2*k]   : p[rr][2*k+1];
                    ve[k] = mine + __shfl_xor_sync(0xffffffff, oth, 1);
                }
                float we[2];
                #pragma unroll
                for (int k = 0; k < 2; k++) {
                    float mine = (og & 2) ? ve[2*k+1] : ve[2*k];
                    float oth  = (og & 2) ? ve[2*k]   : ve[2*k+1];
                    we[k] = mine + __shfl_xor_sync(0xffffffff, oth, 2);
                }
                float mine = (og & 4) ? we[1] : we[0];
                float oth  = (og & 4) ? we[0] : we[1];
                float tot = mine + __shfl_xor_sync(0xffffffff, oth, 4);
                tot += __ldg(rpb + rc[rr] - bofs);
                lreg[rr][jg] = tot;
                tmax[rr] = fmaxf(tmax[rr], tot);
            }
        }
        #pragma unroll
        for (int rr = 0; rr < 4; rr++) {
            tmax[rr] = fmaxf(tmax[rr], __shfl_xor_sync(0xffffffff, tmax[rr], 1));
            tmax[rr] = fmaxf(tmax[rr], __shfl_xor_sync(0xffffffff, tmax[rr], 2));
            tmax[rr] = fmaxf(tmax[rr], __shfl_xor_sync(0xffffffff, tmax[rr], 4));
        }

        float nm[4];
        #pragma unroll
        for (int rr = 0; rr < 4; rr++) {
            nm[rr] = fmaxf(mrun[rr], tmax[rr]);
            float scale = __expf(mrun[rr] - nm[rr]);
            drun[rr] *= scale;
            ull sc2 = dup2(scale);
            #pragma unroll
            for (int i = 0; i < 4; i++) acc2[rr][i] = fma2(acc2[rr][i], sc2, 0ull);
            mrun[rr] = nm[rr];
        }
        #pragma unroll
        for (int jg = 0; jg < 8; jg++) {
            float pj[4];
            #pragma unroll
            for (int rr = 0; rr < 4; rr++) {
                pj[rr] = __expf(lreg[rr][jg] - nm[rr]);
                drun[rr] += pj[rr];
            }
            #pragma unroll
            for (int jq = 0; jq < 8; jq++) {
                int jidx = jg * 8 + jq;
                const ulonglong2* vp = (const ulonglong2*)&vvs[jidx][cbase];
                ulonglong2 V0 = vp[0], V1 = vp[1];
                #pragma unroll
                for (int rr = 0; rr < 4; rr++) {
                    float pb = __shfl_sync(0xffffffff, pj[rr], jq, 8);
                    ull pd = dup2(pb);
                    acc2[rr][0] = fma2(pd, V0.x, acc2[rr][0]);
                    acc2[rr][1] = fma2(pd, V0.y, acc2[rr][1]);
                    acc2[rr][2] = fma2(pd, V1.x, acc2[rr][2]);
                    acc2[rr][3] = fma2(pd, V1.y, acc2[rr][3]);
                }
            }
        }
    }

    // ---- tail m = 3968, split 1 only ----
    if (s == 1) {
        const int mt = LL - 1;
        const float4* ka = (const float4*)(g_tokb + ((size_t)b*LL + mt)*Cc + cbase);
        float4 k0 = ka[0], k1 = ka[1];
        const ulonglong2* vp = (const ulonglong2*)(g_sbv + ((size_t)b*LL + mt)*Cc + cbase);
        ulonglong2 V0 = vp[0], V1 = vp[1];
        #pragma unroll
        for (int rr = 0; rr < 4; rr++) {
            float2 qf[4];
            #pragma unroll
            for (int i = 0; i < 4; i++) qf[i] = unpk(q2[rr][i]);
            float sv = qf[0].x*k0.x + qf[0].y*k0.y
                     + qf[1].x*k0.z + qf[1].y*k0.w
                     + qf[2].x*k1.x + qf[2].y*k1.y
                     + qf[3].x*k1.z + qf[3].y*k1.w;
            sv += __shfl_xor_sync(0xffffffff, sv, 1);
            sv += __shfl_xor_sync(0xffffffff, sv, 2);
            sv += __shfl_xor_sync(0xffffffff, sv, 4);
            sv += __ldg(rpb + rc[rr] - 7812);
            float nm = fmaxf(mrun[rr], sv);
            float scale = __expf(mrun[rr] - nm);
            float p = __expf(sv - nm);
            drun[rr] *= scale;
            if (og == 0) drun[rr] += p;
            ull sc2 = dup2(scale);
            ull pd  = dup2(p);
            #pragma unroll
            for (int i = 0; i < 4; i++) acc2[rr][i] = fma2(acc2[rr][i], sc2, 0ull);
            acc2[rr][0] = fma2(pd, V0.x, acc2[rr][0]);
            acc2[rr][1] = fma2(pd, V0.y, acc2[rr][1]);
            acc2[rr][2] = fma2(pd, V1.x, acc2[rr][2]);
            acc2[rr][3] = fma2(pd, V1.y, acc2[rr][3]);
            mrun[rr] = nm;
        }
    }

    #pragma unroll
    for (int rr = 0; rr < 4; rr++) {
        float d = drun[rr];
        d += __shfl_xor_sync(0xffffffff, d, 1);
        d += __shfl_xor_sync(0xffffffff, d, 2);
        d += __shfl_xor_sync(0xffffffff, d, 4);
        if (vrow[rr]) {
            int l = lrow[rr];
            float* dst = g_pacc + (((size_t)s * Bb + b) * LL + l) * Cc + cbase;
            #pragma unroll
            for (int i = 0; i < 4; i++) {
                float2 f = unpk(acc2[rr][i]);
                dst[2*i]   = f.x;
                dst[2*i+1] = f.y;
            }
            if (og == 0) g_md[((size_t)s * Bb + b) * LL + l] = make_float2(mrun[rr], d);
        }
    }
}

// ---------------- Kernel 3b: combine m-splits -> g_ns ----------------
__global__ __launch_bounds__(256)
void k_combine()
{
    int idx = blockIdx.x * 256 + threadIdx.x;
    if (idx >= Bb * LL * Cc) return;
    int c   = idx & 63;
    int row = idx >> 6;
    int l   = row % LL;
    int b   = row / LL;
    float2 md0 = g_md[(size_t)b * LL + l];
    float2 md1 = g_md[((size_t)Bb + b) * LL + l];
    float M  = fmaxf(md0.x, md1.x);
    float w0 = __expf(md0.x - M);
    float w1 = __expf(md1.x - M);
    float a0 = g_pacc[((size_t)b * LL + l) * Cc + c];
    float a1 = g_pacc[(((size_t)Bb + b) * LL + l) * Cc + c];
    g_ns[((size_t)b * Cc + c) * LL + l] =
        (w0 * a0 + w1 * a1) / (w0 * md0.y + w1 * md1.y);
}

// ---------------- Kernel 4: fold + epilogue ----------------
__global__ __launch_bounds__(256)
void k_epilogue(const float* __restrict__ x, const float* __restrict__ mask,
                const float* __restrict__ fg_g, const float* __restrict__ fg_b,
                const float* __restrict__ bg_g, const float* __restrict__ bg_b,
                float* __restrict__ out)
{
    int tid = blockIdx.x * 256 + threadIdx.x;
    int idx = tid * 4;
    int w0 = idx & 255;
    int h  = (idx >> 8) & 255;
    int c  = (idx >> 16) & 63;
    int b  = idx >> 22;
    int q  = w0 >> 2;

    float4 mv = *(const float4*)(mask + (size_t)b * HW + h * Ww + w0);
    float4 xv = *(const float4*)(x + idx);

    float bgG = 1.0f + bg_g[c], bgB = bg_b[c];
    float fgG = 1.0f + fg_g[c], fgB = fg_b[c];

    int ih_hi = h >> 2;  int ih_lo = ih_hi - 1;
    bool vh_hi = (ih_hi <= NUMS - 1), vh_lo = (ih_lo >= 0);
    int iw_hi = q;       int iw_lo = q - 1;
    bool vw_hi = (iw_hi <= NUMS - 1), vw_lo = (iw_lo >= 0);

    float m[4]  = {mv.x, mv.y, mv.z, mv.w};
    float xs[4] = {xv.x, xv.y, xv.z, xv.w};
    float xm[4], inm[4];
    #pragma unroll
    for (int p = 0; p < 4; p++) { inm[p] = 1.0f - m[p]; xm[p] = xs[p] * m[p]; }

    float sum[4] = {0.f, 0.f, 0.f, 0.f};
    size_t base = ((size_t)b * Cc + c) * LL;

    int ihv[2] = {ih_lo, ih_hi};  bool vav[2] = {vh_lo, vh_hi};
    int iwv[2] = {iw_lo, iw_hi};  bool vev[2] = {vw_lo, vw_hi};
    #pragma unroll
    for (int a = 0; a < 2; a++) {
        #pragma unroll
        for (int e = 0; e < 2; e++) {
            if (vav[a] && vev[e]) {
                int lp = ihv[a] * NUMS + iwv[e];
                float2 mi = g_mif[base + lp];
                float ns  = g_ns [base + lp];
                #pragma unroll
                for (int p = 0; p < 4; p++) {
                    float inf_ = (xm[p] - mi.x) * mi.y * m[p] + mi.x * inm[p];
                    sum[p] += inf_ * ns + ns;
                }
            }
        }
    }
    int cnt = ((int)vh_hi + (int)vh_lo) * ((int)vw_hi + (int)vw_lo);
    float invc = (cnt == 4) ? 0.25f : ((cnt == 2) ? 0.5f : 1.0f);

    float r[4];
    #pragma unroll
    for (int p = 0; p < 4; p++) {
        float ubg = (xs[p] * inm[p] * bgG + bgB) * inm[p];
        float val = (sum[p] * invc) * fgG + fgB;
        r[p] = val * m[p] + ubg;
    }
    *(float4*)(out + idx) = make_float4(r[0], r[1], r[2], r[3]);
}

// ---------------- launch ----------------
extern "C" void kernel_launch(void* const* d_in, const int* in_sizes, int n_in,
                              void* d_out, int out_size)
{
    const float* x       = (const float*)d_in[0];
    const float* mask    = (const float*)d_in[1];
    const float* fg_g    = (const float*)d_in[2];
    const float* fg_b    = (const float*)d_in[3];
    const float* bg_g    = (const float*)d_in[4];
    const float* bg_b    = (const float*)d_in[5];
    const float* w_fore  = (const float*)d_in[6];
    const float* w_back  = (const float*)d_in[7];
    const float* rpb     = (const float*)d_in[8];
    float* out = (float*)d_out;

    k_cells<<<(Bb * Cc * NCELL * NCELL) / 256, 256>>>(x, mask);
    k_pstats<<<(Bb * Cc * LL + 255) / 256, 256>>>();
    k_gemm<<<dim3(63, Bb, 4), 128>>>(x, mask, w_fore, w_back);
    k_merge<<<(BCL / 4 + 255) / 256, 256>>>();
    k_attn<<<dim3(63, Bb, 2), 128>>>(rpb);
    k_combine<<<(Bb * LL * Cc + 255) / 256, 256>>>();
    k_epilogue<<<(Bb * Cc * HW) / (256 * 4), 256>>>(x, mask, fg_g, fg_b, bg_g, bg_b, out);
}

// round 12
// speedup vs baseline: 5.7328x; 2.0417x over previous
#include <cuda_runtime.h>
#include <cuda_bf16.h>

#define Bb 2
#define Cc 64
#define Hh 256
#define Ww 256
#define HW (Hh*Ww)
#define NUMS 63
#define LL (NUMS*NUMS)          // 3969
#define LLP 4032                // padded L (63*64)
#define K2 64
#define EPSf 1e-5f
#define TBL_W (2*NUMS-1)        // 125
#define NCELL 64

typedef unsigned long long ull;
typedef __nv_bfloat16 bf16;

__device__ __forceinline__ unsigned int smaddr(const void* p){
    return (unsigned int)__cvta_generic_to_shared(p);
}
__device__ __forceinline__ void ldsm4(unsigned int* r, unsigned int addr){
    asm volatile("ldmatrix.sync.aligned.m8n8.x4.shared.b16 {%0,%1,%2,%3}, [%4];"
        : "=r"(r[0]), "=r"(r[1]), "=r"(r[2]), "=r"(r[3]) : "r"(addr));
}
__device__ __forceinline__ void ldsm4t(unsigned int* r, unsigned int addr){
    asm volatile("ldmatrix.sync.aligned.m8n8.x4.trans.shared.b16 {%0,%1,%2,%3}, [%4];"
        : "=r"(r[0]), "=r"(r[1]), "=r"(r[2]), "=r"(r[3]) : "r"(addr));
}
__device__ __forceinline__ void mma16816(float* d, const unsigned int* a,
                                         unsigned int b0, unsigned int b1){
    asm volatile("mma.sync.aligned.m16n8k16.row.col.f32.bf16.bf16.f32 "
        "{%0,%1,%2,%3}, {%4,%5,%6,%7}, {%8,%9}, {%0,%1,%2,%3};"
        : "+f"(d[0]), "+f"(d[1]), "+f"(d[2]), "+f"(d[3])
        : "r"(a[0]), "r"(a[1]), "r"(a[2]), "r"(a[3]), "r"(b0), "r"(b1));
}
// pack (a,b) -> bf16x2 hi part; residual pair -> lo
__device__ __forceinline__ unsigned packsplit(float a, float b, unsigned &lo){
    __nv_bfloat162 h = __floats2bfloat162_rn(a, b);
    float ra = a - __bfloat162float(h.x);
    float rb = b - __bfloat162float(h.y);
    __nv_bfloat162 l2 = __floats2bfloat162_rn(ra, rb);
    lo = *(unsigned*)&l2;
    return *(unsigned*)&h;
}

// ---------------- device scratch ----------------
#define BCL (Bb*Cc*LL)
__device__ float2 g_mif [BCL];
__device__ float2 g_mib [BCL];
__device__ float  g_sbv [BCL];
__device__ float  g_tokf[BCL];    // khalf-0 partial
__device__ float  g_tokb[BCL];
__device__ float  g_tokf2[BCL];   // khalf-1 partial
__device__ float  g_tokb2[BCL];
__device__ float  g_ns  [BCL];
__device__ float2 g_md  [2*Bb*LL];
__device__ float  g_pacc[2*Bb*LL*Cc];
__device__ float4 g_cellA[Bb*Cc*NCELL*NCELL];
__device__ float  g_cellM[Bb*NCELL*NCELL];
// bf16-split precomputes
__device__ bf16 g_whT[2*4096*64];       // [type][ck][d]
__device__ bf16 g_wlT[2*4096*64];
__device__ bf16 g_tokfh[Bb*LL*64];      // Q hi  [b][l][c]
__device__ bf16 g_tokfl[Bb*LL*64];
__device__ bf16 g_tokbTh[Bb*64*LLP];    // K^T hi [b][c][m], m padded w/ 0
__device__ bf16 g_tokbTl[Bb*64*LLP];
__device__ bf16 g_vh[Bb*LLP*64];        // V hi [b][m][c], padded w/ 0
__device__ bf16 g_vl[Bb*LLP*64];

// ---------------- Kernel 1a: per-cell raw moments ----------------
__global__ __launch_bounds__(256)
void k_cells(const float* __restrict__ x, const float* __restrict__ mask)
{
    int idx = blockIdx.x * 256 + threadIdx.x;
    int cj = idx & 63;
    int ci = (idx >> 6) & 63;
    int c  = (idx >> 12) & 63;
    int b  = idx >> 18;

    const float* xp = x    + (((size_t)b * Cc + c) * Hh + ci * 4) * Ww + cj * 4;
    const float* mp = mask + ((size_t)b * HW + ci * 4 * Ww) + cj * 4;

    float s1 = 0.f, s2 = 0.f, sm1 = 0.f, sm2 = 0.f, ms = 0.f;
    #pragma unroll
    for (int r = 0; r < 4; r++) {
        float4 xv = *(const float4*)(xp + r * Ww);
        float4 mv = *(const float4*)(mp + r * Ww);
        float vv[4] = {xv.x, xv.y, xv.z, xv.w};
        float mm[4] = {mv.x, mv.y, mv.z, mv.w};
        #pragma unroll
        for (int k = 0; k < 4; k++) {
            float v = vv[k], m = mm[k];
            s1 += v; s2 += v * v;
            sm1 += m * v; sm2 += m * v * v;
            ms += m;
        }
    }
    g_cellA[idx] = make_float4(s1, s2, sm1, sm2);
    if (c == 0) g_cellM[b * (NCELL*NCELL) + ci * NCELL + cj] = ms;
}

// ---------------- Kernel 1b: patch stats from 4 cells ----------------
__global__ __launch_bounds__(256)
void k_pstats()
{
    int idx = blockIdx.x * 256 + threadIdx.x;
    if (idx >= Bb * Cc * LL) return;
    int l  = idx % LL;
    int bc = idx / LL;
    int lh = l / NUMS, lw = l - lh * NUMS;
    int b  = bc >> 6;

    const float4* ca = g_cellA + (size_t)bc * (NCELL*NCELL);
    const float*  cm = g_cellM + (size_t)b * (NCELL*NCELL);
    int c00 = lh * NCELL + lw;

    float4 a0 = ca[c00],         a1 = ca[c00 + 1];
    float4 a2 = ca[c00 + NCELL], a3 = ca[c00 + NCELL + 1];
    float msum = cm[c00] + cm[c00 + 1] + cm[c00 + NCELL] + cm[c00 + NCELL + 1];

    float s1  = a0.x + a1.x + a2.x + a3.x;
    float s2  = a0.y + a1.y + a2.y + a3.y;
    float sm1 = a0.z + a1.z + a2.z + a3.z;
    float sm2 = a0.w + a1.w + a2.w + a3.w;

    float numf = msum;
    float numb = 64.0f - msum;
    float mf = sm1 / (numf + EPSf);
    float vf = (sm2 - 2.f * mf * sm1 + mf * mf * numf) / (numf + EPSf);
    float sb1 = s1 - sm1, sb2 = s2 - sm2;
    float mb = sb1 / (numb + EPSf);
    float vb = (sb2 - 2.f * mb * sb1 + mb * mb * numb) / (numb + EPSf);

    g_mif[idx] = make_float2(mf, 1.0f / vf);
    g_mib[idx] = make_float2(mb, 1.0f / vb);
    int c = bc & 63;
    g_sbv[((size_t)b * LL + l) * Cc + c] = vb;
}

// ---------------- Kernel 1c: W -> transposed bf16 split ----------------
// grid (64 ck-tiles, 2 types), 256 thr. out [type][ck][d].
__global__ __launch_bounds__(256)
void k_wsplit(const float* __restrict__ wf, const float* __restrict__ wb)
{
    int type = blockIdx.y;
    int ck0  = blockIdx.x * 64;
    const float* w = type ? wb : wf;
    __shared__ float tile[64][65];
    int t = threadIdx.x;
    int d = t >> 2, q = t & 3;
    #pragma unroll
    for (int i = 0; i < 4; i++) {
        float4 v = *(const float4*)&w[(size_t)d * 4096 + ck0 + q * 16 + i * 4];
        tile[q*16 + i*4 + 0][d] = v.x;
        tile[q*16 + i*4 + 1][d] = v.y;
        tile[q*16 + i*4 + 2][d] = v.z;
        tile[q*16 + i*4 + 3][d] = v.w;
    }
    __syncthreads();
    int ck = t >> 2, q2 = t & 3, d0 = q2 * 16;
    bf16 hv[16], lv[16];
    #pragma unroll
    for (int j = 0; j < 16; j++) {
        float v = tile[ck][d0 + j];
        bf16 h = __float2bfloat16(v);
        hv[j] = h;
        lv[j] = __float2bfloat16(v - __bfloat162float(h));
    }
    size_t o = ((size_t)type * 4096 + ck0 + ck) * 64 + d0;
    *(uint4*)&g_whT[o]     = *(uint4*)&hv[0];
    *(uint4*)&g_whT[o + 8] = *(uint4*)&hv[8];
    *(uint4*)&g_wlT[o]     = *(uint4*)&lv[0];
    *(uint4*)&g_wlT[o + 8] = *(uint4*)&lv[8];
}

// ---------------- Kernel 2: token GEMM via mma.sync (precomputed W) ----------------
__global__ __launch_bounds__(128)
void k_gemm(const float* __restrict__ x, const float* __restrict__ mask)
{
    int tile  = blockIdx.x;
    int b     = blockIdx.y;
    int type  = blockIdx.z >> 1;
    int khalf = blockIdx.z & 1;
    const float2* g_mi = type ? g_mib : g_mif;
    float* g_tk = type ? (khalf ? g_tokb2 : g_tokb)
                       : (khalf ? g_tokf2 : g_tokf);

    int l0 = tile * 64;
    int t  = threadIdx.x;
    int lane = t & 31, warp = t >> 5;

    __shared__ __align__(16) bf16 Ah[64][40];
    __shared__ __align__(16) bf16 Al[64][40];
    __shared__ __align__(16) bf16 Wh[32][72];
    __shared__ __align__(16) bf16 Wl[32][72];

    int al_  = t >> 1;
    int ksel = t & 1;
    int lgl = l0 + al_;
    int lg  = (lgl < LL) ? lgl : (LL - 1);
    int lh = lg / NUMS, lw = lg - lh * NUMS;

    unsigned int msk[2];
    {
        const float* mp = mask + (size_t)b * HW + (lh * 4) * Ww + lw * 4;
        #pragma unroll
        for (int sub = 0; sub < 2; sub++) {
            unsigned int bits = 0;
            #pragma unroll
            for (int rr = 0; rr < 2; rr++) {
                int prow = sub * 4 + ksel * 2 + rr;
                float4 a = *(const float4*)(mp + prow * Ww);
                float4 bq = *(const float4*)(mp + prow * Ww + 4);
                float mv[8] = {a.x,a.y,a.z,a.w,bq.x,bq.y,bq.z,bq.w};
                #pragma unroll
                for (int kc = 0; kc < 8; kc++) {
                    bool on = mv[kc] > 0.5f;
                    if (type) on = !on;
                    bits |= (on ? 1u : 0u) << (rr * 8 + kc);
                }
            }
            msk[sub] = bits;
        }
    }

    int wrow = t >> 2, wq = t & 3;    // W staging: row 0..31, 16 d each
    int c0 = khalf * 32;

    float acc[8][4];
    #pragma unroll
    for (int i = 0; i < 8; i++)
        #pragma unroll
        for (int j = 0; j < 4; j++) acc[i][j] = 0.f;

    unsigned int aaddr_h[2], aaddr_l[2];
    unsigned int baddr_h[2][4], baddr_l[2][4];
    {
        int arow = warp * 16 + (lane & 15);
        int acol = (lane >> 4) << 3;
        int brow = lane & 15;
        int bcol = (lane >> 4) << 3;
        #pragma unroll
        for (int ks = 0; ks < 2; ks++) {
            aaddr_h[ks] = smaddr(&Ah[arow][ks * 16 + acol]);
            aaddr_l[ks] = smaddr(&Al[arow][ks * 16 + acol]);
            #pragma unroll
            for (int nb2 = 0; nb2 < 4; nb2++) {
                baddr_h[ks][nb2] = smaddr(&Wh[ks * 16 + brow][nb2 * 16 + bcol]);
                baddr_l[ks][nb2] = smaddr(&Wl[ks * 16 + brow][nb2 * 16 + bcol]);
            }
        }
    }

    for (int p = 0; p < 64; p++) {
        int c = c0 + (p >> 1), sub = p & 1;
        // ---- stage A ----
        {
            const float* xp = x + (((size_t)b * Cc + c) * Hh + lh * 4 + sub * 4 + ksel * 2) * Ww + lw * 4;
            float4 r0a = *(const float4*)xp;
            float4 r0b = *(const float4*)(xp + 4);
            float4 r1a = *(const float4*)(xp + Ww);
            float4 r1b = *(const float4*)(xp + Ww + 4);
            float2 mi = g_mi[((size_t)b * Cc + c) * LL + lg];
            unsigned int bits = msk[sub];
            float xv[16] = {r0a.x,r0a.y,r0a.z,r0a.w, r0b.x,r0b.y,r0b.z,r0b.w,
                            r1a.x,r1a.y,r1a.z,r1a.w, r1b.x,r1b.y,r1b.z,r1b.w};
            int kb = ksel * 16;
            #pragma unroll
            for (int i = 0; i < 16; i++) {
                bool on = (bits >> i) & 1u;
                float v = on ? (xv[i] - mi.x) * mi.y : mi.x;
                bf16 h = __float2bfloat16(v);
                Ah[al_][kb + i] = h;
                Al[al_][kb + i] = __float2bfloat16(v - __bfloat162float(h));
            }
        }
        // ---- stage W (copy precomputed bf16) ----
        {
            size_t o = ((size_t)type * 4096 + c * 64 + sub * 32 + wrow) * 64 + wq * 16;
            uint4 h0 = *(const uint4*)&g_whT[o];
            uint4 h1 = *(const uint4*)&g_whT[o + 8];
            uint4 l0v = *(const uint4*)&g_wlT[o];
            uint4 l1v = *(const uint4*)&g_wlT[o + 8];
            *(uint4*)&Wh[wrow][wq * 16]     = h0;
            *(uint4*)&Wh[wrow][wq * 16 + 8] = h1;
            *(uint4*)&Wl[wrow][wq * 16]     = l0v;
            *(uint4*)&Wl[wrow][wq * 16 + 8] = l1v;
        }
        __syncthreads();

        #pragma unroll
        for (int ks = 0; ks < 2; ks++) {
            unsigned int ah[4], alr[4];
            ldsm4(ah,  aaddr_h[ks]);
            ldsm4(alr, aaddr_l[ks]);
            #pragma unroll
            for (int nb2 = 0; nb2 < 4; nb2++) {
                unsigned int bh[4], blr[4];
                ldsm4t(bh,  baddr_h[ks][nb2]);
                ldsm4t(blr, baddr_l[ks][nb2]);
                mma16816(acc[nb2*2],     ah,  bh[0],  bh[1]);
                mma16816(acc[nb2*2 + 1], ah,  bh[2],  bh[3]);
                mma16816(acc[nb2*2],     ah,  blr[0], blr[1]);
                mma16816(acc[nb2*2 + 1], ah,  blr[2], blr[3]);
                mma16816(acc[nb2*2],     alr, bh[0],  bh[1]);
                mma16816(acc[nb2*2 + 1], alr, bh[2],  bh[3]);
            }
        }
        __syncthreads();
    }

    int grp = lane >> 2, tig = lane & 3;
    #pragma unroll
    for (int nb = 0; nb < 8; nb++) {
        int d = nb * 8 + tig * 2;
        int lr0 = l0 + warp * 16 + grp;
        if (lr0 < LL)
            *(float2*)(g_tk + ((size_t)b * LL + lr0) * Cc + d) = make_float2(acc[nb][0], acc[nb][1]);
        int lr1 = lr0 + 8;
        if (lr1 < LL)
            *(float2*)(g_tk + ((size_t)b * LL + lr1) * Cc + d) = make_float2(acc[nb][2], acc[nb][3]);
    }
}

// ---------------- Kernel 2b: merge partials + emit bf16-split Q/K^T/V ----------------
// grid (63, Bb), 256 thr. Covers l in [l0, l0+64) incl. padding rows (zeros).
__global__ __launch_bounds__(256)
void k_prep()
{
    int b  = blockIdx.y;
    int l0 = blockIdx.x * 64;
    int t  = threadIdx.x;
    __shared__ float tb[64][65];

    int r = t >> 2, q = t & 3, c0 = q * 16;
    int l = l0 + r;
    bool valid = l < LL;

    float tf[16], tbv[16], sv[16];
    if (valid) {
        size_t o = ((size_t)b * LL + l) * 64 + c0;
        #pragma unroll
        for (int i = 0; i < 16; i += 4) {
            float4 a = *(const float4*)&g_tokf[o + i];
            float4 c = *(const float4*)&g_tokf2[o + i];
            tf[i] = a.x + c.x; tf[i+1] = a.y + c.y; tf[i+2] = a.z + c.z; tf[i+3] = a.w + c.w;
            float4 d = *(const float4*)&g_tokb[o + i];
            float4 e = *(const float4*)&g_tokb2[o + i];
            tbv[i] = d.x + e.x; tbv[i+1] = d.y + e.y; tbv[i+2] = d.z + e.z; tbv[i+3] = d.w + e.w;
            float4 s = *(const float4*)&g_sbv[o + i];
            sv[i] = s.x; sv[i+1] = s.y; sv[i+2] = s.z; sv[i+3] = s.w;
        }
    } else {
        #pragma unroll
        for (int i = 0; i < 16; i++) { tf[i] = 0.f; tbv[i] = 0.f; sv[i] = 0.f; }
    }

    // Q split (valid rows only)
    if (valid) {
        bf16 h[16], lo[16];
        #pragma unroll
        for (int i = 0; i < 16; i++) {
            bf16 hh = __float2bfloat16(tf[i]);
            h[i] = hh; lo[i] = __float2bfloat16(tf[i] - __bfloat162float(hh));
        }
        size_t o = ((size_t)b * LL + l) * 64 + c0;
        *(uint4*)&g_tokfh[o]     = *(uint4*)&h[0];
        *(uint4*)&g_tokfh[o + 8] = *(uint4*)&h[8];
        *(uint4*)&g_tokfl[o]     = *(uint4*)&lo[0];
        *(uint4*)&g_tokfl[o + 8] = *(uint4*)&lo[8];
    }
    // V split (all rows incl. pad -> zeros)
    {
        bf16 h[16], lo[16];
        #pragma unroll
        for (int i = 0; i < 16; i++) {
            bf16 hh = __float2bfloat16(sv[i]);
            h[i] = hh; lo[i] = __float2bfloat16(sv[i] - __bfloat162float(hh));
        }
        size_t o = ((size_t)b * LLP + l) * 64 + c0;
        *(uint4*)&g_vh[o]     = *(uint4*)&h[0];
        *(uint4*)&g_vh[o + 8] = *(uint4*)&h[8];
        *(uint4*)&g_vl[o]     = *(uint4*)&lo[0];
        *(uint4*)&g_vl[o + 8] = *(uint4*)&lo[8];
    }
    // K merged into smem for transpose
    #pragma unroll
    for (int i = 0; i < 16; i++) tb[r][c0 + i] = tbv[i];
    __syncthreads();

    // transposed K^T bf16 split: rows c, 16 l per thread
    int c = t >> 2, lq = t & 3;
    bf16 h[16], lo[16];
    #pragma unroll
    for (int j = 0; j < 16; j++) {
        float v = tb[lq * 16 + j][c];
        bf16 hh = __float2bfloat16(v);
        h[j] = hh; lo[j] = __float2bfloat16(v - __bfloat162float(hh));
    }
    size_t o = ((size_t)b * 64 + c) * LLP + l0 + lq * 16;
    *(uint4*)&g_tokbTh[o]     = *(uint4*)&h[0];
    *(uint4*)&g_tokbTh[o + 8] = *(uint4*)&h[8];
    *(uint4*)&g_tokbTl[o]     = *(uint4*)&lo[0];
    *(uint4*)&g_tokbTl[o + 8] = *(uint4*)&lo[8];
}

// ---------------- Kernel 3: attention via mma.sync (FA pattern) ----------------
// 128 l-rows/block, 8 warps (warp owns 16 rows). grid (32, Bb, 2 m-splits).
__global__ __launch_bounds__(256)
void k_attn(const float* __restrict__ rpb)
{
    int b = blockIdx.y, s = blockIdx.z;
    int l0 = blockIdx.x * 128;
    int t = threadIdx.x;
    int lane = t & 31, warp = t >> 5;
    int grp = lane >> 2, tig = lane & 3;

    __shared__ __align__(16) char sbuf[36864];
    __shared__ int rpish[64];
    bf16 (*Qh)[72] = (bf16(*)[72])sbuf;                  // [128][72]
    bf16 (*Ql)[72] = (bf16(*)[72])(sbuf + 18432);
    bf16 (*Kh)[72] = (bf16(*)[72])sbuf;                  // [64][72]
    bf16 (*Kl)[72] = (bf16(*)[72])(sbuf + 9216);
    bf16 (*Vh)[72] = (bf16(*)[72])(sbuf + 18432);
    bf16 (*Vl)[72] = (bf16(*)[72])(sbuf + 27648);

    // ---- stage Q, load fragments ----
    #pragma unroll
    for (int i = 0; i < 4; i++) {
        int chunk = t + i * 256;
        int row = chunk >> 3, off = (chunk & 7) * 8;
        int lr = min(l0 + row, LL - 1);
        *(uint4*)&Qh[row][off] = *(const uint4*)&g_tokfh[((size_t)b * LL + lr) * 64 + off];
        *(uint4*)&Ql[row][off] = *(const uint4*)&g_tokfl[((size_t)b * LL + lr) * 64 + off];
    }
    __syncthreads();
    unsigned qh[4][4], ql[4][4];
    {
        int ar = warp * 16 + (lane & 15), ac = (lane >> 4) * 8;
        #pragma unroll
        for (int ks = 0; ks < 4; ks++) {
            ldsm4(qh[ks], smaddr(&Qh[ar][ks * 16 + ac]));
            ldsm4(ql[ks], smaddr(&Ql[ar][ks * 16 + ac]));
        }
    }
    __syncthreads();

    int r0 = l0 + warp * 16 + grp;
    int r1 = r0 + 8;
    int lr0 = min(r0, LL - 1), lr1 = min(r1, LL - 1);
    int rc0, rc1;
    { int lh = lr0 / NUMS, lw = lr0 - lh * NUMS; rc0 = (lh + 62) * TBL_W + (lw + 62); }
    { int lh = lr1 / NUMS, lw = lr1 - lh * NUMS; rc1 = (lh + 62) * TBL_W + (lw + 62); }

    float acc_o[8][4];
    #pragma unroll
    for (int i = 0; i < 8; i++)
        #pragma unroll
        for (int j = 0; j < 4; j++) acc_o[i][j] = 0.f;
    float mrun0 = -1e30f, mrun1 = -1e30f, dr0 = 0.f, dr1 = 0.f;

    unsigned int khb, klb, vhb, vlb;
    {
        unsigned int base = (lane & 15) * 144 + (lane >> 4) * 16;
        khb = smaddr(Kh) + base; klb = smaddr(Kl) + base;
        vhb = smaddr(Vh) + base; vlb = smaddr(Vl) + base;
    }

    int NT = 31 + s;
    for (int tt = 0; tt < NT; tt++) {
        int m0 = (s ? 1984 : 0) + tt * 64;
        // ---- stage K (c-rows) and V (m-rows) ----
        #pragma unroll
        for (int i = 0; i < 2; i++) {
            int chunk = t + i * 256;
            int row = chunk >> 3, off = (chunk & 7) * 8;
            *(uint4*)&Kh[row][off] = *(const uint4*)&g_tokbTh[((size_t)b * 64 + row) * LLP + m0 + off];
            *(uint4*)&Kl[row][off] = *(const uint4*)&g_tokbTl[((size_t)b * 64 + row) * LLP + m0 + off];
            *(uint4*)&Vh[row][off] = *(const uint4*)&g_vh[((size_t)b * LLP + m0 + row) * 64 + off];
            *(uint4*)&Vl[row][off] = *(const uint4*)&g_vl[((size_t)b * LLP + m0 + row) * 64 + off];
        }
        if (t < 64) {
            int m = m0 + t;
            if (m < LL) { int mh = m / NUMS; rpish[t] = mh * TBL_W + (m - mh * NUMS); }
            else rpish[t] = -1;
        }
        __syncthreads();

        // ---- QK^T ----
        float accs[8][4];
        #pragma unroll
        for (int i = 0; i < 8; i++)
            #pragma unroll
            for (int j = 0; j < 4; j++) accs[i][j] = 0.f;
        #pragma unroll
        for (int ks = 0; ks < 4; ks++) {
            #pragma unroll
            for (int nb2 = 0; nb2 < 4; nb2++) {
                unsigned int bh[4], bl[4];
                ldsm4t(bh, khb + ks * 2304 + nb2 * 32);
                ldsm4t(bl, klb + ks * 2304 + nb2 * 32);
                mma16816(accs[nb2*2],     qh[ks], bh[0], bh[1]);
                mma16816(accs[nb2*2 + 1], qh[ks], bh[2], bh[3]);
                mma16816(accs[nb2*2],     qh[ks], bl[0], bl[1]);
                mma16816(accs[nb2*2 + 1], qh[ks], bl[2], bl[3]);
                mma16816(accs[nb2*2],     ql[ks], bh[0], bh[1]);
                mma16816(accs[nb2*2 + 1], ql[ks], bh[2], bh[3]);
            }
        }

        // ---- bias + row max ----
        float tmax0 = -1e30f, tmax1 = -1e30f;
        #pragma unroll
        for (int nb = 0; nb < 8; nb++) {
            #pragma unroll
            for (int e = 0; e < 4; e++) {
                int off = rpish[nb * 8 + tig * 2 + (e & 1)];
                float bias = (off >= 0) ? __ldg(rpb + ((e < 2) ? rc0 : rc1) - off) : -1e30f;
                float v = accs[nb][e] + bias;
                accs[nb][e] = v;
                if (e < 2) tmax0 = fmaxf(tmax0, v); else tmax1 = fmaxf(tmax1, v);
            }
        }
        tmax0 = fmaxf(tmax0, __shfl_xor_sync(0xffffffff, tmax0, 1));
        tmax0 = fmaxf(tmax0, __shfl_xor_sync(0xffffffff, tmax0, 2));
        tmax1 = fmaxf(tmax1, __shfl_xor_sync(0xffffffff, tmax1, 1));
        tmax1 = fmaxf(tmax1, __shfl_xor_sync(0xffffffff, tmax1, 2));

        float nm0 = fmaxf(mrun0, tmax0), nm1 = fmaxf(mrun1, tmax1);
        float sc0 = __expf(mrun0 - nm0), sc1 = __expf(mrun1 - nm1);
        dr0 *= sc0; dr1 *= sc1;
        mrun0 = nm0; mrun1 = nm1;
        #pragma unroll
        for (int nb = 0; nb < 8; nb++) {
            acc_o[nb][0] *= sc0; acc_o[nb][1] *= sc0;
            acc_o[nb][2] *= sc1; acc_o[nb][3] *= sc1;
        }
        // ---- probs ----
        #pragma unroll
        for (int nb = 0; nb < 8; nb++) {
            float p0 = __expf(accs[nb][0] - nm0);
            float p1 = __expf(accs[nb][1] - nm0);
            float p2 = __expf(accs[nb][2] - nm1);
            float p3 = __expf(accs[nb][3] - nm1);
            accs[nb][0] = p0; accs[nb][1] = p1; accs[nb][2] = p2; accs[nb][3] = p3;
            dr0 += p0 + p1; dr1 += p2 + p3;
        }

        // ---- PV ----
        #pragma unroll
        for (int ks = 0; ks < 4; ks++) {
            unsigned ph[4], pl[4];
            ph[0] = packsplit(accs[2*ks][0],   accs[2*ks][1],   pl[0]);
            ph[1] = packsplit(accs[2*ks][2],   accs[2*ks][3],   pl[1]);
            ph[2] = packsplit(accs[2*ks+1][0], accs[2*ks+1][1], pl[2]);
            ph[3] = packsplit(accs[2*ks+1][2], accs[2*ks+1][3], pl[3]);
            #pragma unroll
            for (int nb2 = 0; nb2 < 4; nb2++) {
                unsigned int vh[4], vl[4];
                ldsm4t(vh, vhb + ks * 2304 + nb2 * 32);
                ldsm4t(vl, vlb + ks * 2304 + nb2 * 32);
                mma16816(acc_o[nb2*2],     ph, vh[0], vh[1]);
                mma16816(acc_o[nb2*2 + 1], ph, vh[2], vh[3]);
                mma16816(acc_o[nb2*2],     ph, vl[0], vl[1]);
                mma16816(acc_o[nb2*2 + 1], ph, vl[2], vl[3]);
                mma16816(acc_o[nb2*2],     pl, vh[0], vh[1]);
                mma16816(acc_o[nb2*2 + 1], pl, vh[2], vh[3]);
            }
        }
        __syncthreads();
    }

    // ---- epilogue: reduce denom over quad, store partials ----
    dr0 += __shfl_xor_sync(0xffffffff, dr0, 1);
    dr0 += __shfl_xor_sync(0xffffffff, dr0, 2);
    dr1 += __shfl_xor_sync(0xffffffff, dr1, 1);
    dr1 += __shfl_xor_sync(0xffffffff, dr1, 2);

    if (r0 < LL) {
        float* dst = g_pacc + (((size_t)s * Bb + b) * LL + r0) * Cc;
        #pragma unroll
        for (int nb = 0; nb < 8; nb++)
            *(float2*)(dst + nb * 8 + tig * 2) = make_float2(acc_o[nb][0], acc_o[nb][1]);
        if (tig == 0) g_md[((size_t)s * Bb + b) * LL + r0] = make_float2(mrun0, dr0);
    }
    if (r1 < LL) {
        float* dst = g_pacc + (((size_t)s * Bb + b) * LL + r1) * Cc;
        #pragma unroll
        for (int nb = 0; nb < 8; nb++)
            *(float2*)(dst + nb * 8 + tig * 2) = make_float2(acc_o[nb][2], acc_o[nb][3]);
        if (tig == 0) g_md[((size_t)s * Bb + b) * LL + r1] = make_float2(mrun1, dr1);
    }
}

// ---------------- Kernel 3b: combine m-splits -> g_ns ----------------
__global__ __launch_bounds__(256)
void k_combine()
{
    int idx = blockIdx.x * 256 + threadIdx.x;
    if (idx >= Bb * LL * Cc) return;
    int c   = idx & 63;
    int row = idx >> 6;
    int l   = row % LL;
    int b   = row / LL;
    float2 md0 = g_md[(size_t)b * LL + l];
    float2 md1 = g_md[((size_t)Bb + b) * LL + l];
    float M  = fmaxf(md0.x, md1.x);
    float w0 = __expf(md0.x - M);
    float w1 = __expf(md1.x - M);
    float a0 = g_pacc[((size_t)b * LL + l) * Cc + c];
    float a1 = g_pacc[(((size_t)Bb + b) * LL + l) * Cc + c];
    g_ns[((size_t)b * Cc + c) * LL + l] =
        (w0 * a0 + w1 * a1) / (w0 * md0.y + w1 * md1.y);
}

// ---------------- Kernel 4: fold + epilogue ----------------
__global__ __launch_bounds__(256)
void k_epilogue(const float* __restrict__ x, const float* __restrict__ mask,
                const float* __restrict__ fg_g, const float* __restrict__ fg_b,
                const float* __restrict__ bg_g, const float* __restrict__ bg_b,
                float* __restrict__ out)
{
    int tid = blockIdx.x * 256 + threadIdx.x;
    int idx = tid * 4;
    int w0 = idx & 255;
    int h  = (idx >> 8) & 255;
    int c  = (idx >> 16) & 63;
    int b  = idx >> 22;
    int q  = w0 >> 2;

    float4 mv = *(const float4*)(mask + (size_t)b * HW + h * Ww + w0);
    float4 xv = *(const float4*)(x + idx);

    float bgG = 1.0f + bg_g[c], bgB = bg_b[c];
    float fgG = 1.0f + fg_g[c], fgB = fg_b[c];

    int ih_hi = h >> 2;  int ih_lo = ih_hi - 1;
    bool vh_hi = (ih_hi <= NUMS - 1), vh_lo = (ih_lo >= 0);
    int iw_hi = q;       int iw_lo = q - 1;
    bool vw_hi = (iw_hi <= NUMS - 1), vw_lo = (iw_lo >= 0);

    float m[4]  = {mv.x, mv.y, mv.z, mv.w};
    float xs[4] = {xv.x, xv.y, xv.z, xv.w};
    float xm[4], inm[4];
    #pragma unroll
    for (int p = 0; p < 4; p++) { inm[p] = 1.0f - m[p]; xm[p] = xs[p] * m[p]; }

    float sum[4] = {0.f, 0.f, 0.f, 0.f};
    size_t base = ((size_t)b * Cc + c) * LL;

    int ihv[2] = {ih_lo, ih_hi};  bool vav[2] = {vh_lo, vh_hi};
    int iwv[2] = {iw_lo, iw_hi};  bool vev[2] = {vw_lo, vw_hi};
    #pragma unroll
    for (int a = 0; a < 2; a++) {
        #pragma unroll
        for (int e = 0; e < 2; e++) {
            if (vav[a] && vev[e]) {
                int lp = ihv[a] * NUMS + iwv[e];
                float2 mi = g_mif[base + lp];
                float ns  = g_ns [base + lp];
                #pragma unroll
                for (int p = 0; p < 4; p++) {
                    float inf_ = (xm[p] - mi.x) * mi.y * m[p] + mi.x * inm[p];
                    sum[p] += inf_ * ns + ns;
                }
            }
        }
    }
    int cnt = ((int)vh_hi + (int)vh_lo) * ((int)vw_hi + (int)vw_lo);
    float invc = (cnt == 4) ? 0.25f : ((cnt == 2) ? 0.5f : 1.0f);

    float r[4];
    #pragma unroll
    for (int p = 0; p < 4; p++) {
        float ubg = (xs[p] * inm[p] * bgG + bgB) * inm[p];
        float val = (sum[p] * invc) * fgG + fgB;
        r[p] = val * m[p] + ubg;
    }
    *(float4*)(out + idx) = make_float4(r[0], r[1], r[2], r[3]);
}

// ---------------- launch ----------------
extern "C" void kernel_launch(void* const* d_in, const int* in_sizes, int n_in,
                              void* d_out, int out_size)
{
    const float* x       = (const float*)d_in[0];
    const float* mask    = (const float*)d_in[1];
    const float* fg_g    = (const float*)d_in[2];
    const float* fg_b    = (const float*)d_in[3];
    const float* bg_g    = (const float*)d_in[4];
    const float* bg_b    = (const float*)d_in[5];
    const float* w_fore  = (const float*)d_in[6];
    const float* w_back  = (const float*)d_in[7];
    const float* rpb     = (const float*)d_in[8];
    float* out = (float*)d_out;

    k_cells<<<(Bb * Cc * NCELL * NCELL) / 256, 256>>>(x, mask);
    k_pstats<<<(Bb * Cc * LL + 255) / 256, 256>>>();
    k_wsplit<<<dim3(64, 2), 256>>>(w_fore, w_back);
    k_gemm<<<dim3(63, Bb, 4), 128>>>(x, mask);
    k_prep<<<dim3(63, Bb), 256>>>();
    k_attn<<<dim3(32, Bb, 2), 256>>>(rpb);
    k_combine<<<(Bb * LL * Cc + 255) / 256, 256>>>();
    k_epilogue<<<(Bb * Cc * HW) / (256 * 4), 256>>>(x, mask, fg_g, fg_b, bg_g, bg_b, out);
}